// round 1
// baseline (speedup 1.0000x reference)
#include <cuda_runtime.h>
#include <cuda_bf16.h>
#include <cstddef>

// Problem constants
#define BB 2
#define SS 2048
#define DD 2048
#define NH 16
#define FHD 128
#define KDIM 2048
#define NDIM 2048
#define MDIM (BB * SS)   // 4096

// Scratch (device globals — no allocation allowed)
__device__ float g_Q[(size_t)BB * SS * DD];
__device__ float g_K[(size_t)BB * SS * DD];
__device__ float g_V[(size_t)BB * SS * DD];
__device__ float g_AO[(size_t)BB * SS * DD];

// ---------------------------------------------------------------------------
// Tiled SGEMM: C[M,N] = A[M,K] * B[N,K]^T  (both row-major, K contiguous)
// Block tile 128x128, K-tile 16, 256 threads, 8x8 per-thread register tile.
// ---------------------------------------------------------------------------
#define GBM 128
#define GBN 128
#define GBK 16

__device__ __forceinline__ void gemm_block(const float* __restrict__ A,
                                           const float* __restrict__ Bm,
                                           float* __restrict__ C)
{
    __shared__ __align__(16) float As[GBK][GBM];
    __shared__ __align__(16) float Bs[GBK][GBN];

    const int tid = threadIdx.x;
    const int m0 = blockIdx.y * GBM;
    const int n0 = blockIdx.x * GBN;
    const int tr = (tid >> 4) * 8;   // row offset within tile
    const int tc = (tid & 15) * 8;   // col offset within tile

    float acc[8][8];
#pragma unroll
    for (int i = 0; i < 8; i++)
#pragma unroll
        for (int j = 0; j < 8; j++) acc[i][j] = 0.0f;

    for (int k0 = 0; k0 < KDIM; k0 += GBK) {
        // Load 128x16 tiles of A and B, stored transposed ([k][m]) in shared.
#pragma unroll
        for (int i = 0; i < 2; i++) {
            int idx = tid + i * 256;        // float4 index 0..511
            int row = idx >> 2;             // 0..127
            int c4  = (idx & 3) << 2;       // 0,4,8,12
            float4 va = *(const float4*)(A + (size_t)(m0 + row) * KDIM + k0 + c4);
            As[c4 + 0][row] = va.x;
            As[c4 + 1][row] = va.y;
            As[c4 + 2][row] = va.z;
            As[c4 + 3][row] = va.w;
            float4 vb = *(const float4*)(Bm + (size_t)(n0 + row) * KDIM + k0 + c4);
            Bs[c4 + 0][row] = vb.x;
            Bs[c4 + 1][row] = vb.y;
            Bs[c4 + 2][row] = vb.z;
            Bs[c4 + 3][row] = vb.w;
        }
        __syncthreads();

#pragma unroll
        for (int k = 0; k < GBK; k++) {
            float a[8], b[8];
            *(float4*)&a[0] = *(const float4*)&As[k][tr];
            *(float4*)&a[4] = *(const float4*)&As[k][tr + 4];
            *(float4*)&b[0] = *(const float4*)&Bs[k][tc];
            *(float4*)&b[4] = *(const float4*)&Bs[k][tc + 4];
#pragma unroll
            for (int i = 0; i < 8; i++)
#pragma unroll
                for (int j = 0; j < 8; j++)
                    acc[i][j] = fmaf(a[i], b[j], acc[i][j]);
        }
        __syncthreads();
    }

#pragma unroll
    for (int i = 0; i < 8; i++) {
#pragma unroll
        for (int j = 0; j < 8; j += 4) {
            *(float4*)(C + (size_t)(m0 + tr + i) * NDIM + n0 + tc + j) =
                *(const float4*)&acc[i][j];
        }
    }
}

__global__ void __launch_bounds__(256) qkv_gemm_kernel(const float* __restrict__ x,
                                                       const float* __restrict__ wq,
                                                       const float* __restrict__ wk,
                                                       const float* __restrict__ wv)
{
    const float* W;
    float* C;
    if (blockIdx.z == 0)      { W = wq; C = g_Q; }
    else if (blockIdx.z == 1) { W = wk; C = g_K; }
    else                      { W = wv; C = g_V; }
    gemm_block(x, W, C);
}

__global__ void __launch_bounds__(256) out_gemm_kernel(const float* __restrict__ wo,
                                                       float* __restrict__ out)
{
    gemm_block(g_AO, wo, out);
}

// ---------------------------------------------------------------------------
// RoPE in place on g_Q, g_K. One thread per (row, head, pair).
// Layout: [m][h][hd], pair = (2i, 2i+1). t = m % S.
// ---------------------------------------------------------------------------
__global__ void rope_kernel(const float* __restrict__ cosT, const float* __restrict__ sinT)
{
    int idx = blockIdx.x * blockDim.x + threadIdx.x;   // pair index, total B*S*D/2
    int i = idx & 63;           // pair within head (HD/2 = 64)
    int rest = idx >> 6;        // m*16 + h
    int m = rest >> 4;          // 0..4095
    int t = m & (SS - 1);
    float c = cosT[t * 64 + i];
    float s = sinT[t * 64 + i];
    size_t off = (size_t)idx * 2;
    float2 q = *(const float2*)(g_Q + off);
    float2 k = *(const float2*)(g_K + off);
    float2 qo, ko;
    qo.x = q.x * c - q.y * s;
    qo.y = q.x * s + q.y * c;
    ko.x = k.x * c - k.y * s;
    ko.y = k.x * s + k.y * c;
    *(float2*)(g_Q + off) = qo;
    *(float2*)(g_K + off) = ko;
}

// ---------------------------------------------------------------------------
// Flash attention (fp32, causal). Block = (q-tile of 64) x head x batch.
// 256 threads as 16x16: thread (ty,tx) owns score sub-tile rows ty*4..+3,
// cols tx*4..+3, and output cols tx*8..+7.
// Shared: Qs[128][64] (k-major), Ks[128][64], Vs[64][128], Ps[64][64] (c-major).
// ---------------------------------------------------------------------------
#define FBQ 64
#define FBK 64
#define FSCALE 0.08838834764831845f   // 1/sqrt(128)
#define FLASH_SMEM (114688)           // (8192*3 + 4096) floats * 4B

__global__ void __launch_bounds__(256) flash_attn_kernel()
{
    extern __shared__ __align__(16) float sm[];
    float* Qs = sm;              // [128][64]
    float* Ks = sm + 8192;       // [128][64]
    float* Vs = sm + 16384;      // [64][128]
    float* Ps = sm + 24576;      // [64][64]

    const int q0 = blockIdx.x * FBQ;
    const int h  = blockIdx.y;
    const int b  = blockIdx.z;
    const int tid = threadIdx.x;
    const int ty = tid >> 4;
    const int tx = tid & 15;
    const int r0 = ty * 4;
    const int c0 = tx * 4;
    const int d0 = tx * 8;

    const size_t head_off = (size_t)h * FHD;
    const size_t brow = (size_t)b * SS;

    // Load Q tile transposed: Qs[hd][r]
#pragma unroll
    for (int i = 0; i < 8; i++) {
        int idx = tid + i * 256;       // float4 idx 0..2047
        int r = idx >> 5;              // 32 float4 per 128-dim row
        int hd = (idx & 31) << 2;
        float4 v = *(const float4*)(g_Q + (brow + q0 + r) * (size_t)DD + head_off + hd);
        Qs[(hd + 0) * 64 + r] = v.x;
        Qs[(hd + 1) * 64 + r] = v.y;
        Qs[(hd + 2) * 64 + r] = v.z;
        Qs[(hd + 3) * 64 + r] = v.w;
    }

    float m_i[4], l_i[4], o[4][8];
#pragma unroll
    for (int i = 0; i < 4; i++) {
        m_i[i] = -1e30f;
        l_i[i] = 0.0f;
#pragma unroll
        for (int j = 0; j < 8; j++) o[i][j] = 0.0f;
    }

    for (int k0 = 0; k0 <= q0; k0 += FBK) {
        __syncthreads();   // previous PV done; Qs load visible after next sync
        // Load K transposed (Ks[hd][c]) and V direct (Vs[c][hd])
#pragma unroll
        for (int i = 0; i < 8; i++) {
            int idx = tid + i * 256;
            int r = idx >> 5;
            int hd = (idx & 31) << 2;
            float4 kv = *(const float4*)(g_K + (brow + k0 + r) * (size_t)DD + head_off + hd);
            Ks[(hd + 0) * 64 + r] = kv.x;
            Ks[(hd + 1) * 64 + r] = kv.y;
            Ks[(hd + 2) * 64 + r] = kv.z;
            Ks[(hd + 3) * 64 + r] = kv.w;
            float4 vv = *(const float4*)(g_V + (brow + k0 + r) * (size_t)DD + head_off + hd);
            *(float4*)&Vs[r * 128 + hd] = vv;
        }
        __syncthreads();

        // S tile: s[i][j] = sum_hd Qs[hd][r0+i] * Ks[hd][c0+j]
        float s[4][4];
#pragma unroll
        for (int i = 0; i < 4; i++)
#pragma unroll
            for (int j = 0; j < 4; j++) s[i][j] = 0.0f;

#pragma unroll 8
        for (int k = 0; k < FHD; k++) {
            float4 qa = *(const float4*)&Qs[k * 64 + r0];
            float4 kb = *(const float4*)&Ks[k * 64 + c0];
            float aq[4] = {qa.x, qa.y, qa.z, qa.w};
            float bk[4] = {kb.x, kb.y, kb.z, kb.w};
#pragma unroll
            for (int i = 0; i < 4; i++)
#pragma unroll
                for (int j = 0; j < 4; j++)
                    s[i][j] = fmaf(aq[i], bk[j], s[i][j]);
        }

        // Scale + causal mask + per-row tile max
        float tmax[4];
#pragma unroll
        for (int i = 0; i < 4; i++) {
#pragma unroll
            for (int j = 0; j < 4; j++) {
                float v = s[i][j] * FSCALE;
                if (k0 + c0 + j > q0 + r0 + i) v = -1e30f;
                s[i][j] = v;
            }
            tmax[i] = fmaxf(fmaxf(s[i][0], s[i][1]), fmaxf(s[i][2], s[i][3]));
        }
#pragma unroll
        for (int w = 1; w < 16; w <<= 1)
#pragma unroll
            for (int i = 0; i < 4; i++)
                tmax[i] = fmaxf(tmax[i], __shfl_xor_sync(0xffffffffu, tmax[i], w));

        // Online softmax update
        float rsum[4];
#pragma unroll
        for (int i = 0; i < 4; i++) {
            float m_new = fmaxf(m_i[i], tmax[i]);
            float corr = __expf(m_i[i] - m_new);
            m_i[i] = m_new;
            float rs = 0.0f;
#pragma unroll
            for (int j = 0; j < 4; j++) {
                float p = __expf(s[i][j] - m_new);
                s[i][j] = p;
                rs += p;
            }
            rsum[i] = rs;
            l_i[i] *= corr;
#pragma unroll
            for (int j = 0; j < 8; j++) o[i][j] *= corr;
        }
#pragma unroll
        for (int w = 1; w < 16; w <<= 1)
#pragma unroll
            for (int i = 0; i < 4; i++)
                rsum[i] += __shfl_xor_sync(0xffffffffu, rsum[i], w);
#pragma unroll
        for (int i = 0; i < 4; i++) l_i[i] += rsum[i];

        // Write P transposed: Ps[c][r]
#pragma unroll
        for (int i = 0; i < 4; i++)
#pragma unroll
            for (int j = 0; j < 4; j++)
                Ps[(c0 + j) * 64 + (r0 + i)] = s[i][j];
        __syncthreads();

        // O += P * V : o[i][j] += sum_kc Ps[kc][r0+i] * Vs[kc][d0+j]
#pragma unroll 4
        for (int kc = 0; kc < FBK; kc++) {
            float4 p4  = *(const float4*)&Ps[kc * 64 + r0];
            float4 vlo = *(const float4*)&Vs[kc * 128 + d0];
            float4 vhi = *(const float4*)&Vs[kc * 128 + d0 + 4];
            float pv[4] = {p4.x, p4.y, p4.z, p4.w};
            float vv[8] = {vlo.x, vlo.y, vlo.z, vlo.w, vhi.x, vhi.y, vhi.z, vhi.w};
#pragma unroll
            for (int i = 0; i < 4; i++)
#pragma unroll
                for (int j = 0; j < 8; j++)
                    o[i][j] = fmaf(pv[i], vv[j], o[i][j]);
        }
    }

    // Normalize + store
#pragma unroll
    for (int i = 0; i < 4; i++) {
        float inv = 1.0f / l_i[i];
        float4 o0, o1;
        o0.x = o[i][0] * inv; o0.y = o[i][1] * inv; o0.z = o[i][2] * inv; o0.w = o[i][3] * inv;
        o1.x = o[i][4] * inv; o1.y = o[i][5] * inv; o1.z = o[i][6] * inv; o1.w = o[i][7] * inv;
        float* dst = g_AO + (brow + q0 + r0 + i) * (size_t)DD + head_off + d0;
        *(float4*)dst = o0;
        *(float4*)(dst + 4) = o1;
    }
}

// ---------------------------------------------------------------------------
// Launch
// ---------------------------------------------------------------------------
extern "C" void kernel_launch(void* const* d_in, const int* in_sizes, int n_in,
                              void* d_out, int out_size)
{
    const float* x  = (const float*)d_in[0];
    const float* wq = (const float*)d_in[1];
    const float* wk = (const float*)d_in[2];
    const float* wv = (const float*)d_in[3];
    const float* wo = (const float*)d_in[4];
    const float* fc = (const float*)d_in[5];
    const float* fs = (const float*)d_in[6];
    // d_in[7] = mask (causal, reproduced analytically), d_in[8] = start_pos (0)
    float* out = (float*)d_out;

    cudaFuncSetAttribute(flash_attn_kernel,
                         cudaFuncAttributeMaxDynamicSharedMemorySize, FLASH_SMEM);

    // 1) QKV projections (+ layout [b,s,h,hd] == [M,N] row-major)
    dim3 gq(NDIM / GBN, MDIM / GBM, 3);
    qkv_gemm_kernel<<<gq, 256>>>(x, wq, wk, wv);

    // 2) RoPE in place on Q and K
    rope_kernel<<<(BB * SS * DD / 2) / 256, 256>>>(fc, fs);

    // 3) Causal flash attention -> g_AO
    flash_attn_kernel<<<dim3(SS / FBQ, NH, BB), 256, FLASH_SMEM>>>();

    // 4) Output projection
    out_gemm_kernel<<<dim3(NDIM / GBN, MDIM / GBM), 256>>>(wo, out);
}

// round 4
// speedup vs baseline: 1.8058x; 1.8058x over previous
#include <cuda_runtime.h>
#include <cuda_bf16.h>
#include <cstddef>
#include <cstdint>

// Problem constants
#define BB 2
#define SS 2048
#define DD 2048
#define NH 16
#define FHD 128
#define KDIM 2048
#define NDIM 2048
#define MDIM (BB * SS)   // 4096

// ---------------------------------------------------------------------------
// Scratch (device globals — no allocation allowed)
// ---------------------------------------------------------------------------
__device__ float g_Q[(size_t)BB * SS * DD];
__device__ float g_K[(size_t)BB * SS * DD];
__device__ float g_V[(size_t)BB * SS * DD];
__device__ float g_AO[(size_t)BB * SS * DD];
// tf32-rounded operand copies
__device__ float g_xr[(size_t)MDIM * KDIM];
__device__ float g_wqr[(size_t)NDIM * KDIM];
__device__ float g_wkr[(size_t)NDIM * KDIM];
__device__ float g_wvr[(size_t)NDIM * KDIM];
__device__ float g_wor[(size_t)NDIM * KDIM];

// ---------------------------------------------------------------------------
// Helpers
// ---------------------------------------------------------------------------
__device__ __forceinline__ uint32_t smem_u32(const void* p) {
    uint32_t a;
    asm("{ .reg .u64 t; cvta.to.shared.u64 t, %1; cvt.u32.u64 %0, t; }" : "=r"(a) : "l"(p));
    return a;
}

__device__ __forceinline__ void cp_async16(uint32_t dst, const void* src) {
    asm volatile("cp.async.cg.shared.global [%0], [%1], 16;" :: "r"(dst), "l"(src) : "memory");
}
__device__ __forceinline__ void cp_commit() {
    asm volatile("cp.async.commit_group;" ::: "memory");
}
template <int N>
__device__ __forceinline__ void cp_wait() {
    asm volatile("cp.async.wait_group %0;" :: "n"(N) : "memory");
}

__device__ __forceinline__ uint32_t lds32(uint32_t addr) {
    uint32_t v;
    asm volatile("ld.shared.b32 %0, [%1];" : "=r"(v) : "r"(addr));
    return v;
}

__device__ __forceinline__ void mma_tf32(float* d, const uint32_t* a,
                                         uint32_t b0, uint32_t b1)
{
    asm volatile(
        "mma.sync.aligned.m16n8k8.row.col.f32.tf32.tf32.f32 "
        "{%0,%1,%2,%3}, {%4,%5,%6,%7}, {%8,%9}, {%0,%1,%2,%3};"
        : "+f"(d[0]), "+f"(d[1]), "+f"(d[2]), "+f"(d[3])
        : "r"(a[0]), "r"(a[1]), "r"(a[2]), "r"(a[3]), "r"(b0), "r"(b1));
}

__device__ __forceinline__ float tf32r(float v) {
    asm("cvt.rna.tf32.f32 %0, %1;" : "=f"(v) : "f"(v));
    return v;
}

// ---------------------------------------------------------------------------
// tf32 mma.sync GEMM: C[M,N] = A[M,K] * B[N,K]^T, row-major K-contiguous.
// CTA 128x256, 8 warps (2x4), warp tile 64x64, K-tile 16, 4-stage cp.async.
// Shared layout [row][16] floats, swizzle k' = k ^ (((row>>1)&3)<<2).
// ---------------------------------------------------------------------------
#define GTM 128
#define GTN 256
#define GTK 16
#define NSTG 4
#define A_TILE_B (GTM * GTK * 4)          // 8192
#define B_TILE_B (GTN * GTK * 4)          // 16384
#define STG_B (A_TILE_B + B_TILE_B)       // 24576
#define GEMM_SMEM (NSTG * STG_B)          // 98304
#define KT (KDIM / GTK)                   // 128

__device__ __forceinline__ void gemm_load_stage(uint32_t sbase, int s, int kt,
                                                const float* __restrict__ A,
                                                const float* __restrict__ Bm,
                                                int m0, int n0, int tid)
{
    const uint32_t ab = sbase + s * STG_B;
    const uint32_t bb = ab + A_TILE_B;
    const int kk = kt * GTK;
#pragma unroll
    for (int i = 0; i < 2; i++) {            // A: 512 16B-chunks
        int t = tid + i * 256;
        int r = t >> 2, c = t & 3;
        int cs = c ^ ((r >> 1) & 3);
        cp_async16(ab + r * 64 + cs * 16, A + (size_t)(m0 + r) * KDIM + kk + c * 4);
    }
#pragma unroll
    for (int i = 0; i < 4; i++) {            // B: 1024 16B-chunks
        int t = tid + i * 256;
        int r = t >> 2, c = t & 3;
        int cs = c ^ ((r >> 1) & 3);
        cp_async16(bb + r * 64 + cs * 16, Bm + (size_t)(n0 + r) * KDIM + kk + c * 4);
    }
}

__device__ __forceinline__ void gemm_mma_body(const float* __restrict__ A,
                                              const float* __restrict__ Bm,
                                              float* __restrict__ C)
{
    extern __shared__ __align__(16) char smem[];
    const uint32_t sbase = smem_u32(smem);
    const int tid = threadIdx.x;
    const int wid = tid >> 5, lane = tid & 31;
    const int g = lane >> 2, q = lane & 3;
    const int m0 = blockIdx.y * GTM, n0 = blockIdx.x * GTN;
    const int wm = (wid >> 2) * 64, wn = (wid & 3) * 64;

    float acc[4][8][4];
#pragma unroll
    for (int mi = 0; mi < 4; mi++)
#pragma unroll
        for (int ni = 0; ni < 8; ni++)
#pragma unroll
            for (int j = 0; j < 4; j++) acc[mi][ni][j] = 0.0f;

    // Preload stages 0..2
#pragma unroll
    for (int s = 0; s < NSTG - 1; s++) {
        gemm_load_stage(sbase, s, s, A, Bm, m0, n0, tid);
        cp_commit();
    }

    for (int kt = 0; kt < KT; kt++) {
        if (kt + NSTG - 1 < KT)
            gemm_load_stage(sbase, (kt + NSTG - 1) & 3, kt + NSTG - 1, A, Bm, m0, n0, tid);
        cp_commit();
        cp_wait<NSTG - 1>();
        __syncthreads();

        const uint32_t ab = sbase + (kt & 3) * STG_B;
        const uint32_t bb = ab + A_TILE_B;
#pragma unroll
        for (int ks = 0; ks < 2; ks++) {
            const int kb = ks * 8;
            uint32_t a[4][4];
#pragma unroll
            for (int mi = 0; mi < 4; mi++) {
                int r0 = wm + mi * 16 + g;
                int r1 = r0 + 8;
                int f0 = ((r0 >> 1) & 3) << 2;
                int f1 = ((r1 >> 1) & 3) << 2;
                int klo = kb + q, khi = kb + q + 4;
                a[mi][0] = lds32(ab + (r0 * 16 + (klo ^ f0)) * 4);
                a[mi][1] = lds32(ab + (r1 * 16 + (klo ^ f1)) * 4);
                a[mi][2] = lds32(ab + (r0 * 16 + (khi ^ f0)) * 4);
                a[mi][3] = lds32(ab + (r1 * 16 + (khi ^ f1)) * 4);
            }
#pragma unroll
            for (int ni = 0; ni < 8; ni++) {
                int cn = wn + ni * 8 + g;
                int f = ((cn >> 1) & 3) << 2;
                uint32_t b0 = lds32(bb + (cn * 16 + ((kb + q) ^ f)) * 4);
                uint32_t b1 = lds32(bb + (cn * 16 + ((kb + q + 4) ^ f)) * 4);
#pragma unroll
                for (int mi = 0; mi < 4; mi++)
                    mma_tf32(acc[mi][ni], a[mi], b0, b1);
            }
        }
        __syncthreads();
    }

    // Epilogue
#pragma unroll
    for (int mi = 0; mi < 4; mi++) {
        int row = m0 + wm + mi * 16 + g;
#pragma unroll
        for (int ni = 0; ni < 8; ni++) {
            int col = n0 + wn + ni * 8 + q * 2;
            float2 v0 = make_float2(acc[mi][ni][0], acc[mi][ni][1]);
            float2 v1 = make_float2(acc[mi][ni][2], acc[mi][ni][3]);
            *(float2*)(C + (size_t)row * NDIM + col) = v0;
            *(float2*)(C + (size_t)(row + 8) * NDIM + col) = v1;
        }
    }
}

__global__ void __launch_bounds__(256, 1) gemm_mma_kernel(
    const float* __restrict__ A, const float* __restrict__ Bm, float* __restrict__ C)
{
    gemm_mma_body(A, Bm, C);
}

// QKV variant: one launch, z selects weight/output
__global__ void __launch_bounds__(256, 1) qkv_mma_kernel(
    const float* __restrict__ A,
    const float* __restrict__ Wq, const float* __restrict__ Wk, const float* __restrict__ Wv)
{
    const float* Bm;
    float* C;
    if (blockIdx.z == 0)      { Bm = Wq; C = g_Q; }
    else if (blockIdx.z == 1) { Bm = Wk; C = g_K; }
    else                      { Bm = Wv; C = g_V; }
    gemm_mma_body(Bm == Wq ? A : A, Bm, C);
}

// ---------------------------------------------------------------------------
// tf32 round-to-nearest pre-conversion
// ---------------------------------------------------------------------------
__global__ void cvt_tf32_kernel(const float* __restrict__ in, float* __restrict__ out, int n4)
{
    int i = blockIdx.x * blockDim.x + threadIdx.x;
    if (i < n4) {
        float4 v = ((const float4*)in)[i];
        v.x = tf32r(v.x); v.y = tf32r(v.y); v.z = tf32r(v.z); v.w = tf32r(v.w);
        ((float4*)out)[i] = v;
    }
}

// ---------------------------------------------------------------------------
// RoPE in place on g_Q, g_K.
// ---------------------------------------------------------------------------
__global__ void rope_kernel(const float* __restrict__ cosT, const float* __restrict__ sinT)
{
    int idx = blockIdx.x * blockDim.x + threadIdx.x;
    int i = idx & 63;
    int rest = idx >> 6;
    int m = rest >> 4;
    int t = m & (SS - 1);
    float c = cosT[t * 64 + i];
    float s = sinT[t * 64 + i];
    size_t off = (size_t)idx * 2;
    float2 qv = *(const float2*)(g_Q + off);
    float2 kv = *(const float2*)(g_K + off);
    float2 qo, ko;
    qo.x = qv.x * c - qv.y * s;
    qo.y = qv.x * s + qv.y * c;
    ko.x = kv.x * c - kv.y * s;
    ko.y = kv.x * s + kv.y * c;
    *(float2*)(g_Q + off) = qo;
    *(float2*)(g_K + off) = ko;
}

// ---------------------------------------------------------------------------
// Flash attention (fp32, causal) — stores tf32-rounded.
// ---------------------------------------------------------------------------
#define FBQ 64
#define FBK 64
#define FSCALE 0.08838834764831845f
#define FLASH_SMEM (114688)

__global__ void __launch_bounds__(256) flash_attn_kernel()
{
    extern __shared__ __align__(16) float sm[];
    float* Qs = sm;
    float* Ks = sm + 8192;
    float* Vs = sm + 16384;
    float* Ps = sm + 24576;

    const int q0 = blockIdx.x * FBQ;
    const int h  = blockIdx.y;
    const int b  = blockIdx.z;
    const int tid = threadIdx.x;
    const int ty = tid >> 4;
    const int tx = tid & 15;
    const int r0 = ty * 4;
    const int c0 = tx * 4;
    const int d0 = tx * 8;

    const size_t head_off = (size_t)h * FHD;
    const size_t brow = (size_t)b * SS;

#pragma unroll
    for (int i = 0; i < 8; i++) {
        int idx = tid + i * 256;
        int r = idx >> 5;
        int hd = (idx & 31) << 2;
        float4 v = *(const float4*)(g_Q + (brow + q0 + r) * (size_t)DD + head_off + hd);
        Qs[(hd + 0) * 64 + r] = v.x;
        Qs[(hd + 1) * 64 + r] = v.y;
        Qs[(hd + 2) * 64 + r] = v.z;
        Qs[(hd + 3) * 64 + r] = v.w;
    }

    float m_i[4], l_i[4], o[4][8];
#pragma unroll
    for (int i = 0; i < 4; i++) {
        m_i[i] = -1e30f;
        l_i[i] = 0.0f;
#pragma unroll
        for (int j = 0; j < 8; j++) o[i][j] = 0.0f;
    }

    for (int k0 = 0; k0 <= q0; k0 += FBK) {
        __syncthreads();
#pragma unroll
        for (int i = 0; i < 8; i++) {
            int idx = tid + i * 256;
            int r = idx >> 5;
            int hd = (idx & 31) << 2;
            float4 kv = *(const float4*)(g_K + (brow + k0 + r) * (size_t)DD + head_off + hd);
            Ks[(hd + 0) * 64 + r] = kv.x;
            Ks[(hd + 1) * 64 + r] = kv.y;
            Ks[(hd + 2) * 64 + r] = kv.z;
            Ks[(hd + 3) * 64 + r] = kv.w;
            float4 vv = *(const float4*)(g_V + (brow + k0 + r) * (size_t)DD + head_off + hd);
            *(float4*)&Vs[r * 128 + hd] = vv;
        }
        __syncthreads();

        float s[4][4];
#pragma unroll
        for (int i = 0; i < 4; i++)
#pragma unroll
            for (int j = 0; j < 4; j++) s[i][j] = 0.0f;

#pragma unroll 8
        for (int k = 0; k < FHD; k++) {
            float4 qa = *(const float4*)&Qs[k * 64 + r0];
            float4 kb = *(const float4*)&Ks[k * 64 + c0];
            float aq[4] = {qa.x, qa.y, qa.z, qa.w};
            float bk[4] = {kb.x, kb.y, kb.z, kb.w};
#pragma unroll
            for (int i = 0; i < 4; i++)
#pragma unroll
                for (int j = 0; j < 4; j++)
                    s[i][j] = fmaf(aq[i], bk[j], s[i][j]);
        }

        float tmax[4];
#pragma unroll
        for (int i = 0; i < 4; i++) {
#pragma unroll
            for (int j = 0; j < 4; j++) {
                float v = s[i][j] * FSCALE;
                if (k0 + c0 + j > q0 + r0 + i) v = -1e30f;
                s[i][j] = v;
            }
            tmax[i] = fmaxf(fmaxf(s[i][0], s[i][1]), fmaxf(s[i][2], s[i][3]));
        }
#pragma unroll
        for (int w = 1; w < 16; w <<= 1)
#pragma unroll
            for (int i = 0; i < 4; i++)
                tmax[i] = fmaxf(tmax[i], __shfl_xor_sync(0xffffffffu, tmax[i], w));

        float rsum[4];
#pragma unroll
        for (int i = 0; i < 4; i++) {
            float m_new = fmaxf(m_i[i], tmax[i]);
            float corr = __expf(m_i[i] - m_new);
            m_i[i] = m_new;
            float rs = 0.0f;
#pragma unroll
            for (int j = 0; j < 4; j++) {
                float p = __expf(s[i][j] - m_new);
                s[i][j] = p;
                rs += p;
            }
            rsum[i] = rs;
            l_i[i] *= corr;
#pragma unroll
            for (int j = 0; j < 8; j++) o[i][j] *= corr;
        }
#pragma unroll
        for (int w = 1; w < 16; w <<= 1)
#pragma unroll
            for (int i = 0; i < 4; i++)
                rsum[i] += __shfl_xor_sync(0xffffffffu, rsum[i], w);
#pragma unroll
        for (int i = 0; i < 4; i++) l_i[i] += rsum[i];

#pragma unroll
        for (int i = 0; i < 4; i++)
#pragma unroll
            for (int j = 0; j < 4; j++)
                Ps[(c0 + j) * 64 + (r0 + i)] = s[i][j];
        __syncthreads();

#pragma unroll 4
        for (int kc = 0; kc < FBK; kc++) {
            float4 p4  = *(const float4*)&Ps[kc * 64 + r0];
            float4 vlo = *(const float4*)&Vs[kc * 128 + d0];
            float4 vhi = *(const float4*)&Vs[kc * 128 + d0 + 4];
            float pv[4] = {p4.x, p4.y, p4.z, p4.w};
            float vv[8] = {vlo.x, vlo.y, vlo.z, vlo.w, vhi.x, vhi.y, vhi.z, vhi.w};
#pragma unroll
            for (int i = 0; i < 4; i++)
#pragma unroll
                for (int j = 0; j < 8; j++)
                    o[i][j] = fmaf(pv[i], vv[j], o[i][j]);
        }
    }

    // Normalize + store (tf32-rounded: g_AO feeds the mma.sync out-projection)
#pragma unroll
    for (int i = 0; i < 4; i++) {
        float inv = 1.0f / l_i[i];
        float4 o0, o1;
        o0.x = tf32r(o[i][0] * inv); o0.y = tf32r(o[i][1] * inv);
        o0.z = tf32r(o[i][2] * inv); o0.w = tf32r(o[i][3] * inv);
        o1.x = tf32r(o[i][4] * inv); o1.y = tf32r(o[i][5] * inv);
        o1.z = tf32r(o[i][6] * inv); o1.w = tf32r(o[i][7] * inv);
        float* dst = g_AO + (brow + q0 + r0 + i) * (size_t)DD + head_off + d0;
        *(float4*)dst = o0;
        *(float4*)(dst + 4) = o1;
    }
}

// ---------------------------------------------------------------------------
// Launch
// ---------------------------------------------------------------------------
extern "C" void kernel_launch(void* const* d_in, const int* in_sizes, int n_in,
                              void* d_out, int out_size)
{
    const float* x  = (const float*)d_in[0];
    const float* wq = (const float*)d_in[1];
    const float* wk = (const float*)d_in[2];
    const float* wv = (const float*)d_in[3];
    const float* wo = (const float*)d_in[4];
    const float* fc = (const float*)d_in[5];
    const float* fs = (const float*)d_in[6];
    float* out = (float*)d_out;

    void *p_xr, *p_wqr, *p_wkr, *p_wvr, *p_wor, *p_ao;
    cudaGetSymbolAddress(&p_xr,  g_xr);
    cudaGetSymbolAddress(&p_wqr, g_wqr);
    cudaGetSymbolAddress(&p_wkr, g_wkr);
    cudaGetSymbolAddress(&p_wvr, g_wvr);
    cudaGetSymbolAddress(&p_wor, g_wor);
    cudaGetSymbolAddress(&p_ao,  g_AO);

    cudaFuncSetAttribute(gemm_mma_kernel,
                         cudaFuncAttributeMaxDynamicSharedMemorySize, GEMM_SMEM);
    cudaFuncSetAttribute(qkv_mma_kernel,
                         cudaFuncAttributeMaxDynamicSharedMemorySize, GEMM_SMEM);
    cudaFuncSetAttribute(flash_attn_kernel,
                         cudaFuncAttributeMaxDynamicSharedMemorySize, FLASH_SMEM);

    // 0) tf32-round operands
    cvt_tf32_kernel<<<(MDIM * KDIM / 4 + 255) / 256, 256>>>(x,  (float*)p_xr,  MDIM * KDIM / 4);
    cvt_tf32_kernel<<<(NDIM * KDIM / 4 + 255) / 256, 256>>>(wq, (float*)p_wqr, NDIM * KDIM / 4);
    cvt_tf32_kernel<<<(NDIM * KDIM / 4 + 255) / 256, 256>>>(wk, (float*)p_wkr, NDIM * KDIM / 4);
    cvt_tf32_kernel<<<(NDIM * KDIM / 4 + 255) / 256, 256>>>(wv, (float*)p_wvr, NDIM * KDIM / 4);
    cvt_tf32_kernel<<<(NDIM * KDIM / 4 + 255) / 256, 256>>>(wo, (float*)p_wor, NDIM * KDIM / 4);

    // 1) QKV projections (tensor cores, tf32 mma.sync)
    dim3 gq(NDIM / GTN, MDIM / GTM, 3);   // (8, 32, 3)
    qkv_mma_kernel<<<gq, 256, GEMM_SMEM>>>((const float*)p_xr,
                                           (const float*)p_wqr,
                                           (const float*)p_wkr,
                                           (const float*)p_wvr);

    // 2) RoPE in place on Q and K
    rope_kernel<<<(BB * SS * DD / 2) / 256, 256>>>(fc, fs);

    // 3) Causal flash attention -> g_AO (tf32-rounded)
    flash_attn_kernel<<<dim3(SS / FBQ, NH, BB), 256, FLASH_SMEM>>>();

    // 4) Output projection (tensor cores)
    gemm_mma_kernel<<<dim3(NDIM / GTN, MDIM / GTM), 256, GEMM_SMEM>>>(
        (const float*)p_ao, (const float*)p_wor, out);
}

// round 5
// speedup vs baseline: 3.8821x; 2.1498x over previous
#include <cuda_runtime.h>
#include <cuda_bf16.h>
#include <cstddef>
#include <cstdint>

// Problem constants
#define BB 2
#define SS 2048
#define DD 2048
#define NH 16
#define FHD 128
#define KDIM 2048
#define NDIM 2048
#define MDIM (BB * SS)   // 4096

// ---------------------------------------------------------------------------
// Scratch (device globals — no allocation allowed)
// ---------------------------------------------------------------------------
__device__ float g_Q[(size_t)BB * SS * DD];
__device__ float g_K[(size_t)BB * SS * DD];
__device__ float g_V[(size_t)BB * SS * DD];
__device__ float g_AO[(size_t)BB * SS * DD];
// tf32-rounded operand copies
__device__ float g_xr[(size_t)MDIM * KDIM];
__device__ float g_wqr[(size_t)NDIM * KDIM];
__device__ float g_wkr[(size_t)NDIM * KDIM];
__device__ float g_wvr[(size_t)NDIM * KDIM];
__device__ float g_wor[(size_t)NDIM * KDIM];

// ---------------------------------------------------------------------------
// Helpers
// ---------------------------------------------------------------------------
__device__ __forceinline__ uint32_t smem_u32(const void* p) {
    uint32_t a;
    asm("{ .reg .u64 t; cvta.to.shared.u64 t, %1; cvt.u32.u64 %0, t; }" : "=r"(a) : "l"(p));
    return a;
}

__device__ __forceinline__ void cp_async16(uint32_t dst, const void* src) {
    asm volatile("cp.async.cg.shared.global [%0], [%1], 16;" :: "r"(dst), "l"(src) : "memory");
}
__device__ __forceinline__ void cp_commit() {
    asm volatile("cp.async.commit_group;" ::: "memory");
}
template <int N>
__device__ __forceinline__ void cp_wait() {
    asm volatile("cp.async.wait_group %0;" :: "n"(N) : "memory");
}

__device__ __forceinline__ uint32_t lds32(uint32_t addr) {
    uint32_t v;
    asm volatile("ld.shared.b32 %0, [%1];" : "=r"(v) : "r"(addr));
    return v;
}

__device__ __forceinline__ void mma_tf32(float* d, const uint32_t* a,
                                         uint32_t b0, uint32_t b1)
{
    asm volatile(
        "mma.sync.aligned.m16n8k8.row.col.f32.tf32.tf32.f32 "
        "{%0,%1,%2,%3}, {%4,%5,%6,%7}, {%8,%9}, {%0,%1,%2,%3};"
        : "+f"(d[0]), "+f"(d[1]), "+f"(d[2]), "+f"(d[3])
        : "r"(a[0]), "r"(a[1]), "r"(a[2]), "r"(a[3]), "r"(b0), "r"(b1));
}

__device__ __forceinline__ float tf32r(float v) {
    asm("cvt.rna.tf32.f32 %0, %1;" : "=f"(v) : "f"(v));
    return v;
}

// ---------------------------------------------------------------------------
// tf32 mma.sync GEMM: C[M,N] = A[M,K] * B[N,K]^T, row-major K-contiguous.
// CTA 128x256, 8 warps (2x4), warp tile 64x64, K-tile 16, 4-stage cp.async.
// Shared layout [row][16] floats, swizzle k' = k ^ (((row>>1)&3)<<2).
// ---------------------------------------------------------------------------
#define GTM 128
#define GTN 256
#define GTK 16
#define NSTG 4
#define A_TILE_B (GTM * GTK * 4)          // 8192
#define B_TILE_B (GTN * GTK * 4)          // 16384
#define STG_B (A_TILE_B + B_TILE_B)       // 24576
#define GEMM_SMEM (NSTG * STG_B)          // 98304
#define KT (KDIM / GTK)                   // 128

__device__ __forceinline__ void gemm_load_stage(uint32_t sbase, int s, int kt,
                                                const float* __restrict__ A,
                                                const float* __restrict__ Bm,
                                                int m0, int n0, int tid)
{
    const uint32_t ab = sbase + s * STG_B;
    const uint32_t bb = ab + A_TILE_B;
    const int kk = kt * GTK;
#pragma unroll
    for (int i = 0; i < 2; i++) {            // A: 512 16B-chunks
        int t = tid + i * 256;
        int r = t >> 2, c = t & 3;
        int cs = c ^ ((r >> 1) & 3);
        cp_async16(ab + r * 64 + cs * 16, A + (size_t)(m0 + r) * KDIM + kk + c * 4);
    }
#pragma unroll
    for (int i = 0; i < 4; i++) {            // B: 1024 16B-chunks
        int t = tid + i * 256;
        int r = t >> 2, c = t & 3;
        int cs = c ^ ((r >> 1) & 3);
        cp_async16(bb + r * 64 + cs * 16, Bm + (size_t)(n0 + r) * KDIM + kk + c * 4);
    }
}

__device__ __forceinline__ void gemm_mma_body(const float* __restrict__ A,
                                              const float* __restrict__ Bm,
                                              float* __restrict__ C)
{
    extern __shared__ __align__(16) char smem[];
    const uint32_t sbase = smem_u32(smem);
    const int tid = threadIdx.x;
    const int wid = tid >> 5, lane = tid & 31;
    const int g = lane >> 2, q = lane & 3;
    const int m0 = blockIdx.y * GTM, n0 = blockIdx.x * GTN;
    const int wm = (wid >> 2) * 64, wn = (wid & 3) * 64;

    float acc[4][8][4];
#pragma unroll
    for (int mi = 0; mi < 4; mi++)
#pragma unroll
        for (int ni = 0; ni < 8; ni++)
#pragma unroll
            for (int j = 0; j < 4; j++) acc[mi][ni][j] = 0.0f;

#pragma unroll
    for (int s = 0; s < NSTG - 1; s++) {
        gemm_load_stage(sbase, s, s, A, Bm, m0, n0, tid);
        cp_commit();
    }

    for (int kt = 0; kt < KT; kt++) {
        if (kt + NSTG - 1 < KT)
            gemm_load_stage(sbase, (kt + NSTG - 1) & 3, kt + NSTG - 1, A, Bm, m0, n0, tid);
        cp_commit();
        cp_wait<NSTG - 1>();
        __syncthreads();

        const uint32_t ab = sbase + (kt & 3) * STG_B;
        const uint32_t bb = ab + A_TILE_B;
#pragma unroll
        for (int ks = 0; ks < 2; ks++) {
            const int kb = ks * 8;
            uint32_t a[4][4];
#pragma unroll
            for (int mi = 0; mi < 4; mi++) {
                int r0 = wm + mi * 16 + g;
                int r1 = r0 + 8;
                int f0 = ((r0 >> 1) & 3) << 2;
                int f1 = ((r1 >> 1) & 3) << 2;
                int klo = kb + q, khi = kb + q + 4;
                a[mi][0] = lds32(ab + (r0 * 16 + (klo ^ f0)) * 4);
                a[mi][1] = lds32(ab + (r1 * 16 + (klo ^ f1)) * 4);
                a[mi][2] = lds32(ab + (r0 * 16 + (khi ^ f0)) * 4);
                a[mi][3] = lds32(ab + (r1 * 16 + (khi ^ f1)) * 4);
            }
#pragma unroll
            for (int ni = 0; ni < 8; ni++) {
                int cn = wn + ni * 8 + g;
                int f = ((cn >> 1) & 3) << 2;
                uint32_t b0 = lds32(bb + (cn * 16 + ((kb + q) ^ f)) * 4);
                uint32_t b1 = lds32(bb + (cn * 16 + ((kb + q + 4) ^ f)) * 4);
#pragma unroll
                for (int mi = 0; mi < 4; mi++)
                    mma_tf32(acc[mi][ni], a[mi], b0, b1);
            }
        }
        __syncthreads();
    }

#pragma unroll
    for (int mi = 0; mi < 4; mi++) {
        int row = m0 + wm + mi * 16 + g;
#pragma unroll
        for (int ni = 0; ni < 8; ni++) {
            int col = n0 + wn + ni * 8 + q * 2;
            float2 v0 = make_float2(acc[mi][ni][0], acc[mi][ni][1]);
            float2 v1 = make_float2(acc[mi][ni][2], acc[mi][ni][3]);
            *(float2*)(C + (size_t)row * NDIM + col) = v0;
            *(float2*)(C + (size_t)(row + 8) * NDIM + col) = v1;
        }
    }
}

__global__ void __launch_bounds__(256, 1) gemm_mma_kernel(
    const float* __restrict__ A, const float* __restrict__ Bm, float* __restrict__ C)
{
    gemm_mma_body(A, Bm, C);
}

__global__ void __launch_bounds__(256, 1) qkv_mma_kernel(
    const float* __restrict__ A,
    const float* __restrict__ Wq, const float* __restrict__ Wk, const float* __restrict__ Wv)
{
    const float* Bm;
    float* C;
    if (blockIdx.z == 0)      { Bm = Wq; C = g_Q; }
    else if (blockIdx.z == 1) { Bm = Wk; C = g_K; }
    else                      { Bm = Wv; C = g_V; }
    gemm_mma_body(A, Bm, C);
}

// ---------------------------------------------------------------------------
// tf32 round-to-nearest pre-conversion (also used in-place on g_V)
// ---------------------------------------------------------------------------
__global__ void cvt_tf32_kernel(const float* __restrict__ in, float* __restrict__ out, int n4)
{
    int i = blockIdx.x * blockDim.x + threadIdx.x;
    if (i < n4) {
        float4 v = ((const float4*)in)[i];
        v.x = tf32r(v.x); v.y = tf32r(v.y); v.z = tf32r(v.z); v.w = tf32r(v.w);
        ((float4*)out)[i] = v;
    }
}

// ---------------------------------------------------------------------------
// RoPE in place on g_Q, g_K — outputs tf32-rounded (feeds mma directly).
// ---------------------------------------------------------------------------
__global__ void rope_kernel(const float* __restrict__ cosT, const float* __restrict__ sinT)
{
    int idx = blockIdx.x * blockDim.x + threadIdx.x;
    int i = idx & 63;
    int rest = idx >> 6;
    int m = rest >> 4;
    int t = m & (SS - 1);
    float c = cosT[t * 64 + i];
    float s = sinT[t * 64 + i];
    size_t off = (size_t)idx * 2;
    float2 qv = *(const float2*)(g_Q + off);
    float2 kv = *(const float2*)(g_K + off);
    float2 qo, ko;
    qo.x = tf32r(qv.x * c - qv.y * s);
    qo.y = tf32r(qv.x * s + qv.y * c);
    ko.x = tf32r(kv.x * c - kv.y * s);
    ko.y = tf32r(kv.x * s + kv.y * c);
    *(float2*)(g_Q + off) = qo;
    *(float2*)(g_K + off) = ko;
}

// ---------------------------------------------------------------------------
// Flash attention on tensor cores (tf32 mma.sync, causal).
// CTA: 128 q-rows x one (b,h). 8 warps, warp tile m16. FBK = 64.
// Smem (floats): K buf [64][132] x2, V buf [64][136] x2, P [128][68].
// Strides chosen for conflict-free fragment LDS.
// ---------------------------------------------------------------------------
#define FBQ 128
#define FBK 64
#define FSCALE 0.08838834764831845f   // 1/sqrt(128)
#define KS_STR 132
#define VS_STR 136
#define PS_STR 68
#define KOFF0 0
#define VOFF0 8448
#define KOFF1 17152
#define VOFF1 25600
#define PSOFF 34304
#define FLASH_SMEM ((PSOFF + FBQ * PS_STR) * 4)   // 172032 B

__device__ __forceinline__ void flash_load_kv(uint32_t sb, int buf, int k0,
                                              size_t brow, size_t head, int tid)
{
    const uint32_t kb = sb + (buf ? KOFF1 : KOFF0) * 4;
    const uint32_t vb = sb + (buf ? VOFF1 : VOFF0) * 4;
#pragma unroll
    for (int i = 0; i < 8; i++) {
        int id = tid + i * 256;
        int r = id >> 5, c = id & 31;
        cp_async16(kb + (r * KS_STR + c * 4) * 4,
                   g_K + (brow + k0 + r) * (size_t)DD + head + c * 4);
        cp_async16(vb + (r * VS_STR + c * 4) * 4,
                   g_V + (brow + k0 + r) * (size_t)DD + head + c * 4);
    }
}

__global__ void __launch_bounds__(256, 1) flash_mma_kernel()
{
    extern __shared__ __align__(16) float sm[];
    const uint32_t sb = smem_u32(sm);
    const int tid = threadIdx.x;
    const int wid = tid >> 5, lane = tid & 31;
    const int g = lane >> 2, q = lane & 3;
    // reverse x so heaviest (largest q0) CTAs launch first
    const int q0 = (gridDim.x - 1 - blockIdx.x) * FBQ;
    const int h = blockIdx.y, b = blockIdx.z;
    const size_t brow = (size_t)b * SS;
    const size_t head = (size_t)h * FHD;

    // --- Prologue: stage Q tile [128][132] then read warp-private fragments ---
#pragma unroll
    for (int i = 0; i < 16; i++) {
        int id = tid + i * 256;
        int r = id >> 5, c = id & 31;
        cp_async16(sb + (r * KS_STR + c * 4) * 4,
                   g_Q + (brow + q0 + r) * (size_t)DD + head + c * 4);
    }
    cp_commit(); cp_wait<0>(); __syncthreads();

    const int rl0 = wid * 16 + g;      // local row of frag row g
    const int rl1 = rl0 + 8;
    uint32_t qf[16][4];
#pragma unroll
    for (int ks = 0; ks < 16; ks++) {
        float a0 = sm[rl0 * KS_STR + 8 * ks + q];
        float a1 = sm[rl1 * KS_STR + 8 * ks + q];
        float a2 = sm[rl0 * KS_STR + 8 * ks + q + 4];
        float a3 = sm[rl1 * KS_STR + 8 * ks + q + 4];
        qf[ks][0] = __float_as_uint(tf32r(a0 * FSCALE));
        qf[ks][1] = __float_as_uint(tf32r(a1 * FSCALE));
        qf[ks][2] = __float_as_uint(tf32r(a2 * FSCALE));
        qf[ks][3] = __float_as_uint(tf32r(a3 * FSCALE));
    }
    __syncthreads();

    const int rg0 = q0 + rl0;          // global q rows for this lane
    const int rg1 = rg0 + 8;

    float m0 = -1e30f, m1 = -1e30f, l0 = 0.0f, l1 = 0.0f;
    float o[16][4];
#pragma unroll
    for (int nf = 0; nf < 16; nf++)
#pragma unroll
        for (int j = 0; j < 4; j++) o[nf][j] = 0.0f;

    const int ktiles = q0 / FBK + 2;

    flash_load_kv(sb, 0, 0, brow, head, tid);
    cp_commit();

    for (int t = 0; t < ktiles; t++) {
        if (t + 1 < ktiles)
            flash_load_kv(sb, (t + 1) & 1, (t + 1) * FBK, brow, head, tid);
        cp_commit();
        cp_wait<1>();
        __syncthreads();

        const int k0 = t * FBK;
        const uint32_t kb = sb + ((t & 1) ? KOFF1 : KOFF0) * 4;
        const uint32_t vb = sb + ((t & 1) ? VOFF1 : VOFF0) * 4;

        // ---- S = Q K^T (scaled) ----
        float s[8][4];
#pragma unroll
        for (int nf = 0; nf < 8; nf++)
#pragma unroll
            for (int j = 0; j < 4; j++) s[nf][j] = 0.0f;

#pragma unroll
        for (int ks = 0; ks < 16; ks++) {
#pragma unroll
            for (int nf = 0; nf < 8; nf++) {
                uint32_t b0 = lds32(kb + ((nf * 8 + g) * KS_STR + 8 * ks + q) * 4);
                uint32_t b1 = lds32(kb + ((nf * 8 + g) * KS_STR + 8 * ks + q + 4) * 4);
                mma_tf32(s[nf], qf[ks], b0, b1);
            }
        }

        // ---- causal mask (warp-uniform branch) ----
        if (k0 + FBK - 1 > q0 + wid * 16) {
#pragma unroll
            for (int nf = 0; nf < 8; nf++) {
                int c0 = k0 + nf * 8 + 2 * q;
                if (c0 > rg0)     s[nf][0] = -1e30f;
                if (c0 + 1 > rg0) s[nf][1] = -1e30f;
                if (c0 > rg1)     s[nf][2] = -1e30f;
                if (c0 + 1 > rg1) s[nf][3] = -1e30f;
            }
        }

        // ---- online softmax ----
        float mx0 = -1e30f, mx1 = -1e30f;
#pragma unroll
        for (int nf = 0; nf < 8; nf++) {
            mx0 = fmaxf(mx0, fmaxf(s[nf][0], s[nf][1]));
            mx1 = fmaxf(mx1, fmaxf(s[nf][2], s[nf][3]));
        }
        mx0 = fmaxf(mx0, __shfl_xor_sync(0xffffffffu, mx0, 1));
        mx0 = fmaxf(mx0, __shfl_xor_sync(0xffffffffu, mx0, 2));
        mx1 = fmaxf(mx1, __shfl_xor_sync(0xffffffffu, mx1, 1));
        mx1 = fmaxf(mx1, __shfl_xor_sync(0xffffffffu, mx1, 2));

        float mn0 = fmaxf(m0, mx0), mn1 = fmaxf(m1, mx1);
        float cr0 = __expf(m0 - mn0), cr1 = __expf(m1 - mn1);
        m0 = mn0; m1 = mn1;

        float rs0 = 0.0f, rs1 = 0.0f;
#pragma unroll
        for (int nf = 0; nf < 8; nf++) {
            s[nf][0] = __expf(s[nf][0] - mn0);
            s[nf][1] = __expf(s[nf][1] - mn0);
            s[nf][2] = __expf(s[nf][2] - mn1);
            s[nf][3] = __expf(s[nf][3] - mn1);
            rs0 += s[nf][0] + s[nf][1];
            rs1 += s[nf][2] + s[nf][3];
        }
        rs0 += __shfl_xor_sync(0xffffffffu, rs0, 1);
        rs0 += __shfl_xor_sync(0xffffffffu, rs0, 2);
        rs1 += __shfl_xor_sync(0xffffffffu, rs1, 1);
        rs1 += __shfl_xor_sync(0xffffffffu, rs1, 2);
        l0 = l0 * cr0 + rs0;
        l1 = l1 * cr1 + rs1;

#pragma unroll
        for (int nf = 0; nf < 16; nf++) {
            o[nf][0] *= cr0; o[nf][1] *= cr0;
            o[nf][2] *= cr1; o[nf][3] *= cr1;
        }

        // ---- write P (tf32-rounded), warp-private rows ----
#pragma unroll
        for (int nf = 0; nf < 8; nf++) {
            sm[PSOFF + rl0 * PS_STR + nf * 8 + 2 * q]     = tf32r(s[nf][0]);
            sm[PSOFF + rl0 * PS_STR + nf * 8 + 2 * q + 1] = tf32r(s[nf][1]);
            sm[PSOFF + rl1 * PS_STR + nf * 8 + 2 * q]     = tf32r(s[nf][2]);
            sm[PSOFF + rl1 * PS_STR + nf * 8 + 2 * q + 1] = tf32r(s[nf][3]);
        }
        __syncwarp();

        // ---- O += P V ----
#pragma unroll 2
        for (int ks2 = 0; ks2 < 8; ks2++) {
            uint32_t pa[4];
            pa[0] = lds32(sb + (PSOFF + rl0 * PS_STR + 8 * ks2 + q) * 4);
            pa[1] = lds32(sb + (PSOFF + rl1 * PS_STR + 8 * ks2 + q) * 4);
            pa[2] = lds32(sb + (PSOFF + rl0 * PS_STR + 8 * ks2 + q + 4) * 4);
            pa[3] = lds32(sb + (PSOFF + rl1 * PS_STR + 8 * ks2 + q + 4) * 4);
#pragma unroll
            for (int nf = 0; nf < 16; nf++) {
                uint32_t b0 = lds32(vb + ((8 * ks2 + q) * VS_STR + nf * 8 + g) * 4);
                uint32_t b1 = lds32(vb + ((8 * ks2 + q + 4) * VS_STR + nf * 8 + g) * 4);
                mma_tf32(o[nf], pa, b0, b1);
            }
        }
        __syncwarp();
        __syncthreads();
    }

    // ---- normalize + store (tf32-rounded; feeds out-projection mma) ----
    float i0 = 1.0f / l0, i1 = 1.0f / l1;
#pragma unroll
    for (int nf = 0; nf < 16; nf++) {
        float2 v0 = make_float2(tf32r(o[nf][0] * i0), tf32r(o[nf][1] * i0));
        float2 v1 = make_float2(tf32r(o[nf][2] * i1), tf32r(o[nf][3] * i1));
        *(float2*)(g_AO + (brow + rg0) * (size_t)DD + head + nf * 8 + 2 * q) = v0;
        *(float2*)(g_AO + (brow + rg1) * (size_t)DD + head + nf * 8 + 2 * q) = v1;
    }
}

// ---------------------------------------------------------------------------
// Launch
// ---------------------------------------------------------------------------
extern "C" void kernel_launch(void* const* d_in, const int* in_sizes, int n_in,
                              void* d_out, int out_size)
{
    const float* x  = (const float*)d_in[0];
    const float* wq = (const float*)d_in[1];
    const float* wk = (const float*)d_in[2];
    const float* wv = (const float*)d_in[3];
    const float* wo = (const float*)d_in[4];
    const float* fc = (const float*)d_in[5];
    const float* fs = (const float*)d_in[6];
    float* out = (float*)d_out;

    void *p_xr, *p_wqr, *p_wkr, *p_wvr, *p_wor, *p_ao, *p_v;
    cudaGetSymbolAddress(&p_xr,  g_xr);
    cudaGetSymbolAddress(&p_wqr, g_wqr);
    cudaGetSymbolAddress(&p_wkr, g_wkr);
    cudaGetSymbolAddress(&p_wvr, g_wvr);
    cudaGetSymbolAddress(&p_wor, g_wor);
    cudaGetSymbolAddress(&p_ao,  g_AO);
    cudaGetSymbolAddress(&p_v,   g_V);

    cudaFuncSetAttribute(gemm_mma_kernel,
                         cudaFuncAttributeMaxDynamicSharedMemorySize, GEMM_SMEM);
    cudaFuncSetAttribute(qkv_mma_kernel,
                         cudaFuncAttributeMaxDynamicSharedMemorySize, GEMM_SMEM);
    cudaFuncSetAttribute(flash_mma_kernel,
                         cudaFuncAttributeMaxDynamicSharedMemorySize, FLASH_SMEM);

    // 0) tf32-round GEMM operands
    cvt_tf32_kernel<<<(MDIM * KDIM / 4 + 255) / 256, 256>>>(x,  (float*)p_xr,  MDIM * KDIM / 4);
    cvt_tf32_kernel<<<(NDIM * KDIM / 4 + 255) / 256, 256>>>(wq, (float*)p_wqr, NDIM * KDIM / 4);
    cvt_tf32_kernel<<<(NDIM * KDIM / 4 + 255) / 256, 256>>>(wk, (float*)p_wkr, NDIM * KDIM / 4);
    cvt_tf32_kernel<<<(NDIM * KDIM / 4 + 255) / 256, 256>>>(wv, (float*)p_wvr, NDIM * KDIM / 4);
    cvt_tf32_kernel<<<(NDIM * KDIM / 4 + 255) / 256, 256>>>(wo, (float*)p_wor, NDIM * KDIM / 4);

    // 1) QKV projections (tensor cores)
    dim3 gq(NDIM / GTN, MDIM / GTM, 3);
    qkv_mma_kernel<<<gq, 256, GEMM_SMEM>>>((const float*)p_xr,
                                           (const float*)p_wqr,
                                           (const float*)p_wkr,
                                           (const float*)p_wvr);

    // 2) tf32-round V in place (flash mma reads it as B operand)
    cvt_tf32_kernel<<<(MDIM * DD / 4 + 255) / 256, 256>>>((const float*)p_v,
                                                          (float*)p_v, MDIM * DD / 4);

    // 3) RoPE in place on Q and K (tf32-rounded output)
    rope_kernel<<<(BB * SS * DD / 2) / 256, 256>>>(fc, fs);

    // 4) Causal flash attention on tensor cores -> g_AO
    flash_mma_kernel<<<dim3(SS / FBQ, NH, BB), 256, FLASH_SMEM>>>();

    // 5) Output projection (tensor cores)
    gemm_mma_kernel<<<dim3(NDIM / GTN, MDIM / GTM), 256, GEMM_SMEM>>>(
        (const float*)p_ao, (const float*)p_wor, out);
}

// round 6
// speedup vs baseline: 6.1158x; 1.5754x over previous
#include <cuda_runtime.h>
#include <cuda_fp16.h>
#include <cstddef>
#include <cstdint>

// Problem constants
#define BB 2
#define SS 2048
#define DD 2048
#define NH 16
#define FHD 128
#define KDIM 2048
#define NDIM 2048
#define MDIM (BB * SS)   // 4096

// ---------------------------------------------------------------------------
// Scratch (device globals — no allocation allowed)
// ---------------------------------------------------------------------------
__device__ float  g_Q[(size_t)MDIM * DD];     // fp32 QKV-proj outputs
__device__ float  g_K[(size_t)MDIM * DD];
__device__ float  g_V[(size_t)MDIM * DD];
__device__ __half g_Qh[(size_t)MDIM * DD];    // post-rope half Q/K, half V
__device__ __half g_Kh[(size_t)MDIM * DD];
__device__ __half g_Vh[(size_t)MDIM * DD];
__device__ __half g_AOh[(size_t)MDIM * DD];   // flash output (half)
__device__ __half g_xh[(size_t)MDIM * KDIM];  // half operand copies
__device__ __half g_wqh[(size_t)NDIM * KDIM];
__device__ __half g_wkh[(size_t)NDIM * KDIM];
__device__ __half g_wvh[(size_t)NDIM * KDIM];
__device__ __half g_woh[(size_t)NDIM * KDIM];

// ---------------------------------------------------------------------------
// Helpers
// ---------------------------------------------------------------------------
__device__ __forceinline__ uint32_t smem_u32(const void* p) {
    uint32_t a;
    asm("{ .reg .u64 t; cvta.to.shared.u64 t, %1; cvt.u32.u64 %0, t; }" : "=r"(a) : "l"(p));
    return a;
}
__device__ __forceinline__ void cp_async16(uint32_t dst, const void* src) {
    asm volatile("cp.async.cg.shared.global [%0], [%1], 16;" :: "r"(dst), "l"(src) : "memory");
}
__device__ __forceinline__ void cp_commit() {
    asm volatile("cp.async.commit_group;" ::: "memory");
}
template <int N>
__device__ __forceinline__ void cp_wait() {
    asm volatile("cp.async.wait_group %0;" :: "n"(N) : "memory");
}
__device__ __forceinline__ void ldsm4(uint32_t& r0, uint32_t& r1, uint32_t& r2, uint32_t& r3,
                                      uint32_t addr) {
    asm volatile("ldmatrix.sync.aligned.m8n8.x4.shared.b16 {%0,%1,%2,%3}, [%4];"
                 : "=r"(r0), "=r"(r1), "=r"(r2), "=r"(r3) : "r"(addr));
}
__device__ __forceinline__ void ldsm4t(uint32_t& r0, uint32_t& r1, uint32_t& r2, uint32_t& r3,
                                       uint32_t addr) {
    asm volatile("ldmatrix.sync.aligned.m8n8.x4.trans.shared.b16 {%0,%1,%2,%3}, [%4];"
                 : "=r"(r0), "=r"(r1), "=r"(r2), "=r"(r3) : "r"(addr));
}
__device__ __forceinline__ void mma_f16(float* d, const uint32_t* a, uint32_t b0, uint32_t b1)
{
    asm volatile(
        "mma.sync.aligned.m16n8k16.row.col.f32.f16.f16.f32 "
        "{%0,%1,%2,%3}, {%4,%5,%6,%7}, {%8,%9}, {%0,%1,%2,%3};"
        : "+f"(d[0]), "+f"(d[1]), "+f"(d[2]), "+f"(d[3])
        : "r"(a[0]), "r"(a[1]), "r"(a[2]), "r"(a[3]), "r"(b0), "r"(b1));
}

// ---------------------------------------------------------------------------
// fp16 mma GEMM: C[M,N](f32) = A[M,K](f16) * B[N,K](f16)^T, K contiguous.
// CTA 128x256, 8 warps (2x4), warp tile 64x64, K-tile 32 halves, 4-stage.
// Smem rows: 32 halves data, stride 40 halves (80 B, 16B-aligned, ldmatrix
// conflict-free: 8-row group hits 8 distinct bank-quads).
// ---------------------------------------------------------------------------
#define GTM 128
#define GTN 256
#define GTK 32
#define GSTR 80                            // bytes per smem row
#define A_T_B (GTM * GSTR)                 // 10240
#define B_T_B (GTN * GSTR)                 // 20480
#define STG_B (A_T_B + B_T_B)              // 30720
#define NSTG 4
#define GEMM_SMEM (NSTG * STG_B)           // 122880
#define KT (KDIM / GTK)                    // 64

__device__ __forceinline__ void gemm_load_stage(uint32_t sbase, int s, int kt,
                                                const __half* __restrict__ A,
                                                const __half* __restrict__ Bm,
                                                int m0, int n0, int tid)
{
    const uint32_t ab = sbase + s * STG_B;
    const uint32_t bb = ab + A_T_B;
    const int kk = kt * GTK;
#pragma unroll
    for (int i = 0; i < 2; i++) {            // A: 512 16B-chunks (128 rows x 4)
        int t = tid + i * 256;
        int r = t >> 2, c = t & 3;
        cp_async16(ab + r * GSTR + c * 16, A + (size_t)(m0 + r) * KDIM + kk + c * 8);
    }
#pragma unroll
    for (int i = 0; i < 4; i++) {            // B: 1024 chunks (256 rows x 4)
        int t = tid + i * 256;
        int r = t >> 2, c = t & 3;
        cp_async16(bb + r * GSTR + c * 16, Bm + (size_t)(n0 + r) * KDIM + kk + c * 8);
    }
}

__device__ __forceinline__ void gemm_body(const __half* __restrict__ A,
                                          const __half* __restrict__ Bm,
                                          float* __restrict__ C)
{
    extern __shared__ __align__(16) char smem[];
    const uint32_t sbase = smem_u32(smem);
    const int tid = threadIdx.x;
    const int wid = tid >> 5, lane = tid & 31;
    const int g = lane >> 2, q = lane & 3;
    const int m0 = blockIdx.y * GTM, n0 = blockIdx.x * GTN;
    const int wm = (wid >> 2) * 64, wn = (wid & 3) * 64;
    const int l15 = lane & 15, lhi = (lane >> 4) * 16;

    float acc[4][8][4];
#pragma unroll
    for (int mi = 0; mi < 4; mi++)
#pragma unroll
        for (int ni = 0; ni < 8; ni++)
#pragma unroll
            for (int j = 0; j < 4; j++) acc[mi][ni][j] = 0.0f;

#pragma unroll
    for (int s = 0; s < NSTG - 1; s++) {
        gemm_load_stage(sbase, s, s, A, Bm, m0, n0, tid);
        cp_commit();
    }

    for (int kt = 0; kt < KT; kt++) {
        if (kt + NSTG - 1 < KT)
            gemm_load_stage(sbase, (kt + NSTG - 1) & 3, kt + NSTG - 1, A, Bm, m0, n0, tid);
        cp_commit();
        cp_wait<NSTG - 1>();
        __syncthreads();

        const uint32_t ab = sbase + (kt & 3) * STG_B;
        const uint32_t bb = ab + A_T_B;
#pragma unroll
        for (int ks = 0; ks < 2; ks++) {
            uint32_t a[4][4];
#pragma unroll
            for (int mi = 0; mi < 4; mi++)
                ldsm4(a[mi][0], a[mi][1], a[mi][2], a[mi][3],
                      ab + (wm + mi * 16 + l15) * GSTR + ks * 32 + lhi);
#pragma unroll
            for (int nj = 0; nj < 4; nj++) {
                uint32_t b0, b1, b2, b3;
                ldsm4(b0, b1, b2, b3,
                      bb + (wn + nj * 16 + l15) * GSTR + ks * 32 + lhi);
                // frag(2nj) = (b0,b2); frag(2nj+1) = (b1,b3)
#pragma unroll
                for (int mi = 0; mi < 4; mi++) {
                    mma_f16(acc[mi][2 * nj],     a[mi], b0, b2);
                    mma_f16(acc[mi][2 * nj + 1], a[mi], b1, b3);
                }
            }
        }
        __syncthreads();
    }

#pragma unroll
    for (int mi = 0; mi < 4; mi++) {
        int row = m0 + wm + mi * 16 + g;
#pragma unroll
        for (int ni = 0; ni < 8; ni++) {
            int col = n0 + wn + ni * 8 + q * 2;
            *(float2*)(C + (size_t)row * NDIM + col) =
                make_float2(acc[mi][ni][0], acc[mi][ni][1]);
            *(float2*)(C + (size_t)(row + 8) * NDIM + col) =
                make_float2(acc[mi][ni][2], acc[mi][ni][3]);
        }
    }
}

__global__ void __launch_bounds__(256, 1) gemm_f16_kernel(
    const __half* __restrict__ A, const __half* __restrict__ Bm, float* __restrict__ C)
{
    gemm_body(A, Bm, C);
}

__global__ void __launch_bounds__(256, 1) qkv_f16_kernel(const __half* __restrict__ A)
{
    const __half* Bm;
    float* C;
    if (blockIdx.z == 0)      { Bm = g_wqh; C = g_Q; }
    else if (blockIdx.z == 1) { Bm = g_wkh; C = g_K; }
    else                      { Bm = g_wvh; C = g_V; }
    gemm_body(A, Bm, C);
}

// ---------------------------------------------------------------------------
// f32 -> f16 conversion
// ---------------------------------------------------------------------------
__global__ void cvt_h_kernel(const float* __restrict__ in, __half* __restrict__ out, int n4)
{
    int i = blockIdx.x * blockDim.x + threadIdx.x;
    if (i < n4) {
        float4 v = ((const float4*)in)[i];
        __half2 h0 = __floats2half2_rn(v.x, v.y);
        __half2 h1 = __floats2half2_rn(v.z, v.w);
        uint2 u;
        u.x = *(uint32_t*)&h0;
        u.y = *(uint32_t*)&h1;
        ((uint2*)out)[i] = u;
    }
}

// ---------------------------------------------------------------------------
// RoPE: reads fp32 g_Q/g_K, writes rotated half g_Qh/g_Kh.
// ---------------------------------------------------------------------------
__global__ void rope_kernel(const float* __restrict__ cosT, const float* __restrict__ sinT)
{
    int idx = blockIdx.x * blockDim.x + threadIdx.x;   // pair index
    int i = idx & 63;
    int rest = idx >> 6;
    int m = rest >> 4;
    int t = m & (SS - 1);
    float c = cosT[t * 64 + i];
    float s = sinT[t * 64 + i];
    size_t off = (size_t)idx * 2;
    float2 qv = *(const float2*)(g_Q + off);
    float2 kv = *(const float2*)(g_K + off);
    ((__half2*)g_Qh)[idx] = __floats2half2_rn(qv.x * c - qv.y * s, qv.x * s + qv.y * c);
    ((__half2*)g_Kh)[idx] = __floats2half2_rn(kv.x * c - kv.y * s, kv.x * s + kv.y * c);
}

// ---------------------------------------------------------------------------
// Flash attention, fp16 mma + ldmatrix, causal.
// CTA: 128 q-rows x (b,h). 8 warps x m16. FBK = 64.
// K/V smem rows: 128 halves data, stride 272 B (16B-aligned, conflict-free).
// P smem rows: 64 halves data, stride 144 B.
// ---------------------------------------------------------------------------
#define FBQ 128
#define FBK 64
#define FSCALE 0.08838834764831845f
#define KVSTR 272
#define KOFF0 0
#define VOFF0 17408
#define KOFF1 34816
#define VOFF1 52224
#define PSOFF 69632
#define PSTR 144
#define FLASH_SMEM (PSOFF + FBQ * PSTR)    // 88064 B

__device__ __forceinline__ void flash_load_kv(uint32_t sb, int buf, int k0,
                                              size_t brow, size_t head, int tid)
{
    const uint32_t kb = sb + (buf ? KOFF1 : KOFF0);
    const uint32_t vb = sb + (buf ? VOFF1 : VOFF0);
#pragma unroll
    for (int i = 0; i < 4; i++) {          // 64 rows x 16 chunks each for K and V
        int id = tid + i * 256;
        int r = id >> 4, c = id & 15;
        cp_async16(kb + r * KVSTR + c * 16, g_Kh + (brow + k0 + r) * (size_t)DD + head + c * 8);
        cp_async16(vb + r * KVSTR + c * 16, g_Vh + (brow + k0 + r) * (size_t)DD + head + c * 8);
    }
}

__global__ void __launch_bounds__(256, 1) flash_f16_kernel()
{
    extern __shared__ __align__(16) char smem[];
    const uint32_t sb = smem_u32(smem);
    const int tid = threadIdx.x;
    const int wid = tid >> 5, lane = tid & 31;
    const int g = lane >> 2, q = lane & 3;
    const int l15 = lane & 15, lhi = (lane >> 4) * 16;
    const int q0 = (gridDim.x - 1 - blockIdx.x) * FBQ;   // heavy CTAs first
    const int h = blockIdx.y, b = blockIdx.z;
    const size_t brow = (size_t)b * SS;
    const size_t head = (size_t)h * FHD;

    // --- Prologue: stage Q tile (128 rows x 256B, stride 272) at offset 0 ---
#pragma unroll
    for (int i = 0; i < 8; i++) {
        int id = tid + i * 256;
        int r = id >> 4, c = id & 15;
        cp_async16(sb + r * KVSTR + c * 16, g_Qh + (brow + q0 + r) * (size_t)DD + head + c * 8);
    }
    cp_commit(); cp_wait<0>(); __syncthreads();

    uint32_t qf[8][4];
#pragma unroll
    for (int ks = 0; ks < 8; ks++)
        ldsm4(qf[ks][0], qf[ks][1], qf[ks][2], qf[ks][3],
              sb + (wid * 16 + l15) * KVSTR + ks * 32 + lhi);
    __syncthreads();

    const int rl0 = wid * 16 + g, rl1 = rl0 + 8;
    const int rg0 = q0 + rl0, rg1 = rg0 + 8;

    float m0 = -1e30f, m1 = -1e30f, l0 = 0.0f, l1 = 0.0f;
    float o[16][4];
#pragma unroll
    for (int nf = 0; nf < 16; nf++)
#pragma unroll
        for (int j = 0; j < 4; j++) o[nf][j] = 0.0f;

    const int ktiles = q0 / FBK + 2;
    flash_load_kv(sb, 0, 0, brow, head, tid);
    cp_commit();

    for (int t = 0; t < ktiles; t++) {
        if (t + 1 < ktiles)
            flash_load_kv(sb, (t + 1) & 1, (t + 1) * FBK, brow, head, tid);
        cp_commit();
        cp_wait<1>();
        __syncthreads();

        const int k0 = t * FBK;
        const uint32_t kb = sb + ((t & 1) ? KOFF1 : KOFF0);
        const uint32_t vb = sb + ((t & 1) ? VOFF1 : VOFF0);

        // ---- S = Q K^T ----
        float s[8][4];
#pragma unroll
        for (int nf = 0; nf < 8; nf++)
#pragma unroll
            for (int j = 0; j < 4; j++) s[nf][j] = 0.0f;

#pragma unroll
        for (int ks = 0; ks < 8; ks++) {
#pragma unroll
            for (int nj = 0; nj < 4; nj++) {
                uint32_t b0, b1, b2, b3;
                ldsm4(b0, b1, b2, b3, kb + (nj * 16 + l15) * KVSTR + ks * 32 + lhi);
                mma_f16(s[2 * nj],     qf[ks], b0, b2);
                mma_f16(s[2 * nj + 1], qf[ks], b1, b3);
            }
        }

        // scale in fp32 (exact), then causal mask
#pragma unroll
        for (int nf = 0; nf < 8; nf++)
#pragma unroll
            for (int j = 0; j < 4; j++) s[nf][j] *= FSCALE;

        if (k0 + FBK - 1 > q0 + wid * 16) {
#pragma unroll
            for (int nf = 0; nf < 8; nf++) {
                int c0 = k0 + nf * 8 + 2 * q;
                if (c0 > rg0)     s[nf][0] = -1e30f;
                if (c0 + 1 > rg0) s[nf][1] = -1e30f;
                if (c0 > rg1)     s[nf][2] = -1e30f;
                if (c0 + 1 > rg1) s[nf][3] = -1e30f;
            }
        }

        // ---- online softmax (fp32) ----
        float mx0 = -1e30f, mx1 = -1e30f;
#pragma unroll
        for (int nf = 0; nf < 8; nf++) {
            mx0 = fmaxf(mx0, fmaxf(s[nf][0], s[nf][1]));
            mx1 = fmaxf(mx1, fmaxf(s[nf][2], s[nf][3]));
        }
        mx0 = fmaxf(mx0, __shfl_xor_sync(0xffffffffu, mx0, 1));
        mx0 = fmaxf(mx0, __shfl_xor_sync(0xffffffffu, mx0, 2));
        mx1 = fmaxf(mx1, __shfl_xor_sync(0xffffffffu, mx1, 1));
        mx1 = fmaxf(mx1, __shfl_xor_sync(0xffffffffu, mx1, 2));

        float mn0 = fmaxf(m0, mx0), mn1 = fmaxf(m1, mx1);
        float cr0 = __expf(m0 - mn0), cr1 = __expf(m1 - mn1);
        m0 = mn0; m1 = mn1;

        float rs0 = 0.0f, rs1 = 0.0f;
#pragma unroll
        for (int nf = 0; nf < 8; nf++) {
            s[nf][0] = __expf(s[nf][0] - mn0);
            s[nf][1] = __expf(s[nf][1] - mn0);
            s[nf][2] = __expf(s[nf][2] - mn1);
            s[nf][3] = __expf(s[nf][3] - mn1);
            rs0 += s[nf][0] + s[nf][1];
            rs1 += s[nf][2] + s[nf][3];
        }
        rs0 += __shfl_xor_sync(0xffffffffu, rs0, 1);
        rs0 += __shfl_xor_sync(0xffffffffu, rs0, 2);
        rs1 += __shfl_xor_sync(0xffffffffu, rs1, 1);
        rs1 += __shfl_xor_sync(0xffffffffu, rs1, 2);
        l0 = l0 * cr0 + rs0;
        l1 = l1 * cr1 + rs1;

#pragma unroll
        for (int nf = 0; nf < 16; nf++) {
            o[nf][0] *= cr0; o[nf][1] *= cr0;
            o[nf][2] *= cr1; o[nf][3] *= cr1;
        }

        // ---- write P (half), warp-private rows ----
#pragma unroll
        for (int nf = 0; nf < 8; nf++) {
            *(__half2*)(smem + PSOFF + rl0 * PSTR + (nf * 8 + 2 * q) * 2) =
                __floats2half2_rn(s[nf][0], s[nf][1]);
            *(__half2*)(smem + PSOFF + rl1 * PSTR + (nf * 8 + 2 * q) * 2) =
                __floats2half2_rn(s[nf][2], s[nf][3]);
        }
        __syncwarp();

        // ---- O += P V ----
#pragma unroll
        for (int ks2 = 0; ks2 < 4; ks2++) {
            uint32_t pa[4];
            ldsm4(pa[0], pa[1], pa[2], pa[3],
                  sb + PSOFF + (wid * 16 + l15) * PSTR + ks2 * 32 + lhi);
#pragma unroll
            for (int nj = 0; nj < 8; nj++) {
                uint32_t v0, v1, v2, v3;
                ldsm4t(v0, v1, v2, v3,
                       vb + (ks2 * 16 + l15) * KVSTR + nj * 32 + lhi);
                // trans mapping: frag(2nj) = (v0,v1); frag(2nj+1) = (v2,v3)
                mma_f16(o[2 * nj],     pa, v0, v1);
                mma_f16(o[2 * nj + 1], pa, v2, v3);
            }
        }
        __syncthreads();
    }

    // ---- normalize + store half ----
    float i0 = 1.0f / l0, i1 = 1.0f / l1;
#pragma unroll
    for (int nf = 0; nf < 16; nf++) {
        *(__half2*)(g_AOh + (brow + rg0) * (size_t)DD + head + nf * 8 + 2 * q) =
            __floats2half2_rn(o[nf][0] * i0, o[nf][1] * i0);
        *(__half2*)(g_AOh + (brow + rg1) * (size_t)DD + head + nf * 8 + 2 * q) =
            __floats2half2_rn(o[nf][2] * i1, o[nf][3] * i1);
    }
}

// ---------------------------------------------------------------------------
// Launch
// ---------------------------------------------------------------------------
extern "C" void kernel_launch(void* const* d_in, const int* in_sizes, int n_in,
                              void* d_out, int out_size)
{
    const float* x  = (const float*)d_in[0];
    const float* wq = (const float*)d_in[1];
    const float* wk = (const float*)d_in[2];
    const float* wv = (const float*)d_in[3];
    const float* wo = (const float*)d_in[4];
    const float* fc = (const float*)d_in[5];
    const float* fs = (const float*)d_in[6];
    float* out = (float*)d_out;

    void *p_xh, *p_wqh, *p_wkh, *p_wvh, *p_woh, *p_v, *p_vh, *p_aoh;
    cudaGetSymbolAddress(&p_xh,  g_xh);
    cudaGetSymbolAddress(&p_wqh, g_wqh);
    cudaGetSymbolAddress(&p_wkh, g_wkh);
    cudaGetSymbolAddress(&p_wvh, g_wvh);
    cudaGetSymbolAddress(&p_woh, g_woh);
    cudaGetSymbolAddress(&p_v,   g_V);
    cudaGetSymbolAddress(&p_vh,  g_Vh);
    cudaGetSymbolAddress(&p_aoh, g_AOh);

    cudaFuncSetAttribute(gemm_f16_kernel,
                         cudaFuncAttributeMaxDynamicSharedMemorySize, GEMM_SMEM);
    cudaFuncSetAttribute(qkv_f16_kernel,
                         cudaFuncAttributeMaxDynamicSharedMemorySize, GEMM_SMEM);
    cudaFuncSetAttribute(flash_f16_kernel,
                         cudaFuncAttributeMaxDynamicSharedMemorySize, FLASH_SMEM);

    // 0) f32 -> f16 operand copies
    cvt_h_kernel<<<(MDIM * KDIM / 4 + 255) / 256, 256>>>(x,  (__half*)p_xh,  MDIM * KDIM / 4);
    cvt_h_kernel<<<(NDIM * KDIM / 4 + 255) / 256, 256>>>(wq, (__half*)p_wqh, NDIM * KDIM / 4);
    cvt_h_kernel<<<(NDIM * KDIM / 4 + 255) / 256, 256>>>(wk, (__half*)p_wkh, NDIM * KDIM / 4);
    cvt_h_kernel<<<(NDIM * KDIM / 4 + 255) / 256, 256>>>(wv, (__half*)p_wvh, NDIM * KDIM / 4);
    cvt_h_kernel<<<(NDIM * KDIM / 4 + 255) / 256, 256>>>(wo, (__half*)p_woh, NDIM * KDIM / 4);

    // 1) QKV projections (fp16 tensor path, fp32 outputs)
    dim3 gq(NDIM / GTN, MDIM / GTM, 3);
    qkv_f16_kernel<<<gq, 256, GEMM_SMEM>>>((const __half*)p_xh);

    // 2) V -> half (single rounding)
    cvt_h_kernel<<<(MDIM * DD / 4 + 255) / 256, 256>>>((const float*)p_v,
                                                       (__half*)p_vh, MDIM * DD / 4);

    // 3) RoPE: fp32 rotate, single rounding to half
    rope_kernel<<<(MDIM * DD / 2) / 256, 256>>>(fc, fs);

    // 4) Causal flash attention (fp16 tensor path) -> g_AOh
    flash_f16_kernel<<<dim3(SS / FBQ, NH, BB), 256, FLASH_SMEM>>>();

    // 5) Output projection
    gemm_f16_kernel<<<dim3(NDIM / GTN, MDIM / GTM), 256, GEMM_SMEM>>>(
        (const __half*)p_aoh, (const __half*)p_woh, out);
}

// round 7
// speedup vs baseline: 6.3162x; 1.0328x over previous
#include <cuda_runtime.h>
#include <cuda_fp16.h>
#include <cstddef>
#include <cstdint>

// Problem constants
#define BB 2
#define SS 2048
#define DD 2048
#define NH 16
#define FHD 128
#define KDIM 2048
#define NDIM 2048
#define MDIM (BB * SS)   // 4096

// ---------------------------------------------------------------------------
// Scratch (device globals — no allocation allowed)
// ---------------------------------------------------------------------------
__device__ __half g_Qh[(size_t)MDIM * DD];    // post-rope half Q/K; half V
__device__ __half g_Kh[(size_t)MDIM * DD];
__device__ __half g_Vh[(size_t)MDIM * DD];
__device__ __half g_AOh[(size_t)MDIM * DD];   // flash output (half)
__device__ __half g_xh[(size_t)MDIM * KDIM];  // half operand copies
__device__ __half g_wqh[(size_t)NDIM * KDIM];
__device__ __half g_wkh[(size_t)NDIM * KDIM];
__device__ __half g_wvh[(size_t)NDIM * KDIM];
__device__ __half g_woh[(size_t)NDIM * KDIM];

// ---------------------------------------------------------------------------
// Helpers
// ---------------------------------------------------------------------------
__device__ __forceinline__ uint32_t smem_u32(const void* p) {
    uint32_t a;
    asm("{ .reg .u64 t; cvta.to.shared.u64 t, %1; cvt.u32.u64 %0, t; }" : "=r"(a) : "l"(p));
    return a;
}
__device__ __forceinline__ void cp_async16(uint32_t dst, const void* src) {
    asm volatile("cp.async.cg.shared.global [%0], [%1], 16;" :: "r"(dst), "l"(src) : "memory");
}
__device__ __forceinline__ void cp_commit() {
    asm volatile("cp.async.commit_group;" ::: "memory");
}
template <int N>
__device__ __forceinline__ void cp_wait() {
    asm volatile("cp.async.wait_group %0;" :: "n"(N) : "memory");
}
__device__ __forceinline__ void ldsm4(uint32_t& r0, uint32_t& r1, uint32_t& r2, uint32_t& r3,
                                      uint32_t addr) {
    asm volatile("ldmatrix.sync.aligned.m8n8.x4.shared.b16 {%0,%1,%2,%3}, [%4];"
                 : "=r"(r0), "=r"(r1), "=r"(r2), "=r"(r3) : "r"(addr));
}
__device__ __forceinline__ void ldsm4t(uint32_t& r0, uint32_t& r1, uint32_t& r2, uint32_t& r3,
                                       uint32_t addr) {
    asm volatile("ldmatrix.sync.aligned.m8n8.x4.trans.shared.b16 {%0,%1,%2,%3}, [%4];"
                 : "=r"(r0), "=r"(r1), "=r"(r2), "=r"(r3) : "r"(addr));
}
__device__ __forceinline__ void mma_f16(float* d, const uint32_t* a, uint32_t b0, uint32_t b1)
{
    asm volatile(
        "mma.sync.aligned.m16n8k16.row.col.f32.f16.f16.f32 "
        "{%0,%1,%2,%3}, {%4,%5,%6,%7}, {%8,%9}, {%0,%1,%2,%3};"
        : "+f"(d[0]), "+f"(d[1]), "+f"(d[2]), "+f"(d[3])
        : "r"(a[0]), "r"(a[1]), "r"(a[2]), "r"(a[3]), "r"(b0), "r"(b1));
}

// ---------------------------------------------------------------------------
// fp16 mma GEMM mainloop: acc = A[M,K](f16) * B[N,K](f16)^T for one CTA tile.
// CTA 128x256, 8 warps (2x4), warp tile 64x64, K-tile 32 halves, 4-stage.
// Smem rows: 32 halves data, stride 80 B (16B-aligned, ldmatrix conflict-free).
// ---------------------------------------------------------------------------
#define GTM 128
#define GTN 256
#define GTK 32
#define GSTR 80
#define A_T_B (GTM * GSTR)                 // 10240
#define B_T_B (GTN * GSTR)                 // 20480
#define STG_B (A_T_B + B_T_B)              // 30720
#define NSTG 4
#define GEMM_SMEM (NSTG * STG_B)           // 122880
#define KT (KDIM / GTK)                    // 64

__device__ __forceinline__ void gemm_load_stage(uint32_t sbase, int s, int kt,
                                                const __half* __restrict__ A,
                                                const __half* __restrict__ Bm,
                                                int m0, int n0, int tid)
{
    const uint32_t ab = sbase + s * STG_B;
    const uint32_t bb = ab + A_T_B;
    const int kk = kt * GTK;
#pragma unroll
    for (int i = 0; i < 2; i++) {
        int t = tid + i * 256;
        int r = t >> 2, c = t & 3;
        cp_async16(ab + r * GSTR + c * 16, A + (size_t)(m0 + r) * KDIM + kk + c * 8);
    }
#pragma unroll
    for (int i = 0; i < 4; i++) {
        int t = tid + i * 256;
        int r = t >> 2, c = t & 3;
        cp_async16(bb + r * GSTR + c * 16, Bm + (size_t)(n0 + r) * KDIM + kk + c * 8);
    }
}

__device__ __forceinline__ void gemm_mainloop(const __half* __restrict__ A,
                                              const __half* __restrict__ Bm,
                                              int m0, int n0,
                                              float acc[4][8][4])
{
    extern __shared__ __align__(16) char smem[];
    const uint32_t sbase = smem_u32(smem);
    const int tid = threadIdx.x;
    const int wid = tid >> 5, lane = tid & 31;
    const int wm = (wid >> 2) * 64, wn = (wid & 3) * 64;
    const int l15 = lane & 15, lhi = (lane >> 4) * 16;

#pragma unroll
    for (int mi = 0; mi < 4; mi++)
#pragma unroll
        for (int ni = 0; ni < 8; ni++)
#pragma unroll
            for (int j = 0; j < 4; j++) acc[mi][ni][j] = 0.0f;

#pragma unroll
    for (int s = 0; s < NSTG - 1; s++) {
        gemm_load_stage(sbase, s, s, A, Bm, m0, n0, tid);
        cp_commit();
    }

    for (int kt = 0; kt < KT; kt++) {
        if (kt + NSTG - 1 < KT)
            gemm_load_stage(sbase, (kt + NSTG - 1) & 3, kt + NSTG - 1, A, Bm, m0, n0, tid);
        cp_commit();
        cp_wait<NSTG - 1>();
        __syncthreads();

        const uint32_t ab = sbase + (kt & 3) * STG_B;
        const uint32_t bb = ab + A_T_B;
#pragma unroll
        for (int ks = 0; ks < 2; ks++) {
            uint32_t a[4][4];
#pragma unroll
            for (int mi = 0; mi < 4; mi++)
                ldsm4(a[mi][0], a[mi][1], a[mi][2], a[mi][3],
                      ab + (wm + mi * 16 + l15) * GSTR + ks * 32 + lhi);
#pragma unroll
            for (int nj = 0; nj < 4; nj++) {
                uint32_t b0, b1, b2, b3;
                ldsm4(b0, b1, b2, b3,
                      bb + (wn + nj * 16 + l15) * GSTR + ks * 32 + lhi);
#pragma unroll
                for (int mi = 0; mi < 4; mi++) {
                    mma_f16(acc[mi][2 * nj],     a[mi], b0, b2);
                    mma_f16(acc[mi][2 * nj + 1], a[mi], b1, b3);
                }
            }
        }
        __syncthreads();
    }
}

// ---------------------------------------------------------------------------
// Out projection: fp32 epilogue to d_out
// ---------------------------------------------------------------------------
__global__ void __launch_bounds__(256, 1) gemm_f16_kernel(
    const __half* __restrict__ A, const __half* __restrict__ Bm, float* __restrict__ C)
{
    const int tid = threadIdx.x;
    const int wid = tid >> 5, lane = tid & 31;
    const int g = lane >> 2, q = lane & 3;
    const int m0 = blockIdx.y * GTM, n0 = blockIdx.x * GTN;
    const int wm = (wid >> 2) * 64, wn = (wid & 3) * 64;

    float acc[4][8][4];
    gemm_mainloop(A, Bm, m0, n0, acc);

#pragma unroll
    for (int mi = 0; mi < 4; mi++) {
        int row = m0 + wm + mi * 16 + g;
#pragma unroll
        for (int ni = 0; ni < 8; ni++) {
            int col = n0 + wn + ni * 8 + q * 2;
            *(float2*)(C + (size_t)row * NDIM + col) =
                make_float2(acc[mi][ni][0], acc[mi][ni][1]);
            *(float2*)(C + (size_t)(row + 8) * NDIM + col) =
                make_float2(acc[mi][ni][2], acc[mi][ni][3]);
        }
    }
}

// ---------------------------------------------------------------------------
// QKV projection with fused RoPE epilogue, half output.
// z=0: Q (rope), z=1: K (rope), z=2: V (plain).
// Fragment pair (acc[0],acc[1]) = cols (2i, 2i+1) = one rope pair.
// ---------------------------------------------------------------------------
__global__ void __launch_bounds__(256, 1) qkv_f16_kernel(
    const __half* __restrict__ A,
    const float* __restrict__ fc, const float* __restrict__ fs)
{
    const __half* Bm;
    __half* C;
    const int z = blockIdx.z;
    if (z == 0)      { Bm = g_wqh; C = g_Qh; }
    else if (z == 1) { Bm = g_wkh; C = g_Kh; }
    else             { Bm = g_wvh; C = g_Vh; }

    const int tid = threadIdx.x;
    const int wid = tid >> 5, lane = tid & 31;
    const int g = lane >> 2, q = lane & 3;
    const int m0 = blockIdx.y * GTM, n0 = blockIdx.x * GTN;
    const int wm = (wid >> 2) * 64, wn = (wid & 3) * 64;

    float acc[4][8][4];
    gemm_mainloop(A, Bm, m0, n0, acc);

#pragma unroll
    for (int mi = 0; mi < 4; mi++) {
        int row = m0 + wm + mi * 16 + g;
        int t0 = row & (SS - 1);
        int t1 = (row + 8) & (SS - 1);
#pragma unroll
        for (int ni = 0; ni < 8; ni++) {
            int col = n0 + wn + ni * 8 + q * 2;
            float e0 = acc[mi][ni][0], o0 = acc[mi][ni][1];
            float e1 = acc[mi][ni][2], o1 = acc[mi][ni][3];
            if (z < 2) {
                int i = (col & 127) >> 1;
                float c0 = fc[t0 * 64 + i], s0 = fs[t0 * 64 + i];
                float c1 = fc[t1 * 64 + i], s1 = fs[t1 * 64 + i];
                float re0 = e0 * c0 - o0 * s0, ro0 = e0 * s0 + o0 * c0;
                float re1 = e1 * c1 - o1 * s1, ro1 = e1 * s1 + o1 * c1;
                e0 = re0; o0 = ro0; e1 = re1; o1 = ro1;
            }
            *(__half2*)(C + (size_t)row * DD + col) = __floats2half2_rn(e0, o0);
            *(__half2*)(C + (size_t)(row + 8) * DD + col) = __floats2half2_rn(e1, o1);
        }
    }
}

// ---------------------------------------------------------------------------
// Single conversion pass: x + 4 weights -> half
// ---------------------------------------------------------------------------
#define N4X (MDIM * KDIM / 4)      // 2097152
#define N4W (NDIM * KDIM / 4)      // 1048576
__global__ void cvt_all_kernel(const float* __restrict__ x,
                               const float* __restrict__ wq,
                               const float* __restrict__ wk,
                               const float* __restrict__ wv,
                               const float* __restrict__ wo)
{
    int idx = blockIdx.x * blockDim.x + threadIdx.x;
    const float* src;
    __half* dst;
    int off;
    if (idx < N4X) { src = x; dst = g_xh; off = idx; }
    else {
        int j = idx - N4X;
        int w = j >> 20;            // N4W = 2^20
        off = j & (N4W - 1);
        if (w == 0)      { src = wq; dst = g_wqh; }
        else if (w == 1) { src = wk; dst = g_wkh; }
        else if (w == 2) { src = wv; dst = g_wvh; }
        else             { src = wo; dst = g_woh; }
    }
    float4 v = ((const float4*)src)[off];
    __half2 h0 = __floats2half2_rn(v.x, v.y);
    __half2 h1 = __floats2half2_rn(v.z, v.w);
    uint2 u;
    u.x = *(uint32_t*)&h0;
    u.y = *(uint32_t*)&h1;
    ((uint2*)dst)[off] = u;
}

// ---------------------------------------------------------------------------
// Flash attention, fp16 mma + ldmatrix, causal (unchanged from R6).
// ---------------------------------------------------------------------------
#define FBQ 128
#define FBK 64
#define FSCALE 0.08838834764831845f
#define KVSTR 272
#define KOFF0 0
#define VOFF0 17408
#define KOFF1 34816
#define VOFF1 52224
#define PSOFF 69632
#define PSTR 144
#define FLASH_SMEM (PSOFF + FBQ * PSTR)    // 88064 B

__device__ __forceinline__ void flash_load_kv(uint32_t sb, int buf, int k0,
                                              size_t brow, size_t head, int tid)
{
    const uint32_t kb = sb + (buf ? KOFF1 : KOFF0);
    const uint32_t vb = sb + (buf ? VOFF1 : VOFF0);
#pragma unroll
    for (int i = 0; i < 4; i++) {
        int id = tid + i * 256;
        int r = id >> 4, c = id & 15;
        cp_async16(kb + r * KVSTR + c * 16, g_Kh + (brow + k0 + r) * (size_t)DD + head + c * 8);
        cp_async16(vb + r * KVSTR + c * 16, g_Vh + (brow + k0 + r) * (size_t)DD + head + c * 8);
    }
}

__global__ void __launch_bounds__(256, 1) flash_f16_kernel()
{
    extern __shared__ __align__(16) char smem[];
    const uint32_t sb = smem_u32(smem);
    const int tid = threadIdx.x;
    const int wid = tid >> 5, lane = tid & 31;
    const int g = lane >> 2, q = lane & 3;
    const int l15 = lane & 15, lhi = (lane >> 4) * 16;
    const int q0 = (gridDim.x - 1 - blockIdx.x) * FBQ;   // heavy CTAs first
    const int h = blockIdx.y, b = blockIdx.z;
    const size_t brow = (size_t)b * SS;
    const size_t head = (size_t)h * FHD;

#pragma unroll
    for (int i = 0; i < 8; i++) {
        int id = tid + i * 256;
        int r = id >> 4, c = id & 15;
        cp_async16(sb + r * KVSTR + c * 16, g_Qh + (brow + q0 + r) * (size_t)DD + head + c * 8);
    }
    cp_commit(); cp_wait<0>(); __syncthreads();

    uint32_t qf[8][4];
#pragma unroll
    for (int ks = 0; ks < 8; ks++)
        ldsm4(qf[ks][0], qf[ks][1], qf[ks][2], qf[ks][3],
              sb + (wid * 16 + l15) * KVSTR + ks * 32 + lhi);
    __syncthreads();

    const int rl0 = wid * 16 + g, rl1 = rl0 + 8;
    const int rg0 = q0 + rl0, rg1 = rg0 + 8;

    float m0 = -1e30f, m1 = -1e30f, l0 = 0.0f, l1 = 0.0f;
    float o[16][4];
#pragma unroll
    for (int nf = 0; nf < 16; nf++)
#pragma unroll
        for (int j = 0; j < 4; j++) o[nf][j] = 0.0f;

    const int ktiles = q0 / FBK + 2;
    flash_load_kv(sb, 0, 0, brow, head, tid);
    cp_commit();

    for (int t = 0; t < ktiles; t++) {
        if (t + 1 < ktiles)
            flash_load_kv(sb, (t + 1) & 1, (t + 1) * FBK, brow, head, tid);
        cp_commit();
        cp_wait<1>();
        __syncthreads();

        const int k0 = t * FBK;
        const uint32_t kb = sb + ((t & 1) ? KOFF1 : KOFF0);
        const uint32_t vb = sb + ((t & 1) ? VOFF1 : VOFF0);

        float s[8][4];
#pragma unroll
        for (int nf = 0; nf < 8; nf++)
#pragma unroll
            for (int j = 0; j < 4; j++) s[nf][j] = 0.0f;

#pragma unroll
        for (int ks = 0; ks < 8; ks++) {
#pragma unroll
            for (int nj = 0; nj < 4; nj++) {
                uint32_t b0, b1, b2, b3;
                ldsm4(b0, b1, b2, b3, kb + (nj * 16 + l15) * KVSTR + ks * 32 + lhi);
                mma_f16(s[2 * nj],     qf[ks], b0, b2);
                mma_f16(s[2 * nj + 1], qf[ks], b1, b3);
            }
        }

#pragma unroll
        for (int nf = 0; nf < 8; nf++)
#pragma unroll
            for (int j = 0; j < 4; j++) s[nf][j] *= FSCALE;

        if (k0 + FBK - 1 > q0 + wid * 16) {
#pragma unroll
            for (int nf = 0; nf < 8; nf++) {
                int c0 = k0 + nf * 8 + 2 * q;
                if (c0 > rg0)     s[nf][0] = -1e30f;
                if (c0 + 1 > rg0) s[nf][1] = -1e30f;
                if (c0 > rg1)     s[nf][2] = -1e30f;
                if (c0 + 1 > rg1) s[nf][3] = -1e30f;
            }
        }

        float mx0 = -1e30f, mx1 = -1e30f;
#pragma unroll
        for (int nf = 0; nf < 8; nf++) {
            mx0 = fmaxf(mx0, fmaxf(s[nf][0], s[nf][1]));
            mx1 = fmaxf(mx1, fmaxf(s[nf][2], s[nf][3]));
        }
        mx0 = fmaxf(mx0, __shfl_xor_sync(0xffffffffu, mx0, 1));
        mx0 = fmaxf(mx0, __shfl_xor_sync(0xffffffffu, mx0, 2));
        mx1 = fmaxf(mx1, __shfl_xor_sync(0xffffffffu, mx1, 1));
        mx1 = fmaxf(mx1, __shfl_xor_sync(0xffffffffu, mx1, 2));

        float mn0 = fmaxf(m0, mx0), mn1 = fmaxf(m1, mx1);
        float cr0 = __expf(m0 - mn0), cr1 = __expf(m1 - mn1);
        m0 = mn0; m1 = mn1;

        float rs0 = 0.0f, rs1 = 0.0f;
#pragma unroll
        for (int nf = 0; nf < 8; nf++) {
            s[nf][0] = __expf(s[nf][0] - mn0);
            s[nf][1] = __expf(s[nf][1] - mn0);
            s[nf][2] = __expf(s[nf][2] - mn1);
            s[nf][3] = __expf(s[nf][3] - mn1);
            rs0 += s[nf][0] + s[nf][1];
            rs1 += s[nf][2] + s[nf][3];
        }
        rs0 += __shfl_xor_sync(0xffffffffu, rs0, 1);
        rs0 += __shfl_xor_sync(0xffffffffu, rs0, 2);
        rs1 += __shfl_xor_sync(0xffffffffu, rs1, 1);
        rs1 += __shfl_xor_sync(0xffffffffu, rs1, 2);
        l0 = l0 * cr0 + rs0;
        l1 = l1 * cr1 + rs1;

#pragma unroll
        for (int nf = 0; nf < 16; nf++) {
            o[nf][0] *= cr0; o[nf][1] *= cr0;
            o[nf][2] *= cr1; o[nf][3] *= cr1;
        }

#pragma unroll
        for (int nf = 0; nf < 8; nf++) {
            *(__half2*)(smem + PSOFF + rl0 * PSTR + (nf * 8 + 2 * q) * 2) =
                __floats2half2_rn(s[nf][0], s[nf][1]);
            *(__half2*)(smem + PSOFF + rl1 * PSTR + (nf * 8 + 2 * q) * 2) =
                __floats2half2_rn(s[nf][2], s[nf][3]);
        }
        __syncwarp();

#pragma unroll
        for (int ks2 = 0; ks2 < 4; ks2++) {
            uint32_t pa[4];
            ldsm4(pa[0], pa[1], pa[2], pa[3],
                  sb + PSOFF + (wid * 16 + l15) * PSTR + ks2 * 32 + lhi);
#pragma unroll
            for (int nj = 0; nj < 8; nj++) {
                uint32_t v0, v1, v2, v3;
                ldsm4t(v0, v1, v2, v3,
                       vb + (ks2 * 16 + l15) * KVSTR + nj * 32 + lhi);
                mma_f16(o[2 * nj],     pa, v0, v1);
                mma_f16(o[2 * nj + 1], pa, v2, v3);
            }
        }
        __syncthreads();
    }

    float i0 = 1.0f / l0, i1 = 1.0f / l1;
#pragma unroll
    for (int nf = 0; nf < 16; nf++) {
        *(__half2*)(g_AOh + (brow + rg0) * (size_t)DD + head + nf * 8 + 2 * q) =
            __floats2half2_rn(o[nf][0] * i0, o[nf][1] * i0);
        *(__half2*)(g_AOh + (brow + rg1) * (size_t)DD + head + nf * 8 + 2 * q) =
            __floats2half2_rn(o[nf][2] * i1, o[nf][3] * i1);
    }
}

// ---------------------------------------------------------------------------
// Launch
// ---------------------------------------------------------------------------
extern "C" void kernel_launch(void* const* d_in, const int* in_sizes, int n_in,
                              void* d_out, int out_size)
{
    const float* x  = (const float*)d_in[0];
    const float* wq = (const float*)d_in[1];
    const float* wk = (const float*)d_in[2];
    const float* wv = (const float*)d_in[3];
    const float* wo = (const float*)d_in[4];
    const float* fc = (const float*)d_in[5];
    const float* fs = (const float*)d_in[6];
    float* out = (float*)d_out;

    void *p_xh, *p_woh, *p_aoh;
    cudaGetSymbolAddress(&p_xh,  g_xh);
    cudaGetSymbolAddress(&p_woh, g_woh);
    cudaGetSymbolAddress(&p_aoh, g_AOh);

    cudaFuncSetAttribute(gemm_f16_kernel,
                         cudaFuncAttributeMaxDynamicSharedMemorySize, GEMM_SMEM);
    cudaFuncSetAttribute(qkv_f16_kernel,
                         cudaFuncAttributeMaxDynamicSharedMemorySize, GEMM_SMEM);
    cudaFuncSetAttribute(flash_f16_kernel,
                         cudaFuncAttributeMaxDynamicSharedMemorySize, FLASH_SMEM);

    // 0) one conversion pass: x + 4 weights -> half
    cvt_all_kernel<<<(N4X + 4 * N4W) / 256, 256>>>(x, wq, wk, wv, wo);

    // 1) QKV projections with fused RoPE epilogue -> g_Qh/g_Kh/g_Vh (half)
    dim3 gq(NDIM / GTN, MDIM / GTM, 3);
    qkv_f16_kernel<<<gq, 256, GEMM_SMEM>>>((const __half*)p_xh, fc, fs);

    // 2) Causal flash attention -> g_AOh
    flash_f16_kernel<<<dim3(SS / FBQ, NH, BB), 256, FLASH_SMEM>>>();

    // 3) Output projection -> fp32 out
    gemm_f16_kernel<<<dim3(NDIM / GTN, MDIM / GTM), 256, GEMM_SMEM>>>(
        (const __half*)p_aoh, (const __half*)p_woh, out);
}

// round 8
// speedup vs baseline: 7.1622x; 1.1339x over previous
#include <cuda_runtime.h>
#include <cuda_fp16.h>
#include <cstddef>
#include <cstdint>

// Problem constants
#define BB 2
#define SS 2048
#define DD 2048
#define NH 16
#define FHD 128
#define KDIM 2048
#define NDIM 2048
#define MDIM (BB * SS)   // 4096

// ---------------------------------------------------------------------------
// Scratch (device globals — no allocation allowed)
// ---------------------------------------------------------------------------
__device__ __half g_Qh[(size_t)MDIM * DD];
__device__ __half g_Kh[(size_t)MDIM * DD];
__device__ __half g_Vh[(size_t)MDIM * DD];
__device__ __half g_AOh[(size_t)MDIM * DD];
__device__ __half g_xh[(size_t)MDIM * KDIM];
__device__ __half g_wqh[(size_t)NDIM * KDIM];
__device__ __half g_wkh[(size_t)NDIM * KDIM];
__device__ __half g_wvh[(size_t)NDIM * KDIM];
__device__ __half g_woh[(size_t)NDIM * KDIM];

// ---------------------------------------------------------------------------
// Helpers
// ---------------------------------------------------------------------------
__device__ __forceinline__ uint32_t smem_u32(const void* p) {
    uint32_t a;
    asm("{ .reg .u64 t; cvta.to.shared.u64 t, %1; cvt.u32.u64 %0, t; }" : "=r"(a) : "l"(p));
    return a;
}
__device__ __forceinline__ void cp_async16(uint32_t dst, const void* src) {
    asm volatile("cp.async.cg.shared.global [%0], [%1], 16;" :: "r"(dst), "l"(src) : "memory");
}
__device__ __forceinline__ void cp_commit() {
    asm volatile("cp.async.commit_group;" ::: "memory");
}
template <int N>
__device__ __forceinline__ void cp_wait() {
    asm volatile("cp.async.wait_group %0;" :: "n"(N) : "memory");
}
__device__ __forceinline__ void ldsm4(uint32_t& r0, uint32_t& r1, uint32_t& r2, uint32_t& r3,
                                      uint32_t addr) {
    asm volatile("ldmatrix.sync.aligned.m8n8.x4.shared.b16 {%0,%1,%2,%3}, [%4];"
                 : "=r"(r0), "=r"(r1), "=r"(r2), "=r"(r3) : "r"(addr));
}
__device__ __forceinline__ void ldsm4t(uint32_t& r0, uint32_t& r1, uint32_t& r2, uint32_t& r3,
                                       uint32_t addr) {
    asm volatile("ldmatrix.sync.aligned.m8n8.x4.trans.shared.b16 {%0,%1,%2,%3}, [%4];"
                 : "=r"(r0), "=r"(r1), "=r"(r2), "=r"(r3) : "r"(addr));
}
__device__ __forceinline__ void mma_f16(float* d, const uint32_t* a, uint32_t b0, uint32_t b1)
{
    asm volatile(
        "mma.sync.aligned.m16n8k16.row.col.f32.f16.f16.f32 "
        "{%0,%1,%2,%3}, {%4,%5,%6,%7}, {%8,%9}, {%0,%1,%2,%3};"
        : "+f"(d[0]), "+f"(d[1]), "+f"(d[2]), "+f"(d[3])
        : "r"(a[0]), "r"(a[1]), "r"(a[2]), "r"(a[3]), "r"(b0), "r"(b1));
}

// ---------------------------------------------------------------------------
// fp16 mma GEMM mainloop, 2-CTA/SM shape.
// CTA 128x128, 8 warps (2x4), warp tile 64x32, K-tile 32, 4-stage ring,
// ONE __syncthreads per k-tile. Smem row stride 80 B (ldmatrix conflict-free).
// ---------------------------------------------------------------------------
#define GTM 128
#define GTN 128
#define GTK 32
#define GSTR 80
#define A_T_B (GTM * GSTR)                 // 10240
#define B_T_B (GTN * GSTR)                 // 10240
#define STG_B (A_T_B + B_T_B)              // 20480
#define NSTG 4
#define GEMM_SMEM (NSTG * STG_B)           // 81920  (x2 CTAs = 160 KB/SM)
#define KT (KDIM / GTK)                    // 64

__device__ __forceinline__ void gemm_load_stage(uint32_t sbase, int s, int kt,
                                                const __half* __restrict__ A,
                                                const __half* __restrict__ Bm,
                                                int m0, int n0, int tid)
{
    const uint32_t ab = sbase + s * STG_B;
    const uint32_t bb = ab + A_T_B;
    const int kk = kt * GTK;
#pragma unroll
    for (int i = 0; i < 2; i++) {            // A: 512 chunks
        int t = tid + i * 256;
        int r = t >> 2, c = t & 3;
        cp_async16(ab + r * GSTR + c * 16, A + (size_t)(m0 + r) * KDIM + kk + c * 8);
    }
#pragma unroll
    for (int i = 0; i < 2; i++) {            // B: 512 chunks
        int t = tid + i * 256;
        int r = t >> 2, c = t & 3;
        cp_async16(bb + r * GSTR + c * 16, Bm + (size_t)(n0 + r) * KDIM + kk + c * 8);
    }
}

__device__ __forceinline__ void gemm_mainloop(const __half* __restrict__ A,
                                              const __half* __restrict__ Bm,
                                              int m0, int n0,
                                              float acc[4][4][4])
{
    extern __shared__ __align__(16) char smem[];
    const uint32_t sbase = smem_u32(smem);
    const int tid = threadIdx.x;
    const int wid = tid >> 5, lane = tid & 31;
    const int wm = (wid >> 2) * 64, wn = (wid & 3) * 32;
    const int l15 = lane & 15, lhi = (lane >> 4) * 16;

#pragma unroll
    for (int mi = 0; mi < 4; mi++)
#pragma unroll
        for (int ni = 0; ni < 4; ni++)
#pragma unroll
            for (int j = 0; j < 4; j++) acc[mi][ni][j] = 0.0f;

#pragma unroll
    for (int s = 0; s < NSTG - 1; s++) {
        gemm_load_stage(sbase, s, s, A, Bm, m0, n0, tid);
        cp_commit();
    }

    for (int kt = 0; kt < KT; kt++) {
        cp_wait<NSTG - 2>();
        __syncthreads();
        // prefetch AFTER the barrier: all warps have finished reading the
        // buffer (kt+NSTG-1)&3 at iteration kt-1, so overwrite is safe.
        if (kt + NSTG - 1 < KT)
            gemm_load_stage(sbase, (kt + NSTG - 1) & 3, kt + NSTG - 1, A, Bm, m0, n0, tid);
        cp_commit();   // unconditional: keeps group-count alignment in tail

        const uint32_t ab = sbase + (kt & 3) * STG_B;
        const uint32_t bb = ab + A_T_B;
#pragma unroll
        for (int ks = 0; ks < 2; ks++) {
            uint32_t a[4][4];
#pragma unroll
            for (int mi = 0; mi < 4; mi++)
                ldsm4(a[mi][0], a[mi][1], a[mi][2], a[mi][3],
                      ab + (wm + mi * 16 + l15) * GSTR + ks * 32 + lhi);
#pragma unroll
            for (int nj = 0; nj < 2; nj++) {
                uint32_t b0, b1, b2, b3;
                ldsm4(b0, b1, b2, b3,
                      bb + (wn + nj * 16 + l15) * GSTR + ks * 32 + lhi);
#pragma unroll
                for (int mi = 0; mi < 4; mi++) {
                    mma_f16(acc[mi][2 * nj],     a[mi], b0, b2);
                    mma_f16(acc[mi][2 * nj + 1], a[mi], b1, b3);
                }
            }
        }
    }
}

// ---------------------------------------------------------------------------
// Out projection: fp32 epilogue to d_out
// ---------------------------------------------------------------------------
__global__ void __launch_bounds__(256, 2) gemm_f16_kernel(
    const __half* __restrict__ A, const __half* __restrict__ Bm, float* __restrict__ C)
{
    const int tid = threadIdx.x;
    const int wid = tid >> 5, lane = tid & 31;
    const int g = lane >> 2, q = lane & 3;
    const int m0 = blockIdx.y * GTM, n0 = blockIdx.x * GTN;
    const int wm = (wid >> 2) * 64, wn = (wid & 3) * 32;

    float acc[4][4][4];
    gemm_mainloop(A, Bm, m0, n0, acc);

#pragma unroll
    for (int mi = 0; mi < 4; mi++) {
        int row = m0 + wm + mi * 16 + g;
#pragma unroll
        for (int ni = 0; ni < 4; ni++) {
            int col = n0 + wn + ni * 8 + q * 2;
            *(float2*)(C + (size_t)row * NDIM + col) =
                make_float2(acc[mi][ni][0], acc[mi][ni][1]);
            *(float2*)(C + (size_t)(row + 8) * NDIM + col) =
                make_float2(acc[mi][ni][2], acc[mi][ni][3]);
        }
    }
}

// ---------------------------------------------------------------------------
// QKV projection with fused RoPE epilogue, half output.
// z=0: Q (rope), z=1: K (rope), z=2: V (plain).
// ---------------------------------------------------------------------------
__global__ void __launch_bounds__(256, 2) qkv_f16_kernel(
    const __half* __restrict__ A,
    const float* __restrict__ fc, const float* __restrict__ fs)
{
    const __half* Bm;
    __half* C;
    const int z = blockIdx.z;
    if (z == 0)      { Bm = g_wqh; C = g_Qh; }
    else if (z == 1) { Bm = g_wkh; C = g_Kh; }
    else             { Bm = g_wvh; C = g_Vh; }

    const int tid = threadIdx.x;
    const int wid = tid >> 5, lane = tid & 31;
    const int g = lane >> 2, q = lane & 3;
    const int m0 = blockIdx.y * GTM, n0 = blockIdx.x * GTN;
    const int wm = (wid >> 2) * 64, wn = (wid & 3) * 32;

    float acc[4][4][4];
    gemm_mainloop(A, Bm, m0, n0, acc);

#pragma unroll
    for (int mi = 0; mi < 4; mi++) {
        int row = m0 + wm + mi * 16 + g;
        int t0 = row & (SS - 1);
        int t1 = (row + 8) & (SS - 1);
#pragma unroll
        for (int ni = 0; ni < 4; ni++) {
            int col = n0 + wn + ni * 8 + q * 2;
            float e0 = acc[mi][ni][0], o0 = acc[mi][ni][1];
            float e1 = acc[mi][ni][2], o1 = acc[mi][ni][3];
            if (z < 2) {
                int i = (col & 127) >> 1;
                float c0 = fc[t0 * 64 + i], s0 = fs[t0 * 64 + i];
                float c1 = fc[t1 * 64 + i], s1 = fs[t1 * 64 + i];
                float re0 = e0 * c0 - o0 * s0, ro0 = e0 * s0 + o0 * c0;
                float re1 = e1 * c1 - o1 * s1, ro1 = e1 * s1 + o1 * c1;
                e0 = re0; o0 = ro0; e1 = re1; o1 = ro1;
            }
            *(__half2*)(C + (size_t)row * DD + col) = __floats2half2_rn(e0, o0);
            *(__half2*)(C + (size_t)(row + 8) * DD + col) = __floats2half2_rn(e1, o1);
        }
    }
}

// ---------------------------------------------------------------------------
// Single conversion pass: x + 4 weights -> half
// ---------------------------------------------------------------------------
#define N4X (MDIM * KDIM / 4)      // 2097152
#define N4W (NDIM * KDIM / 4)      // 1048576
__global__ void cvt_all_kernel(const float* __restrict__ x,
                               const float* __restrict__ wq,
                               const float* __restrict__ wk,
                               const float* __restrict__ wv,
                               const float* __restrict__ wo)
{
    int idx = blockIdx.x * blockDim.x + threadIdx.x;
    const float* src;
    __half* dst;
    int off;
    if (idx < N4X) { src = x; dst = g_xh; off = idx; }
    else {
        int j = idx - N4X;
        int w = j >> 20;
        off = j & (N4W - 1);
        if (w == 0)      { src = wq; dst = g_wqh; }
        else if (w == 1) { src = wk; dst = g_wkh; }
        else if (w == 2) { src = wv; dst = g_wvh; }
        else             { src = wo; dst = g_woh; }
    }
    float4 v = ((const float4*)src)[off];
    __half2 h0 = __floats2half2_rn(v.x, v.y);
    __half2 h1 = __floats2half2_rn(v.z, v.w);
    uint2 u;
    u.x = *(uint32_t*)&h0;
    u.y = *(uint32_t*)&h1;
    ((uint2*)dst)[off] = u;
}

// ---------------------------------------------------------------------------
// Flash attention, fp16 mma + ldmatrix, causal (unchanged from R7).
// ---------------------------------------------------------------------------
#define FBQ 128
#define FBK 64
#define FSCALE 0.08838834764831845f
#define KVSTR 272
#define KOFF0 0
#define VOFF0 17408
#define KOFF1 34816
#define VOFF1 52224
#define PSOFF 69632
#define PSTR 144
#define FLASH_SMEM (PSOFF + FBQ * PSTR)    // 88064 B

__device__ __forceinline__ void flash_load_kv(uint32_t sb, int buf, int k0,
                                              size_t brow, size_t head, int tid)
{
    const uint32_t kb = sb + (buf ? KOFF1 : KOFF0);
    const uint32_t vb = sb + (buf ? VOFF1 : VOFF0);
#pragma unroll
    for (int i = 0; i < 4; i++) {
        int id = tid + i * 256;
        int r = id >> 4, c = id & 15;
        cp_async16(kb + r * KVSTR + c * 16, g_Kh + (brow + k0 + r) * (size_t)DD + head + c * 8);
        cp_async16(vb + r * KVSTR + c * 16, g_Vh + (brow + k0 + r) * (size_t)DD + head + c * 8);
    }
}

__global__ void __launch_bounds__(256, 1) flash_f16_kernel()
{
    extern __shared__ __align__(16) char smem[];
    const uint32_t sb = smem_u32(smem);
    const int tid = threadIdx.x;
    const int wid = tid >> 5, lane = tid & 31;
    const int g = lane >> 2, q = lane & 3;
    const int l15 = lane & 15, lhi = (lane >> 4) * 16;
    const int q0 = (gridDim.x - 1 - blockIdx.x) * FBQ;
    const int h = blockIdx.y, b = blockIdx.z;
    const size_t brow = (size_t)b * SS;
    const size_t head = (size_t)h * FHD;

#pragma unroll
    for (int i = 0; i < 8; i++) {
        int id = tid + i * 256;
        int r = id >> 4, c = id & 15;
        cp_async16(sb + r * KVSTR + c * 16, g_Qh + (brow + q0 + r) * (size_t)DD + head + c * 8);
    }
    cp_commit(); cp_wait<0>(); __syncthreads();

    uint32_t qf[8][4];
#pragma unroll
    for (int ks = 0; ks < 8; ks++)
        ldsm4(qf[ks][0], qf[ks][1], qf[ks][2], qf[ks][3],
              sb + (wid * 16 + l15) * KVSTR + ks * 32 + lhi);
    __syncthreads();

    const int rl0 = wid * 16 + g, rl1 = rl0 + 8;
    const int rg0 = q0 + rl0, rg1 = rg0 + 8;

    float m0 = -1e30f, m1 = -1e30f, l0 = 0.0f, l1 = 0.0f;
    float o[16][4];
#pragma unroll
    for (int nf = 0; nf < 16; nf++)
#pragma unroll
        for (int j = 0; j < 4; j++) o[nf][j] = 0.0f;

    const int ktiles = q0 / FBK + 2;
    flash_load_kv(sb, 0, 0, brow, head, tid);
    cp_commit();

    for (int t = 0; t < ktiles; t++) {
        if (t + 1 < ktiles)
            flash_load_kv(sb, (t + 1) & 1, (t + 1) * FBK, brow, head, tid);
        cp_commit();
        cp_wait<1>();
        __syncthreads();

        const int k0 = t * FBK;
        const uint32_t kb = sb + ((t & 1) ? KOFF1 : KOFF0);
        const uint32_t vb = sb + ((t & 1) ? VOFF1 : VOFF0);

        float s[8][4];
#pragma unroll
        for (int nf = 0; nf < 8; nf++)
#pragma unroll
            for (int j = 0; j < 4; j++) s[nf][j] = 0.0f;

#pragma unroll
        for (int ks = 0; ks < 8; ks++) {
#pragma unroll
            for (int nj = 0; nj < 4; nj++) {
                uint32_t b0, b1, b2, b3;
                ldsm4(b0, b1, b2, b3, kb + (nj * 16 + l15) * KVSTR + ks * 32 + lhi);
                mma_f16(s[2 * nj],     qf[ks], b0, b2);
                mma_f16(s[2 * nj + 1], qf[ks], b1, b3);
            }
        }

#pragma unroll
        for (int nf = 0; nf < 8; nf++)
#pragma unroll
            for (int j = 0; j < 4; j++) s[nf][j] *= FSCALE;

        if (k0 + FBK - 1 > q0 + wid * 16) {
#pragma unroll
            for (int nf = 0; nf < 8; nf++) {
                int c0 = k0 + nf * 8 + 2 * q;
                if (c0 > rg0)     s[nf][0] = -1e30f;
                if (c0 + 1 > rg0) s[nf][1] = -1e30f;
                if (c0 > rg1)     s[nf][2] = -1e30f;
                if (c0 + 1 > rg1) s[nf][3] = -1e30f;
            }
        }

        float mx0 = -1e30f, mx1 = -1e30f;
#pragma unroll
        for (int nf = 0; nf < 8; nf++) {
            mx0 = fmaxf(mx0, fmaxf(s[nf][0], s[nf][1]));
            mx1 = fmaxf(mx1, fmaxf(s[nf][2], s[nf][3]));
        }
        mx0 = fmaxf(mx0, __shfl_xor_sync(0xffffffffu, mx0, 1));
        mx0 = fmaxf(mx0, __shfl_xor_sync(0xffffffffu, mx0, 2));
        mx1 = fmaxf(mx1, __shfl_xor_sync(0xffffffffu, mx1, 1));
        mx1 = fmaxf(mx1, __shfl_xor_sync(0xffffffffu, mx1, 2));

        float mn0 = fmaxf(m0, mx0), mn1 = fmaxf(m1, mx1);
        float cr0 = __expf(m0 - mn0), cr1 = __expf(m1 - mn1);
        m0 = mn0; m1 = mn1;

        float rs0 = 0.0f, rs1 = 0.0f;
#pragma unroll
        for (int nf = 0; nf < 8; nf++) {
            s[nf][0] = __expf(s[nf][0] - mn0);
            s[nf][1] = __expf(s[nf][1] - mn0);
            s[nf][2] = __expf(s[nf][2] - mn1);
            s[nf][3] = __expf(s[nf][3] - mn1);
            rs0 += s[nf][0] + s[nf][1];
            rs1 += s[nf][2] + s[nf][3];
        }
        rs0 += __shfl_xor_sync(0xffffffffu, rs0, 1);
        rs0 += __shfl_xor_sync(0xffffffffu, rs0, 2);
        rs1 += __shfl_xor_sync(0xffffffffu, rs1, 1);
        rs1 += __shfl_xor_sync(0xffffffffu, rs1, 2);
        l0 = l0 * cr0 + rs0;
        l1 = l1 * cr1 + rs1;

#pragma unroll
        for (int nf = 0; nf < 16; nf++) {
            o[nf][0] *= cr0; o[nf][1] *= cr0;
            o[nf][2] *= cr1; o[nf][3] *= cr1;
        }

#pragma unroll
        for (int nf = 0; nf < 8; nf++) {
            *(__half2*)(smem + PSOFF + rl0 * PSTR + (nf * 8 + 2 * q) * 2) =
                __floats2half2_rn(s[nf][0], s[nf][1]);
            *(__half2*)(smem + PSOFF + rl1 * PSTR + (nf * 8 + 2 * q) * 2) =
                __floats2half2_rn(s[nf][2], s[nf][3]);
        }
        __syncwarp();

#pragma unroll
        for (int ks2 = 0; ks2 < 4; ks2++) {
            uint32_t pa[4];
            ldsm4(pa[0], pa[1], pa[2], pa[3],
                  sb + PSOFF + (wid * 16 + l15) * PSTR + ks2 * 32 + lhi);
#pragma unroll
            for (int nj = 0; nj < 8; nj++) {
                uint32_t v0, v1, v2, v3;
                ldsm4t(v0, v1, v2, v3,
                       vb + (ks2 * 16 + l15) * KVSTR + nj * 32 + lhi);
                mma_f16(o[2 * nj],     pa, v0, v1);
                mma_f16(o[2 * nj + 1], pa, v2, v3);
            }
        }
        __syncthreads();
    }

    float i0 = 1.0f / l0, i1 = 1.0f / l1;
#pragma unroll
    for (int nf = 0; nf < 16; nf++) {
        *(__half2*)(g_AOh + (brow + rg0) * (size_t)DD + head + nf * 8 + 2 * q) =
            __floats2half2_rn(o[nf][0] * i0, o[nf][1] * i0);
        *(__half2*)(g_AOh + (brow + rg1) * (size_t)DD + head + nf * 8 + 2 * q) =
            __floats2half2_rn(o[nf][2] * i1, o[nf][3] * i1);
    }
}

// ---------------------------------------------------------------------------
// Launch
// ---------------------------------------------------------------------------
extern "C" void kernel_launch(void* const* d_in, const int* in_sizes, int n_in,
                              void* d_out, int out_size)
{
    const float* x  = (const float*)d_in[0];
    const float* wq = (const float*)d_in[1];
    const float* wk = (const float*)d_in[2];
    const float* wv = (const float*)d_in[3];
    const float* wo = (const float*)d_in[4];
    const float* fc = (const float*)d_in[5];
    const float* fs = (const float*)d_in[6];
    float* out = (float*)d_out;

    void *p_xh, *p_woh, *p_aoh;
    cudaGetSymbolAddress(&p_xh,  g_xh);
    cudaGetSymbolAddress(&p_woh, g_woh);
    cudaGetSymbolAddress(&p_aoh, g_AOh);

    cudaFuncSetAttribute(gemm_f16_kernel,
                         cudaFuncAttributeMaxDynamicSharedMemorySize, GEMM_SMEM);
    cudaFuncSetAttribute(qkv_f16_kernel,
                         cudaFuncAttributeMaxDynamicSharedMemorySize, GEMM_SMEM);
    cudaFuncSetAttribute(flash_f16_kernel,
                         cudaFuncAttributeMaxDynamicSharedMemorySize, FLASH_SMEM);

    // 0) one conversion pass: x + 4 weights -> half
    cvt_all_kernel<<<(N4X + 4 * N4W) / 256, 256>>>(x, wq, wk, wv, wo);

    // 1) QKV projections with fused RoPE epilogue -> g_Qh/g_Kh/g_Vh (half)
    dim3 gq(NDIM / GTN, MDIM / GTM, 3);   // (16, 32, 3)
    qkv_f16_kernel<<<gq, 256, GEMM_SMEM>>>((const __half*)p_xh, fc, fs);

    // 2) Causal flash attention -> g_AOh
    flash_f16_kernel<<<dim3(SS / FBQ, NH, BB), 256, FLASH_SMEM>>>();

    // 3) Output projection -> fp32 out
    gemm_f16_kernel<<<dim3(NDIM / GTN, MDIM / GTM), 256, GEMM_SMEM>>>(
        (const __half*)p_aoh, (const __half*)p_woh, out);
}

// round 10
// speedup vs baseline: 7.1667x; 1.0006x over previous
#include <cuda_runtime.h>
#include <cuda_fp16.h>
#include <cstddef>
#include <cstdint>

// Problem constants
#define BB 2
#define SS 2048
#define DD 2048
#define NH 16
#define FHD 128
#define KDIM 2048
#define NDIM 2048
#define MDIM (BB * SS)   // 4096

// ---------------------------------------------------------------------------
// Scratch (device globals — no allocation allowed)
// ---------------------------------------------------------------------------
__device__ __half g_Qh[(size_t)MDIM * DD];
__device__ __half g_Kh[(size_t)MDIM * DD];
__device__ __half g_Vh[(size_t)MDIM * DD];
__device__ __half g_AOh[(size_t)MDIM * DD];
__device__ __half g_xh[(size_t)MDIM * KDIM];
__device__ __half g_wqh[(size_t)NDIM * KDIM];
__device__ __half g_wkh[(size_t)NDIM * KDIM];
__device__ __half g_wvh[(size_t)NDIM * KDIM];
__device__ __half g_woh[(size_t)NDIM * KDIM];

// ---------------------------------------------------------------------------
// Helpers
// ---------------------------------------------------------------------------
__device__ __forceinline__ uint32_t smem_u32(const void* p) {
    uint32_t a;
    asm("{ .reg .u64 t; cvta.to.shared.u64 t, %1; cvt.u32.u64 %0, t; }" : "=r"(a) : "l"(p));
    return a;
}
__device__ __forceinline__ void cp_async16(uint32_t dst, const void* src) {
    asm volatile("cp.async.cg.shared.global [%0], [%1], 16;" :: "r"(dst), "l"(src) : "memory");
}
__device__ __forceinline__ void cp_commit() {
    asm volatile("cp.async.commit_group;" ::: "memory");
}
template <int N>
__device__ __forceinline__ void cp_wait() {
    asm volatile("cp.async.wait_group %0;" :: "n"(N) : "memory");
}
__device__ __forceinline__ void ldsm4(uint32_t& r0, uint32_t& r1, uint32_t& r2, uint32_t& r3,
                                      uint32_t addr) {
    asm volatile("ldmatrix.sync.aligned.m8n8.x4.shared.b16 {%0,%1,%2,%3}, [%4];"
                 : "=r"(r0), "=r"(r1), "=r"(r2), "=r"(r3) : "r"(addr));
}
__device__ __forceinline__ void ldsm4t(uint32_t& r0, uint32_t& r1, uint32_t& r2, uint32_t& r3,
                                       uint32_t addr) {
    asm volatile("ldmatrix.sync.aligned.m8n8.x4.trans.shared.b16 {%0,%1,%2,%3}, [%4];"
                 : "=r"(r0), "=r"(r1), "=r"(r2), "=r"(r3) : "r"(addr));
}
__device__ __forceinline__ void mma_f16(float* d, const uint32_t* a, uint32_t b0, uint32_t b1)
{
    asm volatile(
        "mma.sync.aligned.m16n8k16.row.col.f32.f16.f16.f32 "
        "{%0,%1,%2,%3}, {%4,%5,%6,%7}, {%8,%9}, {%0,%1,%2,%3};"
        : "+f"(d[0]), "+f"(d[1]), "+f"(d[2]), "+f"(d[3])
        : "r"(a[0]), "r"(a[1]), "r"(a[2]), "r"(a[3]), "r"(b0), "r"(b1));
}

// ---------------------------------------------------------------------------
// fp16 mma GEMM mainloop, 3-CTA/SM shape.
// CTA 128x64, 8 warps (4 m x 2 n), warp tile 32x32, K-tile 32, 4-stage ring,
// one __syncthreads per k-tile. Smem row stride 80 B (ldmatrix conflict-free).
// ---------------------------------------------------------------------------
#define GTM 128
#define GTN 64
#define GTK 32
#define GSTR 80
#define A_T_B (GTM * GSTR)                 // 10240
#define B_T_B (GTN * GSTR)                 // 5120
#define STG_B (A_T_B + B_T_B)              // 15360
#define NSTG 4
#define GEMM_SMEM (NSTG * STG_B)           // 61440  (x3 CTAs = 180 KB/SM)
#define KT (KDIM / GTK)                    // 64

__device__ __forceinline__ void gemm_load_stage(uint32_t sbase, int s, int kt,
                                                const __half* __restrict__ A,
                                                const __half* __restrict__ Bm,
                                                int m0, int n0, int tid)
{
    const uint32_t ab = sbase + s * STG_B;
    const uint32_t bb = ab + A_T_B;
    const int kk = kt * GTK;
#pragma unroll
    for (int i = 0; i < 2; i++) {            // A: 512 chunks (128 rows x 4)
        int t = tid + i * 256;
        int r = t >> 2, c = t & 3;
        cp_async16(ab + r * GSTR + c * 16, A + (size_t)(m0 + r) * KDIM + kk + c * 8);
    }
    {                                         // B: 256 chunks (64 rows x 4)
        int r = tid >> 2, c = tid & 3;
        cp_async16(bb + r * GSTR + c * 16, Bm + (size_t)(n0 + r) * KDIM + kk + c * 8);
    }
}

__device__ __forceinline__ void gemm_mainloop(const __half* __restrict__ A,
                                              const __half* __restrict__ Bm,
                                              int m0, int n0,
                                              float acc[2][4][4])
{
    extern __shared__ __align__(16) char smem[];
    const uint32_t sbase = smem_u32(smem);
    const int tid = threadIdx.x;
    const int wid = tid >> 5, lane = tid & 31;
    const int wm = (wid >> 1) * 32, wn = (wid & 1) * 32;
    const int l15 = lane & 15, lhi = (lane >> 4) * 16;

#pragma unroll
    for (int mi = 0; mi < 2; mi++)
#pragma unroll
        for (int ni = 0; ni < 4; ni++)
#pragma unroll
            for (int j = 0; j < 4; j++) acc[mi][ni][j] = 0.0f;

#pragma unroll
    for (int s = 0; s < NSTG - 1; s++) {
        gemm_load_stage(sbase, s, s, A, Bm, m0, n0, tid);
        cp_commit();
    }

    for (int kt = 0; kt < KT; kt++) {
        cp_wait<NSTG - 2>();
        __syncthreads();
        if (kt + NSTG - 1 < KT)
            gemm_load_stage(sbase, (kt + NSTG - 1) & 3, kt + NSTG - 1, A, Bm, m0, n0, tid);
        cp_commit();

        const uint32_t ab = sbase + (kt & 3) * STG_B;
        const uint32_t bb = ab + A_T_B;
#pragma unroll
        for (int ks = 0; ks < 2; ks++) {
            uint32_t a[2][4];
#pragma unroll
            for (int mi = 0; mi < 2; mi++)
                ldsm4(a[mi][0], a[mi][1], a[mi][2], a[mi][3],
                      ab + (wm + mi * 16 + l15) * GSTR + ks * 32 + lhi);
#pragma unroll
            for (int nj = 0; nj < 2; nj++) {
                uint32_t b0, b1, b2, b3;
                ldsm4(b0, b1, b2, b3,
                      bb + (wn + nj * 16 + l15) * GSTR + ks * 32 + lhi);
#pragma unroll
                for (int mi = 0; mi < 2; mi++) {
                    mma_f16(acc[mi][2 * nj],     a[mi], b0, b2);
                    mma_f16(acc[mi][2 * nj + 1], a[mi], b1, b3);
                }
            }
        }
    }
}

// ---------------------------------------------------------------------------
// Out projection: fp32 epilogue to d_out
// ---------------------------------------------------------------------------
__global__ void __launch_bounds__(256, 3) gemm_f16_kernel(
    const __half* __restrict__ A, const __half* __restrict__ Bm, float* __restrict__ C)
{
    const int tid = threadIdx.x;
    const int wid = tid >> 5, lane = tid & 31;
    const int g = lane >> 2, q = lane & 3;
    const int m0 = blockIdx.y * GTM, n0 = blockIdx.x * GTN;
    const int wm = (wid >> 1) * 32, wn = (wid & 1) * 32;

    float acc[2][4][4];
    gemm_mainloop(A, Bm, m0, n0, acc);

#pragma unroll
    for (int mi = 0; mi < 2; mi++) {
        int row = m0 + wm + mi * 16 + g;
#pragma unroll
        for (int ni = 0; ni < 4; ni++) {
            int col = n0 + wn + ni * 8 + q * 2;
            *(float2*)(C + (size_t)row * NDIM + col) =
                make_float2(acc[mi][ni][0], acc[mi][ni][1]);
            *(float2*)(C + (size_t)(row + 8) * NDIM + col) =
                make_float2(acc[mi][ni][2], acc[mi][ni][3]);
        }
    }
}

// ---------------------------------------------------------------------------
// QKV projection with fused RoPE epilogue, half output.
// z=0: Q (rope), z=1: K (rope), z=2: V (plain).
// ---------------------------------------------------------------------------
__global__ void __launch_bounds__(256, 3) qkv_f16_kernel(
    const __half* __restrict__ A,
    const float* __restrict__ fc, const float* __restrict__ fs)
{
    const __half* Bm;
    __half* C;
    const int z = blockIdx.z;
    if (z == 0)      { Bm = g_wqh; C = g_Qh; }
    else if (z == 1) { Bm = g_wkh; C = g_Kh; }
    else             { Bm = g_wvh; C = g_Vh; }

    const int tid = threadIdx.x;
    const int wid = tid >> 5, lane = tid & 31;
    const int g = lane >> 2, q = lane & 3;
    const int m0 = blockIdx.y * GTM, n0 = blockIdx.x * GTN;
    const int wm = (wid >> 1) * 32, wn = (wid & 1) * 32;

    float acc[2][4][4];
    gemm_mainloop(A, Bm, m0, n0, acc);

#pragma unroll
    for (int mi = 0; mi < 2; mi++) {
        int row = m0 + wm + mi * 16 + g;
        int t0 = row & (SS - 1);
        int t1 = (row + 8) & (SS - 1);
#pragma unroll
        for (int ni = 0; ni < 4; ni++) {
            int col = n0 + wn + ni * 8 + q * 2;
            float e0 = acc[mi][ni][0], o0 = acc[mi][ni][1];
            float e1 = acc[mi][ni][2], o1 = acc[mi][ni][3];
            if (z < 2) {
                int i = (col & 127) >> 1;
                float c0 = fc[t0 * 64 + i], s0 = fs[t0 * 64 + i];
                float c1 = fc[t1 * 64 + i], s1 = fs[t1 * 64 + i];
                float re0 = e0 * c0 - o0 * s0, ro0 = e0 * s0 + o0 * c0;
                float re1 = e1 * c1 - o1 * s1, ro1 = e1 * s1 + o1 * c1;
                e0 = re0; o0 = ro0; e1 = re1; o1 = ro1;
            }
            *(__half2*)(C + (size_t)row * DD + col) = __floats2half2_rn(e0, o0);
            *(__half2*)(C + (size_t)(row + 8) * DD + col) = __floats2half2_rn(e1, o1);
        }
    }
}

// ---------------------------------------------------------------------------
// Single conversion pass: x + 4 weights -> half
// ---------------------------------------------------------------------------
#define N4X (MDIM * KDIM / 4)      // 2097152
#define N4W (NDIM * KDIM / 4)      // 1048576
__global__ void cvt_all_kernel(const float* __restrict__ x,
                               const float* __restrict__ wq,
                               const float* __restrict__ wk,
                               const float* __restrict__ wv,
                               const float* __restrict__ wo)
{
    int idx = blockIdx.x * blockDim.x + threadIdx.x;
    const float* src;
    __half* dst;
    int off;
    if (idx < N4X) { src = x; dst = g_xh; off = idx; }
    else {
        int j = idx - N4X;
        int w = j >> 20;
        off = j & (N4W - 1);
        if (w == 0)      { src = wq; dst = g_wqh; }
        else if (w == 1) { src = wk; dst = g_wkh; }
        else if (w == 2) { src = wv; dst = g_wvh; }
        else             { src = wo; dst = g_woh; }
    }
    float4 v = ((const float4*)src)[off];
    __half2 h0 = __floats2half2_rn(v.x, v.y);
    __half2 h1 = __floats2half2_rn(v.z, v.w);
    uint2 u;
    u.x = *(uint32_t*)&h0;
    u.y = *(uint32_t*)&h1;
    ((uint2*)dst)[off] = u;
}

// ---------------------------------------------------------------------------
// Flash attention, fp16 mma + ldmatrix, causal (unchanged from R8).
// ---------------------------------------------------------------------------
#define FBQ 128
#define FBK 64
#define FSCALE 0.08838834764831845f
#define KVSTR 272
#define KOFF0 0
#define VOFF0 17408
#define KOFF1 34816
#define VOFF1 52224
#define PSOFF 69632
#define PSTR 144
#define FLASH_SMEM (PSOFF + FBQ * PSTR)    // 88064 B

__device__ __forceinline__ void flash_load_kv(uint32_t sb, int buf, int k0,
                                              size_t brow, size_t head, int tid)
{
    const uint32_t kb = sb + (buf ? KOFF1 : KOFF0);
    const uint32_t vb = sb + (buf ? VOFF1 : VOFF0);
#pragma unroll
    for (int i = 0; i < 4; i++) {
        int id = tid + i * 256;
        int r = id >> 4, c = id & 15;
        cp_async16(kb + r * KVSTR + c * 16, g_Kh + (brow + k0 + r) * (size_t)DD + head + c * 8);
        cp_async16(vb + r * KVSTR + c * 16, g_Vh + (brow + k0 + r) * (size_t)DD + head + c * 8);
    }
}

__global__ void __launch_bounds__(256, 1) flash_f16_kernel()
{
    extern __shared__ __align__(16) char smem[];
    const uint32_t sb = smem_u32(smem);
    const int tid = threadIdx.x;
    const int wid = tid >> 5, lane = tid & 31;
    const int g = lane >> 2, q = lane & 3;
    const int l15 = lane & 15, lhi = (lane >> 4) * 16;
    const int q0 = (gridDim.x - 1 - blockIdx.x) * FBQ;
    const int h = blockIdx.y, b = blockIdx.z;
    const size_t brow = (size_t)b * SS;
    const size_t head = (size_t)h * FHD;

#pragma unroll
    for (int i = 0; i < 8; i++) {
        int id = tid + i * 256;
        int r = id >> 4, c = id & 15;
        cp_async16(sb + r * KVSTR + c * 16, g_Qh + (brow + q0 + r) * (size_t)DD + head + c * 8);
    }
    cp_commit(); cp_wait<0>(); __syncthreads();

    uint32_t qf[8][4];
#pragma unroll
    for (int ks = 0; ks < 8; ks++)
        ldsm4(qf[ks][0], qf[ks][1], qf[ks][2], qf[ks][3],
              sb + (wid * 16 + l15) * KVSTR + ks * 32 + lhi);
    __syncthreads();

    const int rl0 = wid * 16 + g, rl1 = rl0 + 8;
    const int rg0 = q0 + rl0, rg1 = rg0 + 8;

    float m0 = -1e30f, m1 = -1e30f, l0 = 0.0f, l1 = 0.0f;
    float o[16][4];
#pragma unroll
    for (int nf = 0; nf < 16; nf++)
#pragma unroll
        for (int j = 0; j < 4; j++) o[nf][j] = 0.0f;

    const int ktiles = q0 / FBK + 2;
    flash_load_kv(sb, 0, 0, brow, head, tid);
    cp_commit();

    for (int t = 0; t < ktiles; t++) {
        if (t + 1 < ktiles)
            flash_load_kv(sb, (t + 1) & 1, (t + 1) * FBK, brow, head, tid);
        cp_commit();
        cp_wait<1>();
        __syncthreads();

        const int k0 = t * FBK;
        const uint32_t kb = sb + ((t & 1) ? KOFF1 : KOFF0);
        const uint32_t vb = sb + ((t & 1) ? VOFF1 : VOFF0);

        float s[8][4];
#pragma unroll
        for (int nf = 0; nf < 8; nf++)
#pragma unroll
            for (int j = 0; j < 4; j++) s[nf][j] = 0.0f;

#pragma unroll
        for (int ks = 0; ks < 8; ks++) {
#pragma unroll
            for (int nj = 0; nj < 4; nj++) {
                uint32_t b0, b1, b2, b3;
                ldsm4(b0, b1, b2, b3, kb + (nj * 16 + l15) * KVSTR + ks * 32 + lhi);
                mma_f16(s[2 * nj],     qf[ks], b0, b2);
                mma_f16(s[2 * nj + 1], qf[ks], b1, b3);
            }
        }

#pragma unroll
        for (int nf = 0; nf < 8; nf++)
#pragma unroll
            for (int j = 0; j < 4; j++) s[nf][j] *= FSCALE;

        if (k0 + FBK - 1 > q0 + wid * 16) {
#pragma unroll
            for (int nf = 0; nf < 8; nf++) {
                int c0 = k0 + nf * 8 + 2 * q;
                if (c0 > rg0)     s[nf][0] = -1e30f;
                if (c0 + 1 > rg0) s[nf][1] = -1e30f;
                if (c0 > rg1)     s[nf][2] = -1e30f;
                if (c0 + 1 > rg1) s[nf][3] = -1e30f;
            }
        }

        float mx0 = -1e30f, mx1 = -1e30f;
#pragma unroll
        for (int nf = 0; nf < 8; nf++) {
            mx0 = fmaxf(mx0, fmaxf(s[nf][0], s[nf][1]));
            mx1 = fmaxf(mx1, fmaxf(s[nf][2], s[nf][3]));
        }
        mx0 = fmaxf(mx0, __shfl_xor_sync(0xffffffffu, mx0, 1));
        mx0 = fmaxf(mx0, __shfl_xor_sync(0xffffffffu, mx0, 2));
        mx1 = fmaxf(mx1, __shfl_xor_sync(0xffffffffu, mx1, 1));
        mx1 = fmaxf(mx1, __shfl_xor_sync(0xffffffffu, mx1, 2));

        float mn0 = fmaxf(m0, mx0), mn1 = fmaxf(m1, mx1);
        float cr0 = __expf(m0 - mn0), cr1 = __expf(m1 - mn1);
        m0 = mn0; m1 = mn1;

        float rs0 = 0.0f, rs1 = 0.0f;
#pragma unroll
        for (int nf = 0; nf < 8; nf++) {
            s[nf][0] = __expf(s[nf][0] - mn0);
            s[nf][1] = __expf(s[nf][1] - mn0);
            s[nf][2] = __expf(s[nf][2] - mn1);
            s[nf][3] = __expf(s[nf][3] - mn1);
            rs0 += s[nf][0] + s[nf][1];
            rs1 += s[nf][2] + s[nf][3];
        }
        rs0 += __shfl_xor_sync(0xffffffffu, rs0, 1);
        rs0 += __shfl_xor_sync(0xffffffffu, rs0, 2);
        rs1 += __shfl_xor_sync(0xffffffffu, rs1, 1);
        rs1 += __shfl_xor_sync(0xffffffffu, rs1, 2);
        l0 = l0 * cr0 + rs0;
        l1 = l1 * cr1 + rs1;

#pragma unroll
        for (int nf = 0; nf < 16; nf++) {
            o[nf][0] *= cr0; o[nf][1] *= cr0;
            o[nf][2] *= cr1; o[nf][3] *= cr1;
        }

#pragma unroll
        for (int nf = 0; nf < 8; nf++) {
            *(__half2*)(smem + PSOFF + rl0 * PSTR + (nf * 8 + 2 * q) * 2) =
                __floats2half2_rn(s[nf][0], s[nf][1]);
            *(__half2*)(smem + PSOFF + rl1 * PSTR + (nf * 8 + 2 * q) * 2) =
                __floats2half2_rn(s[nf][2], s[nf][3]);
        }
        __syncwarp();

#pragma unroll
        for (int ks2 = 0; ks2 < 4; ks2++) {
            uint32_t pa[4];
            ldsm4(pa[0], pa[1], pa[2], pa[3],
                  sb + PSOFF + (wid * 16 + l15) * PSTR + ks2 * 32 + lhi);
#pragma unroll
            for (int nj = 0; nj < 8; nj++) {
                uint32_t v0, v1, v2, v3;
                ldsm4t(v0, v1, v2, v3,
                       vb + (ks2 * 16 + l15) * KVSTR + nj * 32 + lhi);
                mma_f16(o[2 * nj],     pa, v0, v1);
                mma_f16(o[2 * nj + 1], pa, v2, v3);
            }
        }
        __syncthreads();
    }

    float i0 = 1.0f / l0, i1 = 1.0f / l1;
#pragma unroll
    for (int nf = 0; nf < 16; nf++) {
        *(__half2*)(g_AOh + (brow + rg0) * (size_t)DD + head + nf * 8 + 2 * q) =
            __floats2half2_rn(o[nf][0] * i0, o[nf][1] * i0);
        *(__half2*)(g_AOh + (brow + rg1) * (size_t)DD + head + nf * 8 + 2 * q) =
            __floats2half2_rn(o[nf][2] * i1, o[nf][3] * i1);
    }
}

// ---------------------------------------------------------------------------
// Launch
// ---------------------------------------------------------------------------
extern "C" void kernel_launch(void* const* d_in, const int* in_sizes, int n_in,
                              void* d_out, int out_size)
{
    const float* x  = (const float*)d_in[0];
    const float* wq = (const float*)d_in[1];
    const float* wk = (const float*)d_in[2];
    const float* wv = (const float*)d_in[3];
    const float* wo = (const float*)d_in[4];
    const float* fc = (const float*)d_in[5];
    const float* fs = (const float*)d_in[6];
    float* out = (float*)d_out;

    void *p_xh, *p_woh, *p_aoh;
    cudaGetSymbolAddress(&p_xh,  g_xh);
    cudaGetSymbolAddress(&p_woh, g_woh);
    cudaGetSymbolAddress(&p_aoh, g_AOh);

    cudaFuncSetAttribute(gemm_f16_kernel,
                         cudaFuncAttributeMaxDynamicSharedMemorySize, GEMM_SMEM);
    cudaFuncSetAttribute(qkv_f16_kernel,
                         cudaFuncAttributeMaxDynamicSharedMemorySize, GEMM_SMEM);
    cudaFuncSetAttribute(flash_f16_kernel,
                         cudaFuncAttributeMaxDynamicSharedMemorySize, FLASH_SMEM);

    // 0) one conversion pass: x + 4 weights -> half
    cvt_all_kernel<<<(N4X + 4 * N4W) / 256, 256>>>(x, wq, wk, wv, wo);

    // 1) QKV projections with fused RoPE epilogue -> g_Qh/g_Kh/g_Vh (half)
    dim3 gq(NDIM / GTN, MDIM / GTM, 3);   // (32, 32, 3)
    qkv_f16_kernel<<<gq, 256, GEMM_SMEM>>>((const __half*)p_xh, fc, fs);

    // 2) Causal flash attention -> g_AOh
    flash_f16_kernel<<<dim3(SS / FBQ, NH, BB), 256, FLASH_SMEM>>>();

    // 3) Output projection -> fp32 out
    gemm_f16_kernel<<<dim3(NDIM / GTN, MDIM / GTM), 256, GEMM_SMEM>>>(
        (const __half*)p_aoh, (const __half*)p_woh, out);
}

// round 11
// speedup vs baseline: 7.2724x; 1.0147x over previous
#include <cuda_runtime.h>
#include <cuda_fp16.h>
#include <cstddef>
#include <cstdint>

// Problem constants
#define BB 2
#define SS 2048
#define DD 2048
#define NH 16
#define FHD 128
#define KDIM 2048
#define NDIM 2048
#define MDIM (BB * SS)   // 4096

// ---------------------------------------------------------------------------
// Scratch (device globals — no allocation allowed)
// ---------------------------------------------------------------------------
__device__ __half g_Qh[(size_t)MDIM * DD];
__device__ __half g_Kh[(size_t)MDIM * DD];
__device__ __half g_Vh[(size_t)MDIM * DD];
__device__ __half g_AOh[(size_t)MDIM * DD];
__device__ __half g_xh[(size_t)MDIM * KDIM];
__device__ __half g_wqh[(size_t)NDIM * KDIM];
__device__ __half g_wkh[(size_t)NDIM * KDIM];
__device__ __half g_wvh[(size_t)NDIM * KDIM];
__device__ __half g_woh[(size_t)NDIM * KDIM];

// ---------------------------------------------------------------------------
// Helpers
// ---------------------------------------------------------------------------
__device__ __forceinline__ uint32_t smem_u32(const void* p) {
    uint32_t a;
    asm("{ .reg .u64 t; cvta.to.shared.u64 t, %1; cvt.u32.u64 %0, t; }" : "=r"(a) : "l"(p));
    return a;
}
__device__ __forceinline__ void cp_async16(uint32_t dst, const void* src) {
    asm volatile("cp.async.cg.shared.global [%0], [%1], 16;" :: "r"(dst), "l"(src) : "memory");
}
__device__ __forceinline__ void cp_commit() {
    asm volatile("cp.async.commit_group;" ::: "memory");
}
template <int N>
__device__ __forceinline__ void cp_wait() {
    asm volatile("cp.async.wait_group %0;" :: "n"(N) : "memory");
}
__device__ __forceinline__ void ldsm4(uint32_t& r0, uint32_t& r1, uint32_t& r2, uint32_t& r3,
                                      uint32_t addr) {
    asm volatile("ldmatrix.sync.aligned.m8n8.x4.shared.b16 {%0,%1,%2,%3}, [%4];"
                 : "=r"(r0), "=r"(r1), "=r"(r2), "=r"(r3) : "r"(addr));
}
__device__ __forceinline__ void ldsm4t(uint32_t& r0, uint32_t& r1, uint32_t& r2, uint32_t& r3,
                                       uint32_t addr) {
    asm volatile("ldmatrix.sync.aligned.m8n8.x4.trans.shared.b16 {%0,%1,%2,%3}, [%4];"
                 : "=r"(r0), "=r"(r1), "=r"(r2), "=r"(r3) : "r"(addr));
}
__device__ __forceinline__ void mma_f16(float* d, const uint32_t* a, uint32_t b0, uint32_t b1)
{
    asm volatile(
        "mma.sync.aligned.m16n8k16.row.col.f32.f16.f16.f32 "
        "{%0,%1,%2,%3}, {%4,%5,%6,%7}, {%8,%9}, {%0,%1,%2,%3};"
        : "+f"(d[0]), "+f"(d[1]), "+f"(d[2]), "+f"(d[3])
        : "r"(a[0]), "r"(a[1]), "r"(a[2]), "r"(a[3]), "r"(b0), "r"(b1));
}

// ---------------------------------------------------------------------------
// fp16 mma GEMM mainloop, software-pipelined fragments.
// CTA 128x64, 8 warps (4m x 2n), warp tile 32x32, K-tile 32, 5-stage ring,
// 2 CTAs/SM. Frags for (kt, ks0) are loaded during iteration kt-1, so mma
// never waits on ldmatrix. cp_wait<2> guarantees stage kt+1 complete at kt.
// ---------------------------------------------------------------------------
#define GTM 128
#define GTN 64
#define GTK 32
#define GSTR 80
#define A_T_B (GTM * GSTR)                 // 10240
#define B_T_B (GTN * GSTR)                 // 5120
#define STG_B (A_T_B + B_T_B)              // 15360
#define NSTG 5
#define GEMM_SMEM (NSTG * STG_B)           // 76800 (x2 CTAs = 153.6 KB/SM)
#define KT (KDIM / GTK)                    // 64

__device__ __forceinline__ void gemm_load_stage(uint32_t sbase, int s, int kt,
                                                const __half* __restrict__ A,
                                                const __half* __restrict__ Bm,
                                                int m0, int n0, int tid)
{
    const uint32_t ab = sbase + s * STG_B;
    const uint32_t bb = ab + A_T_B;
    const int kk = kt * GTK;
#pragma unroll
    for (int i = 0; i < 2; i++) {            // A: 512 chunks (128 rows x 4)
        int t = tid + i * 256;
        int r = t >> 2, c = t & 3;
        cp_async16(ab + r * GSTR + c * 16, A + (size_t)(m0 + r) * KDIM + kk + c * 8);
    }
    {                                         // B: 256 chunks (64 rows x 4)
        int r = tid >> 2, c = tid & 3;
        cp_async16(bb + r * GSTR + c * 16, Bm + (size_t)(n0 + r) * KDIM + kk + c * 8);
    }
}

__device__ __forceinline__ void gemm_mainloop(const __half* __restrict__ A,
                                              const __half* __restrict__ Bm,
                                              int m0, int n0,
                                              float acc[2][4][4])
{
    extern __shared__ __align__(16) char smem[];
    const uint32_t sbase = smem_u32(smem);
    const int tid = threadIdx.x;
    const int wid = tid >> 5, lane = tid & 31;
    const int wm = (wid >> 1) * 32, wn = (wid & 1) * 32;
    const int l15 = lane & 15, lhi = (lane >> 4) * 16;
    const uint32_t aoff = (wm + l15) * GSTR + lhi;   // + mi*16*GSTR + ks*32
    const uint32_t boff = (wn + l15) * GSTR + lhi;

#pragma unroll
    for (int mi = 0; mi < 2; mi++)
#pragma unroll
        for (int ni = 0; ni < 4; ni++)
#pragma unroll
            for (int j = 0; j < 4; j++) acc[mi][ni][j] = 0.0f;

    // Prologue: fill stages 0..3
#pragma unroll
    for (int s = 0; s < NSTG - 1; s++) {
        gemm_load_stage(sbase, s, s, A, Bm, m0, n0, tid);
        cp_commit();
    }
    cp_wait<2>();          // stages 0,1 complete
    __syncthreads();

    uint32_t a0[2][4], b0[2][4];   // frag buffer for ks=0 of current kt
    uint32_t a1[2][4], b1[2][4];   // frag buffer for ks=1
    {
        const uint32_t ab = sbase;
#pragma unroll
        for (int mi = 0; mi < 2; mi++)
            ldsm4(a0[mi][0], a0[mi][1], a0[mi][2], a0[mi][3],
                  ab + aoff + mi * 16 * GSTR);
        const uint32_t bb = ab + A_T_B;
#pragma unroll
        for (int nj = 0; nj < 2; nj++)
            ldsm4(b0[nj][0], b0[nj][1], b0[nj][2], b0[nj][3],
                  bb + boff + nj * 16 * GSTR);
    }

    int st_cur = 0, st_wr = NSTG - 1;
    for (int kt = 0; kt < KT; kt++) {
        cp_wait<2>();
        __syncthreads();
        if (kt + NSTG - 1 < KT)
            gemm_load_stage(sbase, st_wr, kt + NSTG - 1, A, Bm, m0, n0, tid);
        cp_commit();

        const uint32_t ab = sbase + st_cur * STG_B;
        const uint32_t bb = ab + A_T_B;
        const int st_nxt = (st_cur + 1 == NSTG) ? 0 : st_cur + 1;

        // load ks=1 frags (current stage)
#pragma unroll
        for (int mi = 0; mi < 2; mi++)
            ldsm4(a1[mi][0], a1[mi][1], a1[mi][2], a1[mi][3],
                  ab + aoff + mi * 16 * GSTR + 32);
#pragma unroll
        for (int nj = 0; nj < 2; nj++)
            ldsm4(b1[nj][0], b1[nj][1], b1[nj][2], b1[nj][3],
                  bb + boff + nj * 16 * GSTR + 32);

        // mma ks=0 (frags loaded last iteration)
#pragma unroll
        for (int nj = 0; nj < 2; nj++)
#pragma unroll
            for (int mi = 0; mi < 2; mi++) {
                mma_f16(acc[mi][2 * nj],     a0[mi], b0[nj][0], b0[nj][2]);
                mma_f16(acc[mi][2 * nj + 1], a0[mi], b0[nj][1], b0[nj][3]);
            }

        // early load ks=0 frags of NEXT k-tile (stage st_nxt; complete per wait<2>)
        if (kt + 1 < KT) {
            const uint32_t abn = sbase + st_nxt * STG_B;
            const uint32_t bbn = abn + A_T_B;
#pragma unroll
            for (int mi = 0; mi < 2; mi++)
                ldsm4(a0[mi][0], a0[mi][1], a0[mi][2], a0[mi][3],
                      abn + aoff + mi * 16 * GSTR);
#pragma unroll
            for (int nj = 0; nj < 2; nj++)
                ldsm4(b0[nj][0], b0[nj][1], b0[nj][2], b0[nj][3],
                      bbn + boff + nj * 16 * GSTR);
        }

        // mma ks=1
#pragma unroll
        for (int nj = 0; nj < 2; nj++)
#pragma unroll
            for (int mi = 0; mi < 2; mi++) {
                mma_f16(acc[mi][2 * nj],     a1[mi], b1[nj][0], b1[nj][2]);
                mma_f16(acc[mi][2 * nj + 1], a1[mi], b1[nj][1], b1[nj][3]);
            }

        st_cur = st_nxt;
        st_wr = (st_wr + 1 == NSTG) ? 0 : st_wr + 1;
    }
}

// ---------------------------------------------------------------------------
// Out projection: fp32 epilogue to d_out
// ---------------------------------------------------------------------------
__global__ void __launch_bounds__(256, 2) gemm_f16_kernel(
    const __half* __restrict__ A, const __half* __restrict__ Bm, float* __restrict__ C)
{
    const int tid = threadIdx.x;
    const int wid = tid >> 5, lane = tid & 31;
    const int g = lane >> 2, q = lane & 3;
    const int m0 = blockIdx.y * GTM, n0 = blockIdx.x * GTN;
    const int wm = (wid >> 1) * 32, wn = (wid & 1) * 32;

    float acc[2][4][4];
    gemm_mainloop(A, Bm, m0, n0, acc);

#pragma unroll
    for (int mi = 0; mi < 2; mi++) {
        int row = m0 + wm + mi * 16 + g;
#pragma unroll
        for (int ni = 0; ni < 4; ni++) {
            int col = n0 + wn + ni * 8 + q * 2;
            *(float2*)(C + (size_t)row * NDIM + col) =
                make_float2(acc[mi][ni][0], acc[mi][ni][1]);
            *(float2*)(C + (size_t)(row + 8) * NDIM + col) =
                make_float2(acc[mi][ni][2], acc[mi][ni][3]);
        }
    }
}

// ---------------------------------------------------------------------------
// QKV projection with fused RoPE epilogue, half output.
// z=0: Q (rope), z=1: K (rope), z=2: V (plain).
// ---------------------------------------------------------------------------
__global__ void __launch_bounds__(256, 2) qkv_f16_kernel(
    const __half* __restrict__ A,
    const float* __restrict__ fc, const float* __restrict__ fs)
{
    const __half* Bm;
    __half* C;
    const int z = blockIdx.z;
    if (z == 0)      { Bm = g_wqh; C = g_Qh; }
    else if (z == 1) { Bm = g_wkh; C = g_Kh; }
    else             { Bm = g_wvh; C = g_Vh; }

    const int tid = threadIdx.x;
    const int wid = tid >> 5, lane = tid & 31;
    const int g = lane >> 2, q = lane & 3;
    const int m0 = blockIdx.y * GTM, n0 = blockIdx.x * GTN;
    const int wm = (wid >> 1) * 32, wn = (wid & 1) * 32;

    float acc[2][4][4];
    gemm_mainloop(A, Bm, m0, n0, acc);

#pragma unroll
    for (int mi = 0; mi < 2; mi++) {
        int row = m0 + wm + mi * 16 + g;
        int t0 = row & (SS - 1);
        int t1 = (row + 8) & (SS - 1);
#pragma unroll
        for (int ni = 0; ni < 4; ni++) {
            int col = n0 + wn + ni * 8 + q * 2;
            float e0 = acc[mi][ni][0], o0 = acc[mi][ni][1];
            float e1 = acc[mi][ni][2], o1 = acc[mi][ni][3];
            if (z < 2) {
                int i = (col & 127) >> 1;
                float c0 = fc[t0 * 64 + i], s0 = fs[t0 * 64 + i];
                float c1 = fc[t1 * 64 + i], s1 = fs[t1 * 64 + i];
                float re0 = e0 * c0 - o0 * s0, ro0 = e0 * s0 + o0 * c0;
                float re1 = e1 * c1 - o1 * s1, ro1 = e1 * s1 + o1 * c1;
                e0 = re0; o0 = ro0; e1 = re1; o1 = ro1;
            }
            *(__half2*)(C + (size_t)row * DD + col) = __floats2half2_rn(e0, o0);
            *(__half2*)(C + (size_t)(row + 8) * DD + col) = __floats2half2_rn(e1, o1);
        }
    }
}

// ---------------------------------------------------------------------------
// Single conversion pass: x + 4 weights -> half
// ---------------------------------------------------------------------------
#define N4X (MDIM * KDIM / 4)      // 2097152
#define N4W (NDIM * KDIM / 4)      // 1048576
__global__ void cvt_all_kernel(const float* __restrict__ x,
                               const float* __restrict__ wq,
                               const float* __restrict__ wk,
                               const float* __restrict__ wv,
                               const float* __restrict__ wo)
{
    int idx = blockIdx.x * blockDim.x + threadIdx.x;
    const float* src;
    __half* dst;
    int off;
    if (idx < N4X) { src = x; dst = g_xh; off = idx; }
    else {
        int j = idx - N4X;
        int w = j >> 20;
        off = j & (N4W - 1);
        if (w == 0)      { src = wq; dst = g_wqh; }
        else if (w == 1) { src = wk; dst = g_wkh; }
        else if (w == 2) { src = wv; dst = g_wvh; }
        else             { src = wo; dst = g_woh; }
    }
    float4 v = ((const float4*)src)[off];
    __half2 h0 = __floats2half2_rn(v.x, v.y);
    __half2 h1 = __floats2half2_rn(v.z, v.w);
    uint2 u;
    u.x = *(uint32_t*)&h0;
    u.y = *(uint32_t*)&h1;
    ((uint2*)dst)[off] = u;
}

// ---------------------------------------------------------------------------
// Flash attention, fp16 mma + ldmatrix, causal (unchanged from R10).
// ---------------------------------------------------------------------------
#define FBQ 128
#define FBK 64
#define FSCALE 0.08838834764831845f
#define KVSTR 272
#define KOFF0 0
#define VOFF0 17408
#define KOFF1 34816
#define VOFF1 52224
#define PSOFF 69632
#define PSTR 144
#define FLASH_SMEM (PSOFF + FBQ * PSTR)    // 88064 B

__device__ __forceinline__ void flash_load_kv(uint32_t sb, int buf, int k0,
                                              size_t brow, size_t head, int tid)
{
    const uint32_t kb = sb + (buf ? KOFF1 : KOFF0);
    const uint32_t vb = sb + (buf ? VOFF1 : VOFF0);
#pragma unroll
    for (int i = 0; i < 4; i++) {
        int id = tid + i * 256;
        int r = id >> 4, c = id & 15;
        cp_async16(kb + r * KVSTR + c * 16, g_Kh + (brow + k0 + r) * (size_t)DD + head + c * 8);
        cp_async16(vb + r * KVSTR + c * 16, g_Vh + (brow + k0 + r) * (size_t)DD + head + c * 8);
    }
}

__global__ void __launch_bounds__(256, 1) flash_f16_kernel()
{
    extern __shared__ __align__(16) char smem[];
    const uint32_t sb = smem_u32(smem);
    const int tid = threadIdx.x;
    const int wid = tid >> 5, lane = tid & 31;
    const int g = lane >> 2, q = lane & 3;
    const int l15 = lane & 15, lhi = (lane >> 4) * 16;
    const int q0 = (gridDim.x - 1 - blockIdx.x) * FBQ;
    const int h = blockIdx.y, b = blockIdx.z;
    const size_t brow = (size_t)b * SS;
    const size_t head = (size_t)h * FHD;

#pragma unroll
    for (int i = 0; i < 8; i++) {
        int id = tid + i * 256;
        int r = id >> 4, c = id & 15;
        cp_async16(sb + r * KVSTR + c * 16, g_Qh + (brow + q0 + r) * (size_t)DD + head + c * 8);
    }
    cp_commit(); cp_wait<0>(); __syncthreads();

    uint32_t qf[8][4];
#pragma unroll
    for (int ks = 0; ks < 8; ks++)
        ldsm4(qf[ks][0], qf[ks][1], qf[ks][2], qf[ks][3],
              sb + (wid * 16 + l15) * KVSTR + ks * 32 + lhi);
    __syncthreads();

    const int rl0 = wid * 16 + g, rl1 = rl0 + 8;
    const int rg0 = q0 + rl0, rg1 = rg0 + 8;

    float m0 = -1e30f, m1 = -1e30f, l0 = 0.0f, l1 = 0.0f;
    float o[16][4];
#pragma unroll
    for (int nf = 0; nf < 16; nf++)
#pragma unroll
        for (int j = 0; j < 4; j++) o[nf][j] = 0.0f;

    const int ktiles = q0 / FBK + 2;
    flash_load_kv(sb, 0, 0, brow, head, tid);
    cp_commit();

    for (int t = 0; t < ktiles; t++) {
        if (t + 1 < ktiles)
            flash_load_kv(sb, (t + 1) & 1, (t + 1) * FBK, brow, head, tid);
        cp_commit();
        cp_wait<1>();
        __syncthreads();

        const int k0 = t * FBK;
        const uint32_t kb = sb + ((t & 1) ? KOFF1 : KOFF0);
        const uint32_t vb = sb + ((t & 1) ? VOFF1 : VOFF0);

        float s[8][4];
#pragma unroll
        for (int nf = 0; nf < 8; nf++)
#pragma unroll
            for (int j = 0; j < 4; j++) s[nf][j] = 0.0f;

#pragma unroll
        for (int ks = 0; ks < 8; ks++) {
#pragma unroll
            for (int nj = 0; nj < 4; nj++) {
                uint32_t b0, b1, b2, b3;
                ldsm4(b0, b1, b2, b3, kb + (nj * 16 + l15) * KVSTR + ks * 32 + lhi);
                mma_f16(s[2 * nj],     qf[ks], b0, b2);
                mma_f16(s[2 * nj + 1], qf[ks], b1, b3);
            }
        }

#pragma unroll
        for (int nf = 0; nf < 8; nf++)
#pragma unroll
            for (int j = 0; j < 4; j++) s[nf][j] *= FSCALE;

        if (k0 + FBK - 1 > q0 + wid * 16) {
#pragma unroll
            for (int nf = 0; nf < 8; nf++) {
                int c0 = k0 + nf * 8 + 2 * q;
                if (c0 > rg0)     s[nf][0] = -1e30f;
                if (c0 + 1 > rg0) s[nf][1] = -1e30f;
                if (c0 > rg1)     s[nf][2] = -1e30f;
                if (c0 + 1 > rg1) s[nf][3] = -1e30f;
            }
        }

        float mx0 = -1e30f, mx1 = -1e30f;
#pragma unroll
        for (int nf = 0; nf < 8; nf++) {
            mx0 = fmaxf(mx0, fmaxf(s[nf][0], s[nf][1]));
            mx1 = fmaxf(mx1, fmaxf(s[nf][2], s[nf][3]));
        }
        mx0 = fmaxf(mx0, __shfl_xor_sync(0xffffffffu, mx0, 1));
        mx0 = fmaxf(mx0, __shfl_xor_sync(0xffffffffu, mx0, 2));
        mx1 = fmaxf(mx1, __shfl_xor_sync(0xffffffffu, mx1, 1));
        mx1 = fmaxf(mx1, __shfl_xor_sync(0xffffffffu, mx1, 2));

        float mn0 = fmaxf(m0, mx0), mn1 = fmaxf(m1, mx1);
        float cr0 = __expf(m0 - mn0), cr1 = __expf(m1 - mn1);
        m0 = mn0; m1 = mn1;

        float rs0 = 0.0f, rs1 = 0.0f;
#pragma unroll
        for (int nf = 0; nf < 8; nf++) {
            s[nf][0] = __expf(s[nf][0] - mn0);
            s[nf][1] = __expf(s[nf][1] - mn0);
            s[nf][2] = __expf(s[nf][2] - mn1);
            s[nf][3] = __expf(s[nf][3] - mn1);
            rs0 += s[nf][0] + s[nf][1];
            rs1 += s[nf][2] + s[nf][3];
        }
        rs0 += __shfl_xor_sync(0xffffffffu, rs0, 1);
        rs0 += __shfl_xor_sync(0xffffffffu, rs0, 2);
        rs1 += __shfl_xor_sync(0xffffffffu, rs1, 1);
        rs1 += __shfl_xor_sync(0xffffffffu, rs1, 2);
        l0 = l0 * cr0 + rs0;
        l1 = l1 * cr1 + rs1;

#pragma unroll
        for (int nf = 0; nf < 16; nf++) {
            o[nf][0] *= cr0; o[nf][1] *= cr0;
            o[nf][2] *= cr1; o[nf][3] *= cr1;
        }

#pragma unroll
        for (int nf = 0; nf < 8; nf++) {
            *(__half2*)(smem + PSOFF + rl0 * PSTR + (nf * 8 + 2 * q) * 2) =
                __floats2half2_rn(s[nf][0], s[nf][1]);
            *(__half2*)(smem + PSOFF + rl1 * PSTR + (nf * 8 + 2 * q) * 2) =
                __floats2half2_rn(s[nf][2], s[nf][3]);
        }
        __syncwarp();

#pragma unroll
        for (int ks2 = 0; ks2 < 4; ks2++) {
            uint32_t pa[4];
            ldsm4(pa[0], pa[1], pa[2], pa[3],
                  sb + PSOFF + (wid * 16 + l15) * PSTR + ks2 * 32 + lhi);
#pragma unroll
            for (int nj = 0; nj < 8; nj++) {
                uint32_t v0, v1, v2, v3;
                ldsm4t(v0, v1, v2, v3,
                       vb + (ks2 * 16 + l15) * KVSTR + nj * 32 + lhi);
                mma_f16(o[2 * nj],     pa, v0, v1);
                mma_f16(o[2 * nj + 1], pa, v2, v3);
            }
        }
        __syncthreads();
    }

    float i0 = 1.0f / l0, i1 = 1.0f / l1;
#pragma unroll
    for (int nf = 0; nf < 16; nf++) {
        *(__half2*)(g_AOh + (brow + rg0) * (size_t)DD + head + nf * 8 + 2 * q) =
            __floats2half2_rn(o[nf][0] * i0, o[nf][1] * i0);
        *(__half2*)(g_AOh + (brow + rg1) * (size_t)DD + head + nf * 8 + 2 * q) =
            __floats2half2_rn(o[nf][2] * i1, o[nf][3] * i1);
    }
}

// ---------------------------------------------------------------------------
// Launch
// ---------------------------------------------------------------------------
extern "C" void kernel_launch(void* const* d_in, const int* in_sizes, int n_in,
                              void* d_out, int out_size)
{
    const float* x  = (const float*)d_in[0];
    const float* wq = (const float*)d_in[1];
    const float* wk = (const float*)d_in[2];
    const float* wv = (const float*)d_in[3];
    const float* wo = (const float*)d_in[4];
    const float* fc = (const float*)d_in[5];
    const float* fs = (const float*)d_in[6];
    float* out = (float*)d_out;

    void *p_xh, *p_woh, *p_aoh;
    cudaGetSymbolAddress(&p_xh,  g_xh);
    cudaGetSymbolAddress(&p_woh, g_woh);
    cudaGetSymbolAddress(&p_aoh, g_AOh);

    cudaFuncSetAttribute(gemm_f16_kernel,
                         cudaFuncAttributeMaxDynamicSharedMemorySize, GEMM_SMEM);
    cudaFuncSetAttribute(qkv_f16_kernel,
                         cudaFuncAttributeMaxDynamicSharedMemorySize, GEMM_SMEM);
    cudaFuncSetAttribute(flash_f16_kernel,
                         cudaFuncAttributeMaxDynamicSharedMemorySize, FLASH_SMEM);

    // 0) one conversion pass: x + 4 weights -> half
    cvt_all_kernel<<<(N4X + 4 * N4W) / 256, 256>>>(x, wq, wk, wv, wo);

    // 1) QKV projections with fused RoPE epilogue -> g_Qh/g_Kh/g_Vh (half)
    dim3 gq(NDIM / GTN, MDIM / GTM, 3);   // (32, 32, 3)
    qkv_f16_kernel<<<gq, 256, GEMM_SMEM>>>((const __half*)p_xh, fc, fs);

    // 2) Causal flash attention -> g_AOh
    flash_f16_kernel<<<dim3(SS / FBQ, NH, BB), 256, FLASH_SMEM>>>();

    // 3) Output projection -> fp32 out
    gemm_f16_kernel<<<dim3(NDIM / GTN, MDIM / GTM), 256, GEMM_SMEM>>>(
        (const __half*)p_aoh, (const __half*)p_woh, out);
}

// round 12
// speedup vs baseline: 7.6272x; 1.0488x over previous
#include <cuda_runtime.h>
#include <cuda_fp16.h>
#include <cstddef>
#include <cstdint>

// Problem constants
#define BB 2
#define SS 2048
#define DD 2048
#define NH 16
#define FHD 128
#define KDIM 2048
#define NDIM 2048
#define MDIM (BB * SS)   // 4096

// ---------------------------------------------------------------------------
// Scratch (device globals — no allocation allowed)
// ---------------------------------------------------------------------------
__device__ __half g_Qh[(size_t)MDIM * DD];
__device__ __half g_Kh[(size_t)MDIM * DD];
__device__ __half g_Vh[(size_t)MDIM * DD];
__device__ __half g_AOh[(size_t)MDIM * DD];
__device__ __half g_xh[(size_t)MDIM * KDIM];
__device__ __half g_wqh[(size_t)NDIM * KDIM];
__device__ __half g_wkh[(size_t)NDIM * KDIM];
__device__ __half g_wvh[(size_t)NDIM * KDIM];
__device__ __half g_woh[(size_t)NDIM * KDIM];

// ---------------------------------------------------------------------------
// Helpers
// ---------------------------------------------------------------------------
__device__ __forceinline__ uint32_t smem_u32(const void* p) {
    uint32_t a;
    asm("{ .reg .u64 t; cvta.to.shared.u64 t, %1; cvt.u32.u64 %0, t; }" : "=r"(a) : "l"(p));
    return a;
}
__device__ __forceinline__ void cp_async16(uint32_t dst, const void* src) {
    asm volatile("cp.async.cg.shared.global [%0], [%1], 16;" :: "r"(dst), "l"(src) : "memory");
}
__device__ __forceinline__ void cp_commit() {
    asm volatile("cp.async.commit_group;" ::: "memory");
}
template <int N>
__device__ __forceinline__ void cp_wait() {
    asm volatile("cp.async.wait_group %0;" :: "n"(N) : "memory");
}
__device__ __forceinline__ void ldsm4(uint32_t& r0, uint32_t& r1, uint32_t& r2, uint32_t& r3,
                                      uint32_t addr) {
    asm volatile("ldmatrix.sync.aligned.m8n8.x4.shared.b16 {%0,%1,%2,%3}, [%4];"
                 : "=r"(r0), "=r"(r1), "=r"(r2), "=r"(r3) : "r"(addr));
}
__device__ __forceinline__ void ldsm4t(uint32_t& r0, uint32_t& r1, uint32_t& r2, uint32_t& r3,
                                       uint32_t addr) {
    asm volatile("ldmatrix.sync.aligned.m8n8.x4.trans.shared.b16 {%0,%1,%2,%3}, [%4];"
                 : "=r"(r0), "=r"(r1), "=r"(r2), "=r"(r3) : "r"(addr));
}
__device__ __forceinline__ void mma_f16(float* d, const uint32_t* a, uint32_t b0, uint32_t b1)
{
    asm volatile(
        "mma.sync.aligned.m16n8k16.row.col.f32.f16.f16.f32 "
        "{%0,%1,%2,%3}, {%4,%5,%6,%7}, {%8,%9}, {%0,%1,%2,%3};"
        : "+f"(d[0]), "+f"(d[1]), "+f"(d[2]), "+f"(d[3])
        : "r"(a[0]), "r"(a[1]), "r"(a[2]), "r"(a[3]), "r"(b0), "r"(b1));
}

// ---------------------------------------------------------------------------
// fp16 mma GEMM mainloop, crossbar-light shape + pipelined fragments.
// CTA 128x256, 8 warps (2m x 4n), warp tile 64x64 (0.086 B/MAC total smem
// traffic -> under the 128 B/cyc crossbar at full tensor rate).
// K-tile 32, 4-stage ring, one barrier per k-tile, ldmatrix frags
// double-buffered so mma never waits on LDS. 1 CTA/SM.
// ---------------------------------------------------------------------------
#define GTM 128
#define GTN 256
#define GTK 32
#define GSTR 80
#define A_T_B (GTM * GSTR)                 // 10240
#define B_T_B (GTN * GSTR)                 // 20480
#define STG_B (A_T_B + B_T_B)              // 30720
#define NSTG 4
#define GEMM_SMEM (NSTG * STG_B)           // 122880
#define KT (KDIM / GTK)                    // 64

__device__ __forceinline__ void gemm_load_stage(uint32_t sbase, int s, int kt,
                                                const __half* __restrict__ A,
                                                const __half* __restrict__ Bm,
                                                int m0, int n0, int tid)
{
    const uint32_t ab = sbase + s * STG_B;
    const uint32_t bb = ab + A_T_B;
    const int kk = kt * GTK;
#pragma unroll
    for (int i = 0; i < 2; i++) {            // A: 512 chunks (128 rows x 4)
        int t = tid + i * 256;
        int r = t >> 2, c = t & 3;
        cp_async16(ab + r * GSTR + c * 16, A + (size_t)(m0 + r) * KDIM + kk + c * 8);
    }
#pragma unroll
    for (int i = 0; i < 4; i++) {            // B: 1024 chunks (256 rows x 4)
        int t = tid + i * 256;
        int r = t >> 2, c = t & 3;
        cp_async16(bb + r * GSTR + c * 16, Bm + (size_t)(n0 + r) * KDIM + kk + c * 8);
    }
}

__device__ __forceinline__ void gemm_mainloop(const __half* __restrict__ A,
                                              const __half* __restrict__ Bm,
                                              int m0, int n0,
                                              float acc[4][8][4])
{
    extern __shared__ __align__(16) char smem[];
    const uint32_t sbase = smem_u32(smem);
    const int tid = threadIdx.x;
    const int wid = tid >> 5, lane = tid & 31;
    const int wm = (wid >> 2) * 64, wn = (wid & 3) * 64;
    const int l15 = lane & 15, lhi = (lane >> 4) * 16;
    const uint32_t aoff = (wm + l15) * GSTR + lhi;   // + mi*16*GSTR + ks*32
    const uint32_t boff = (wn + l15) * GSTR + lhi;   // + nj*16*GSTR + ks*32

#pragma unroll
    for (int mi = 0; mi < 4; mi++)
#pragma unroll
        for (int ni = 0; ni < 8; ni++)
#pragma unroll
            for (int j = 0; j < 4; j++) acc[mi][ni][j] = 0.0f;

    // Prologue: fill stages 0..2
#pragma unroll
    for (int s = 0; s < NSTG - 1; s++) {
        gemm_load_stage(sbase, s, s, A, Bm, m0, n0, tid);
        cp_commit();
    }
    cp_wait<2>();          // stage 0 complete
    __syncthreads();

    uint32_t a0[4][4], b0f[4][4];   // frags for ks=0 of current kt
    uint32_t a1[4][4], b1f[4][4];   // frags for ks=1
    {
        const uint32_t ab = sbase;
        const uint32_t bb = ab + A_T_B;
#pragma unroll
        for (int mi = 0; mi < 4; mi++)
            ldsm4(a0[mi][0], a0[mi][1], a0[mi][2], a0[mi][3],
                  ab + aoff + mi * 16 * GSTR);
#pragma unroll
        for (int nj = 0; nj < 4; nj++)
            ldsm4(b0f[nj][0], b0f[nj][1], b0f[nj][2], b0f[nj][3],
                  bb + boff + nj * 16 * GSTR);
    }

    int st_cur = 0, st_wr = NSTG - 1;
    for (int kt = 0; kt < KT; kt++) {
        cp_wait<2>();      // stage kt+1 complete (3 groups in flight max)
        __syncthreads();
        if (kt + NSTG - 1 < KT)
            gemm_load_stage(sbase, st_wr, kt + NSTG - 1, A, Bm, m0, n0, tid);
        cp_commit();

        const uint32_t ab = sbase + st_cur * STG_B;
        const uint32_t bb = ab + A_T_B;
        const int st_nxt = (st_cur + 1 == NSTG) ? 0 : st_cur + 1;

        // load ks=1 frags (current stage)
#pragma unroll
        for (int mi = 0; mi < 4; mi++)
            ldsm4(a1[mi][0], a1[mi][1], a1[mi][2], a1[mi][3],
                  ab + aoff + mi * 16 * GSTR + 32);
#pragma unroll
        for (int nj = 0; nj < 4; nj++)
            ldsm4(b1f[nj][0], b1f[nj][1], b1f[nj][2], b1f[nj][3],
                  bb + boff + nj * 16 * GSTR + 32);

        // mma ks=0 (frags loaded during previous iteration)
#pragma unroll
        for (int nj = 0; nj < 4; nj++)
#pragma unroll
            for (int mi = 0; mi < 4; mi++) {
                mma_f16(acc[mi][2 * nj],     a0[mi], b0f[nj][0], b0f[nj][2]);
                mma_f16(acc[mi][2 * nj + 1], a0[mi], b0f[nj][1], b0f[nj][3]);
            }

        // early load ks=0 frags of NEXT k-tile (stage st_nxt, already complete)
        if (kt + 1 < KT) {
            const uint32_t abn = sbase + st_nxt * STG_B;
            const uint32_t bbn = abn + A_T_B;
#pragma unroll
            for (int mi = 0; mi < 4; mi++)
                ldsm4(a0[mi][0], a0[mi][1], a0[mi][2], a0[mi][3],
                      abn + aoff + mi * 16 * GSTR);
#pragma unroll
            for (int nj = 0; nj < 4; nj++)
                ldsm4(b0f[nj][0], b0f[nj][1], b0f[nj][2], b0f[nj][3],
                      bbn + boff + nj * 16 * GSTR);
        }

        // mma ks=1
#pragma unroll
        for (int nj = 0; nj < 4; nj++)
#pragma unroll
            for (int mi = 0; mi < 4; mi++) {
                mma_f16(acc[mi][2 * nj],     a1[mi], b1f[nj][0], b1f[nj][2]);
                mma_f16(acc[mi][2 * nj + 1], a1[mi], b1f[nj][1], b1f[nj][3]);
            }

        st_cur = st_nxt;
        st_wr = (st_wr + 1 == NSTG) ? 0 : st_wr + 1;
    }
}

// ---------------------------------------------------------------------------
// Out projection: fp32 epilogue to d_out
// ---------------------------------------------------------------------------
__global__ void __launch_bounds__(256, 1) gemm_f16_kernel(
    const __half* __restrict__ A, const __half* __restrict__ Bm, float* __restrict__ C)
{
    const int tid = threadIdx.x;
    const int wid = tid >> 5, lane = tid & 31;
    const int g = lane >> 2, q = lane & 3;
    const int m0 = blockIdx.y * GTM, n0 = blockIdx.x * GTN;
    const int wm = (wid >> 2) * 64, wn = (wid & 3) * 64;

    float acc[4][8][4];
    gemm_mainloop(A, Bm, m0, n0, acc);

#pragma unroll
    for (int mi = 0; mi < 4; mi++) {
        int row = m0 + wm + mi * 16 + g;
#pragma unroll
        for (int ni = 0; ni < 8; ni++) {
            int col = n0 + wn + ni * 8 + q * 2;
            *(float2*)(C + (size_t)row * NDIM + col) =
                make_float2(acc[mi][ni][0], acc[mi][ni][1]);
            *(float2*)(C + (size_t)(row + 8) * NDIM + col) =
                make_float2(acc[mi][ni][2], acc[mi][ni][3]);
        }
    }
}

// ---------------------------------------------------------------------------
// QKV projection with fused RoPE epilogue, half output.
// z=0: Q (rope), z=1: K (rope), z=2: V (plain).
// ---------------------------------------------------------------------------
__global__ void __launch_bounds__(256, 1) qkv_f16_kernel(
    const __half* __restrict__ A,
    const float* __restrict__ fc, const float* __restrict__ fs)
{
    const __half* Bm;
    __half* C;
    const int z = blockIdx.z;
    if (z == 0)      { Bm = g_wqh; C = g_Qh; }
    else if (z == 1) { Bm = g_wkh; C = g_Kh; }
    else             { Bm = g_wvh; C = g_Vh; }

    const int tid = threadIdx.x;
    const int wid = tid >> 5, lane = tid & 31;
    const int g = lane >> 2, q = lane & 3;
    const int m0 = blockIdx.y * GTM, n0 = blockIdx.x * GTN;
    const int wm = (wid >> 2) * 64, wn = (wid & 3) * 64;

    float acc[4][8][4];
    gemm_mainloop(A, Bm, m0, n0, acc);

#pragma unroll
    for (int mi = 0; mi < 4; mi++) {
        int row = m0 + wm + mi * 16 + g;
        int t0 = row & (SS - 1);
        int t1 = (row + 8) & (SS - 1);
#pragma unroll
        for (int ni = 0; ni < 8; ni++) {
            int col = n0 + wn + ni * 8 + q * 2;
            float e0 = acc[mi][ni][0], o0 = acc[mi][ni][1];
            float e1 = acc[mi][ni][2], o1 = acc[mi][ni][3];
            if (z < 2) {
                int i = (col & 127) >> 1;
                float c0 = fc[t0 * 64 + i], s0 = fs[t0 * 64 + i];
                float c1 = fc[t1 * 64 + i], s1 = fs[t1 * 64 + i];
                float re0 = e0 * c0 - o0 * s0, ro0 = e0 * s0 + o0 * c0;
                float re1 = e1 * c1 - o1 * s1, ro1 = e1 * s1 + o1 * c1;
                e0 = re0; o0 = ro0; e1 = re1; o1 = ro1;
            }
            *(__half2*)(C + (size_t)row * DD + col) = __floats2half2_rn(e0, o0);
            *(__half2*)(C + (size_t)(row + 8) * DD + col) = __floats2half2_rn(e1, o1);
        }
    }
}

// ---------------------------------------------------------------------------
// Single conversion pass: x + 4 weights -> half
// ---------------------------------------------------------------------------
#define N4X (MDIM * KDIM / 4)      // 2097152
#define N4W (NDIM * KDIM / 4)      // 1048576
__global__ void cvt_all_kernel(const float* __restrict__ x,
                               const float* __restrict__ wq,
                               const float* __restrict__ wk,
                               const float* __restrict__ wv,
                               const float* __restrict__ wo)
{
    int idx = blockIdx.x * blockDim.x + threadIdx.x;
    const float* src;
    __half* dst;
    int off;
    if (idx < N4X) { src = x; dst = g_xh; off = idx; }
    else {
        int j = idx - N4X;
        int w = j >> 20;
        off = j & (N4W - 1);
        if (w == 0)      { src = wq; dst = g_wqh; }
        else if (w == 1) { src = wk; dst = g_wkh; }
        else if (w == 2) { src = wv; dst = g_wvh; }
        else             { src = wo; dst = g_woh; }
    }
    float4 v = ((const float4*)src)[off];
    __half2 h0 = __floats2half2_rn(v.x, v.y);
    __half2 h1 = __floats2half2_rn(v.z, v.w);
    uint2 u;
    u.x = *(uint32_t*)&h0;
    u.y = *(uint32_t*)&h1;
    ((uint2*)dst)[off] = u;
}

// ---------------------------------------------------------------------------
// Flash attention, fp16 mma + ldmatrix, causal (unchanged from R11).
// ---------------------------------------------------------------------------
#define FBQ 128
#define FBK 64
#define FSCALE 0.08838834764831845f
#define KVSTR 272
#define KOFF0 0
#define VOFF0 17408
#define KOFF1 34816
#define VOFF1 52224
#define PSOFF 69632
#define PSTR 144
#define FLASH_SMEM (PSOFF + FBQ * PSTR)    // 88064 B

__device__ __forceinline__ void flash_load_kv(uint32_t sb, int buf, int k0,
                                              size_t brow, size_t head, int tid)
{
    const uint32_t kb = sb + (buf ? KOFF1 : KOFF0);
    const uint32_t vb = sb + (buf ? VOFF1 : VOFF0);
#pragma unroll
    for (int i = 0; i < 4; i++) {
        int id = tid + i * 256;
        int r = id >> 4, c = id & 15;
        cp_async16(kb + r * KVSTR + c * 16, g_Kh + (brow + k0 + r) * (size_t)DD + head + c * 8);
        cp_async16(vb + r * KVSTR + c * 16, g_Vh + (brow + k0 + r) * (size_t)DD + head + c * 8);
    }
}

__global__ void __launch_bounds__(256, 1) flash_f16_kernel()
{
    extern __shared__ __align__(16) char smem[];
    const uint32_t sb = smem_u32(smem);
    const int tid = threadIdx.x;
    const int wid = tid >> 5, lane = tid & 31;
    const int g = lane >> 2, q = lane & 3;
    const int l15 = lane & 15, lhi = (lane >> 4) * 16;
    const int q0 = (gridDim.x - 1 - blockIdx.x) * FBQ;
    const int h = blockIdx.y, b = blockIdx.z;
    const size_t brow = (size_t)b * SS;
    const size_t head = (size_t)h * FHD;

#pragma unroll
    for (int i = 0; i < 8; i++) {
        int id = tid + i * 256;
        int r = id >> 4, c = id & 15;
        cp_async16(sb + r * KVSTR + c * 16, g_Qh + (brow + q0 + r) * (size_t)DD + head + c * 8);
    }
    cp_commit(); cp_wait<0>(); __syncthreads();

    uint32_t qf[8][4];
#pragma unroll
    for (int ks = 0; ks < 8; ks++)
        ldsm4(qf[ks][0], qf[ks][1], qf[ks][2], qf[ks][3],
              sb + (wid * 16 + l15) * KVSTR + ks * 32 + lhi);
    __syncthreads();

    const int rl0 = wid * 16 + g, rl1 = rl0 + 8;
    const int rg0 = q0 + rl0, rg1 = rg0 + 8;

    float m0 = -1e30f, m1 = -1e30f, l0 = 0.0f, l1 = 0.0f;
    float o[16][4];
#pragma unroll
    for (int nf = 0; nf < 16; nf++)
#pragma unroll
        for (int j = 0; j < 4; j++) o[nf][j] = 0.0f;

    const int ktiles = q0 / FBK + 2;
    flash_load_kv(sb, 0, 0, brow, head, tid);
    cp_commit();

    for (int t = 0; t < ktiles; t++) {
        if (t + 1 < ktiles)
            flash_load_kv(sb, (t + 1) & 1, (t + 1) * FBK, brow, head, tid);
        cp_commit();
        cp_wait<1>();
        __syncthreads();

        const int k0 = t * FBK;
        const uint32_t kb = sb + ((t & 1) ? KOFF1 : KOFF0);
        const uint32_t vb = sb + ((t & 1) ? VOFF1 : VOFF0);

        float s[8][4];
#pragma unroll
        for (int nf = 0; nf < 8; nf++)
#pragma unroll
            for (int j = 0; j < 4; j++) s[nf][j] = 0.0f;

#pragma unroll
        for (int ks = 0; ks < 8; ks++) {
#pragma unroll
            for (int nj = 0; nj < 4; nj++) {
                uint32_t b0, b1, b2, b3;
                ldsm4(b0, b1, b2, b3, kb + (nj * 16 + l15) * KVSTR + ks * 32 + lhi);
                mma_f16(s[2 * nj],     qf[ks], b0, b2);
                mma_f16(s[2 * nj + 1], qf[ks], b1, b3);
            }
        }

#pragma unroll
        for (int nf = 0; nf < 8; nf++)
#pragma unroll
            for (int j = 0; j < 4; j++) s[nf][j] *= FSCALE;

        if (k0 + FBK - 1 > q0 + wid * 16) {
#pragma unroll
            for (int nf = 0; nf < 8; nf++) {
                int c0 = k0 + nf * 8 + 2 * q;
                if (c0 > rg0)     s[nf][0] = -1e30f;
                if (c0 + 1 > rg0) s[nf][1] = -1e30f;
                if (c0 > rg1)     s[nf][2] = -1e30f;
                if (c0 + 1 > rg1) s[nf][3] = -1e30f;
            }
        }

        float mx0 = -1e30f, mx1 = -1e30f;
#pragma unroll
        for (int nf = 0; nf < 8; nf++) {
            mx0 = fmaxf(mx0, fmaxf(s[nf][0], s[nf][1]));
            mx1 = fmaxf(mx1, fmaxf(s[nf][2], s[nf][3]));
        }
        mx0 = fmaxf(mx0, __shfl_xor_sync(0xffffffffu, mx0, 1));
        mx0 = fmaxf(mx0, __shfl_xor_sync(0xffffffffu, mx0, 2));
        mx1 = fmaxf(mx1, __shfl_xor_sync(0xffffffffu, mx1, 1));
        mx1 = fmaxf(mx1, __shfl_xor_sync(0xffffffffu, mx1, 2));

        float mn0 = fmaxf(m0, mx0), mn1 = fmaxf(m1, mx1);
        float cr0 = __expf(m0 - mn0), cr1 = __expf(m1 - mn1);
        m0 = mn0; m1 = mn1;

        float rs0 = 0.0f, rs1 = 0.0f;
#pragma unroll
        for (int nf = 0; nf < 8; nf++) {
            s[nf][0] = __expf(s[nf][0] - mn0);
            s[nf][1] = __expf(s[nf][1] - mn0);
            s[nf][2] = __expf(s[nf][2] - mn1);
            s[nf][3] = __expf(s[nf][3] - mn1);
            rs0 += s[nf][0] + s[nf][1];
            rs1 += s[nf][2] + s[nf][3];
        }
        rs0 += __shfl_xor_sync(0xffffffffu, rs0, 1);
        rs0 += __shfl_xor_sync(0xffffffffu, rs0, 2);
        rs1 += __shfl_xor_sync(0xffffffffu, rs1, 1);
        rs1 += __shfl_xor_sync(0xffffffffu, rs1, 2);
        l0 = l0 * cr0 + rs0;
        l1 = l1 * cr1 + rs1;

#pragma unroll
        for (int nf = 0; nf < 16; nf++) {
            o[nf][0] *= cr0; o[nf][1] *= cr0;
            o[nf][2] *= cr1; o[nf][3] *= cr1;
        }

#pragma unroll
        for (int nf = 0; nf < 8; nf++) {
            *(__half2*)(smem + PSOFF + rl0 * PSTR + (nf * 8 + 2 * q) * 2) =
                __floats2half2_rn(s[nf][0], s[nf][1]);
            *(__half2*)(smem + PSOFF + rl1 * PSTR + (nf * 8 + 2 * q) * 2) =
                __floats2half2_rn(s[nf][2], s[nf][3]);
        }
        __syncwarp();

#pragma unroll
        for (int ks2 = 0; ks2 < 4; ks2++) {
            uint32_t pa[4];
            ldsm4(pa[0], pa[1], pa[2], pa[3],
                  sb + PSOFF + (wid * 16 + l15) * PSTR + ks2 * 32 + lhi);
#pragma unroll
            for (int nj = 0; nj < 8; nj++) {
                uint32_t v0, v1, v2, v3;
                ldsm4t(v0, v1, v2, v3,
                       vb + (ks2 * 16 + l15) * KVSTR + nj * 32 + lhi);
                mma_f16(o[2 * nj],     pa, v0, v1);
                mma_f16(o[2 * nj + 1], pa, v2, v3);
            }
        }
        __syncthreads();
    }

    float i0 = 1.0f / l0, i1 = 1.0f / l1;
#pragma unroll
    for (int nf = 0; nf < 16; nf++) {
        *(__half2*)(g_AOh + (brow + rg0) * (size_t)DD + head + nf * 8 + 2 * q) =
            __floats2half2_rn(o[nf][0] * i0, o[nf][1] * i0);
        *(__half2*)(g_AOh + (brow + rg1) * (size_t)DD + head + nf * 8 + 2 * q) =
            __floats2half2_rn(o[nf][2] * i1, o[nf][3] * i1);
    }
}

// ---------------------------------------------------------------------------
// Launch
// ---------------------------------------------------------------------------
extern "C" void kernel_launch(void* const* d_in, const int* in_sizes, int n_in,
                              void* d_out, int out_size)
{
    const float* x  = (const float*)d_in[0];
    const float* wq = (const float*)d_in[1];
    const float* wk = (const float*)d_in[2];
    const float* wv = (const float*)d_in[3];
    const float* wo = (const float*)d_in[4];
    const float* fc = (const float*)d_in[5];
    const float* fs = (const float*)d_in[6];
    float* out = (float*)d_out;

    void *p_xh, *p_woh, *p_aoh;
    cudaGetSymbolAddress(&p_xh,  g_xh);
    cudaGetSymbolAddress(&p_woh, g_woh);
    cudaGetSymbolAddress(&p_aoh, g_AOh);

    cudaFuncSetAttribute(gemm_f16_kernel,
                         cudaFuncAttributeMaxDynamicSharedMemorySize, GEMM_SMEM);
    cudaFuncSetAttribute(qkv_f16_kernel,
                         cudaFuncAttributeMaxDynamicSharedMemorySize, GEMM_SMEM);
    cudaFuncSetAttribute(flash_f16_kernel,
                         cudaFuncAttributeMaxDynamicSharedMemorySize, FLASH_SMEM);

    // 0) one conversion pass: x + 4 weights -> half
    cvt_all_kernel<<<(N4X + 4 * N4W) / 256, 256>>>(x, wq, wk, wv, wo);

    // 1) QKV projections with fused RoPE epilogue -> g_Qh/g_Kh/g_Vh (half)
    dim3 gq(NDIM / GTN, MDIM / GTM, 3);   // (8, 32, 3)
    qkv_f16_kernel<<<gq, 256, GEMM_SMEM>>>((const __half*)p_xh, fc, fs);

    // 2) Causal flash attention -> g_AOh
    flash_f16_kernel<<<dim3(SS / FBQ, NH, BB), 256, FLASH_SMEM>>>();

    // 3) Output projection -> fp32 out
    gemm_f16_kernel<<<dim3(NDIM / GTN, MDIM / GTM), 256, GEMM_SMEM>>>(
        (const __half*)p_aoh, (const __half*)p_woh, out);
}

// round 14
// speedup vs baseline: 8.4493x; 1.1078x over previous
#include <cuda_runtime.h>
#include <cuda_fp16.h>
#include <cstddef>
#include <cstdint>

// Problem constants
#define BB 2
#define SS 2048
#define DD 2048
#define NH 16
#define FHD 128
#define KDIM 2048
#define NDIM 2048
#define MDIM (BB * SS)   // 4096

// ---------------------------------------------------------------------------
// Scratch (device globals — no allocation allowed)
// ---------------------------------------------------------------------------
__device__ __half g_Qh[(size_t)MDIM * DD];
__device__ __half g_Kh[(size_t)MDIM * DD];
__device__ __half g_Vh[(size_t)MDIM * DD];
__device__ __half g_AOh[(size_t)MDIM * DD];
__device__ __half g_xh[(size_t)MDIM * KDIM];
__device__ __half g_wqh[(size_t)NDIM * KDIM];
__device__ __half g_wkh[(size_t)NDIM * KDIM];
__device__ __half g_wvh[(size_t)NDIM * KDIM];
__device__ __half g_woh[(size_t)NDIM * KDIM];

// ---------------------------------------------------------------------------
// Helpers
// ---------------------------------------------------------------------------
__device__ __forceinline__ uint32_t smem_u32(const void* p) {
    uint32_t a;
    asm("{ .reg .u64 t; cvta.to.shared.u64 t, %1; cvt.u32.u64 %0, t; }" : "=r"(a) : "l"(p));
    return a;
}
__device__ __forceinline__ void cp_async16(uint32_t dst, const void* src) {
    asm volatile("cp.async.cg.shared.global [%0], [%1], 16;" :: "r"(dst), "l"(src) : "memory");
}
__device__ __forceinline__ void cp_commit() {
    asm volatile("cp.async.commit_group;" ::: "memory");
}
template <int N>
__device__ __forceinline__ void cp_wait() {
    asm volatile("cp.async.wait_group %0;" :: "n"(N) : "memory");
}
__device__ __forceinline__ void ldsm4(uint32_t& r0, uint32_t& r1, uint32_t& r2, uint32_t& r3,
                                      uint32_t addr) {
    asm volatile("ldmatrix.sync.aligned.m8n8.x4.shared.b16 {%0,%1,%2,%3}, [%4];"
                 : "=r"(r0), "=r"(r1), "=r"(r2), "=r"(r3) : "r"(addr));
}
__device__ __forceinline__ void ldsm4t(uint32_t& r0, uint32_t& r1, uint32_t& r2, uint32_t& r3,
                                       uint32_t addr) {
    asm volatile("ldmatrix.sync.aligned.m8n8.x4.trans.shared.b16 {%0,%1,%2,%3}, [%4];"
                 : "=r"(r0), "=r"(r1), "=r"(r2), "=r"(r3) : "r"(addr));
}
__device__ __forceinline__ void mma_f16(float* d, const uint32_t* a, uint32_t b0, uint32_t b1)
{
    asm volatile(
        "mma.sync.aligned.m16n8k16.row.col.f32.f16.f16.f32 "
        "{%0,%1,%2,%3}, {%4,%5,%6,%7}, {%8,%9}, {%0,%1,%2,%3};"
        : "+f"(d[0]), "+f"(d[1]), "+f"(d[2]), "+f"(d[3])
        : "r"(a[0]), "r"(a[1]), "r"(a[2]), "r"(a[3]), "r"(b0), "r"(b1));
}

// ---------------------------------------------------------------------------
// fp16 mma GEMM mainloop: 128-thread CTA, 4 warps (2m x 2n) of 64x64 tiles,
// 2 CTAs/SM (two independent barrier domains), K-tile 32, 4-stage ring,
// one barrier per k-tile, ldmatrix frags double-buffered.
// Crossbar traffic ~0.094 B/MAC -> under 128 B/cyc at full tensor rate.
// ---------------------------------------------------------------------------
#define GTM 128
#define GTN 128
#define GTK 32
#define GSTR 80
#define NTHR 128
#define A_T_B (GTM * GSTR)                 // 10240
#define B_T_B (GTN * GSTR)                 // 10240
#define STG_B (A_T_B + B_T_B)              // 20480
#define NSTG 4
#define GEMM_SMEM (NSTG * STG_B)           // 81920 (x2 CTAs = 163.8 KB/SM)
#define KT (KDIM / GTK)                    // 64

__device__ __forceinline__ void gemm_load_stage(uint32_t sbase, int s, int kt,
                                                const __half* __restrict__ A,
                                                const __half* __restrict__ Bm,
                                                int m0, int n0, int tid)
{
    const uint32_t ab = sbase + s * STG_B;
    const uint32_t bb = ab + A_T_B;
    const int kk = kt * GTK;
#pragma unroll
    for (int i = 0; i < 4; i++) {            // A: 512 chunks (128 rows x 4)
        int t = tid + i * NTHR;
        int r = t >> 2, c = t & 3;
        cp_async16(ab + r * GSTR + c * 16, A + (size_t)(m0 + r) * KDIM + kk + c * 8);
    }
#pragma unroll
    for (int i = 0; i < 4; i++) {            // B: 512 chunks (128 rows x 4)
        int t = tid + i * NTHR;
        int r = t >> 2, c = t & 3;
        cp_async16(bb + r * GSTR + c * 16, Bm + (size_t)(n0 + r) * KDIM + kk + c * 8);
    }
}

__device__ __forceinline__ void gemm_mainloop(const __half* __restrict__ A,
                                              const __half* __restrict__ Bm,
                                              int m0, int n0,
                                              float acc[4][8][4])
{
    extern __shared__ __align__(16) char smem[];
    const uint32_t sbase = smem_u32(smem);
    const int tid = threadIdx.x;
    const int wid = tid >> 5, lane = tid & 31;
    const int wm = (wid >> 1) * 64, wn = (wid & 1) * 64;
    const int l15 = lane & 15, lhi = (lane >> 4) * 16;
    const uint32_t aoff = (wm + l15) * GSTR + lhi;
    const uint32_t boff = (wn + l15) * GSTR + lhi;

#pragma unroll
    for (int mi = 0; mi < 4; mi++)
#pragma unroll
        for (int ni = 0; ni < 8; ni++)
#pragma unroll
            for (int j = 0; j < 4; j++) acc[mi][ni][j] = 0.0f;

    // Prologue: fill stages 0..2
#pragma unroll
    for (int s = 0; s < NSTG - 1; s++) {
        gemm_load_stage(sbase, s, s, A, Bm, m0, n0, tid);
        cp_commit();
    }
    cp_wait<2>();          // stage 0 complete
    __syncthreads();

    uint32_t a0[4][4], b0f[4][4];   // frags for ks=0 of current kt
    uint32_t a1[4][4], b1f[4][4];   // frags for ks=1
    {
        const uint32_t ab = sbase;
        const uint32_t bb = ab + A_T_B;
#pragma unroll
        for (int mi = 0; mi < 4; mi++)
            ldsm4(a0[mi][0], a0[mi][1], a0[mi][2], a0[mi][3],
                  ab + aoff + mi * 16 * GSTR);
#pragma unroll
        for (int nj = 0; nj < 4; nj++)
            ldsm4(b0f[nj][0], b0f[nj][1], b0f[nj][2], b0f[nj][3],
                  bb + boff + nj * 16 * GSTR);
    }

    int st_cur = 0, st_wr = NSTG - 1;
    for (int kt = 0; kt < KT; kt++) {
        cp_wait<2>();      // stage kt+1 complete
        __syncthreads();
        if (kt + NSTG - 1 < KT)
            gemm_load_stage(sbase, st_wr, kt + NSTG - 1, A, Bm, m0, n0, tid);
        cp_commit();

        const uint32_t ab = sbase + st_cur * STG_B;
        const uint32_t bb = ab + A_T_B;
        const int st_nxt = (st_cur + 1 == NSTG) ? 0 : st_cur + 1;

        // load ks=1 frags (current stage)
#pragma unroll
        for (int mi = 0; mi < 4; mi++)
            ldsm4(a1[mi][0], a1[mi][1], a1[mi][2], a1[mi][3],
                  ab + aoff + mi * 16 * GSTR + 32);
#pragma unroll
        for (int nj = 0; nj < 4; nj++)
            ldsm4(b1f[nj][0], b1f[nj][1], b1f[nj][2], b1f[nj][3],
                  bb + boff + nj * 16 * GSTR + 32);

        // mma ks=0 (frags loaded during previous iteration)
#pragma unroll
        for (int nj = 0; nj < 4; nj++)
#pragma unroll
            for (int mi = 0; mi < 4; mi++) {
                mma_f16(acc[mi][2 * nj],     a0[mi], b0f[nj][0], b0f[nj][2]);
                mma_f16(acc[mi][2 * nj + 1], a0[mi], b0f[nj][1], b0f[nj][3]);
            }

        // early load ks=0 frags of NEXT k-tile
        if (kt + 1 < KT) {
            const uint32_t abn = sbase + st_nxt * STG_B;
            const uint32_t bbn = abn + A_T_B;
#pragma unroll
            for (int mi = 0; mi < 4; mi++)
                ldsm4(a0[mi][0], a0[mi][1], a0[mi][2], a0[mi][3],
                      abn + aoff + mi * 16 * GSTR);
#pragma unroll
            for (int nj = 0; nj < 4; nj++)
                ldsm4(b0f[nj][0], b0f[nj][1], b0f[nj][2], b0f[nj][3],
                      bbn + boff + nj * 16 * GSTR);
        }

        // mma ks=1
#pragma unroll
        for (int nj = 0; nj < 4; nj++)
#pragma unroll
            for (int mi = 0; mi < 4; mi++) {
                mma_f16(acc[mi][2 * nj],     a1[mi], b1f[nj][0], b1f[nj][2]);
                mma_f16(acc[mi][2 * nj + 1], a1[mi], b1f[nj][1], b1f[nj][3]);
            }

        st_cur = st_nxt;
        st_wr = (st_wr + 1 == NSTG) ? 0 : st_wr + 1;
    }
}

// ---------------------------------------------------------------------------
// Out projection: fp32 epilogue to d_out
// ---------------------------------------------------------------------------
__global__ void __launch_bounds__(NTHR, 2) gemm_f16_kernel(
    const __half* __restrict__ A, const __half* __restrict__ Bm, float* __restrict__ C)
{
    const int tid = threadIdx.x;
    const int wid = tid >> 5, lane = tid & 31;
    const int g = lane >> 2, q = lane & 3;
    const int m0 = blockIdx.y * GTM, n0 = blockIdx.x * GTN;
    const int wm = (wid >> 1) * 64, wn = (wid & 1) * 64;

    float acc[4][8][4];
    gemm_mainloop(A, Bm, m0, n0, acc);

#pragma unroll
    for (int mi = 0; mi < 4; mi++) {
        int row = m0 + wm + mi * 16 + g;
#pragma unroll
        for (int ni = 0; ni < 8; ni++) {
            int col = n0 + wn + ni * 8 + q * 2;
            *(float2*)(C + (size_t)row * NDIM + col) =
                make_float2(acc[mi][ni][0], acc[mi][ni][1]);
            *(float2*)(C + (size_t)(row + 8) * NDIM + col) =
                make_float2(acc[mi][ni][2], acc[mi][ni][3]);
        }
    }
}

// ---------------------------------------------------------------------------
// QKV projection with fused RoPE epilogue, half output.
// z=0: Q (rope), z=1: K (rope), z=2: V (plain).
// ---------------------------------------------------------------------------
__global__ void __launch_bounds__(NTHR, 2) qkv_f16_kernel(
    const __half* __restrict__ A,
    const float* __restrict__ fc, const float* __restrict__ fs)
{
    const __half* Bm;
    __half* C;
    const int z = blockIdx.z;
    if (z == 0)      { Bm = g_wqh; C = g_Qh; }
    else if (z == 1) { Bm = g_wkh; C = g_Kh; }
    else             { Bm = g_wvh; C = g_Vh; }

    const int tid = threadIdx.x;
    const int wid = tid >> 5, lane = tid & 31;
    const int g = lane >> 2, q = lane & 3;
    const int m0 = blockIdx.y * GTM, n0 = blockIdx.x * GTN;
    const int wm = (wid >> 1) * 64, wn = (wid & 1) * 64;

    float acc[4][8][4];
    gemm_mainloop(A, Bm, m0, n0, acc);

#pragma unroll
    for (int mi = 0; mi < 4; mi++) {
        int row = m0 + wm + mi * 16 + g;
        int t0 = row & (SS - 1);
        int t1 = (row + 8) & (SS - 1);
#pragma unroll
        for (int ni = 0; ni < 8; ni++) {
            int col = n0 + wn + ni * 8 + q * 2;
            float e0 = acc[mi][ni][0], o0 = acc[mi][ni][1];
            float e1 = acc[mi][ni][2], o1 = acc[mi][ni][3];
            if (z < 2) {
                int i = (col & 127) >> 1;
                float c0 = fc[t0 * 64 + i], s0 = fs[t0 * 64 + i];
                float c1 = fc[t1 * 64 + i], s1 = fs[t1 * 64 + i];
                float re0 = e0 * c0 - o0 * s0, ro0 = e0 * s0 + o0 * c0;
                float re1 = e1 * c1 - o1 * s1, ro1 = e1 * s1 + o1 * c1;
                e0 = re0; o0 = ro0; e1 = re1; o1 = ro1;
            }
            *(__half2*)(C + (size_t)row * DD + col) = __floats2half2_rn(e0, o0);
            *(__half2*)(C + (size_t)(row + 8) * DD + col) = __floats2half2_rn(e1, o1);
        }
    }
}

// ---------------------------------------------------------------------------
// Single conversion pass: x + 4 weights -> half
// ---------------------------------------------------------------------------
#define N4X (MDIM * KDIM / 4)      // 2097152
#define N4W (NDIM * KDIM / 4)      // 1048576
__global__ void cvt_all_kernel(const float* __restrict__ x,
                               const float* __restrict__ wq,
                               const float* __restrict__ wk,
                               const float* __restrict__ wv,
                               const float* __restrict__ wo)
{
    int idx = blockIdx.x * blockDim.x + threadIdx.x;
    const float* src;
    __half* dst;
    int off;
    if (idx < N4X) { src = x; dst = g_xh; off = idx; }
    else {
        int j = idx - N4X;
        int w = j >> 20;
        off = j & (N4W - 1);
        if (w == 0)      { src = wq; dst = g_wqh; }
        else if (w == 1) { src = wk; dst = g_wkh; }
        else if (w == 2) { src = wv; dst = g_wvh; }
        else             { src = wo; dst = g_woh; }
    }
    float4 v = ((const float4*)src)[off];
    __half2 h0 = __floats2half2_rn(v.x, v.y);
    __half2 h1 = __floats2half2_rn(v.z, v.w);
    uint2 u;
    u.x = *(uint32_t*)&h0;
    u.y = *(uint32_t*)&h1;
    ((uint2*)dst)[off] = u;
}

// ---------------------------------------------------------------------------
// Flash attention, fp16 mma + ldmatrix, causal (unchanged from R12).
// ---------------------------------------------------------------------------
#define FBQ 128
#define FBK 64
#define FSCALE 0.08838834764831845f
#define KVSTR 272
#define KOFF0 0
#define VOFF0 17408
#define KOFF1 34816
#define VOFF1 52224
#define PSOFF 69632
#define PSTR 144
#define FLASH_SMEM (PSOFF + FBQ * PSTR)    // 88064 B

__device__ __forceinline__ void flash_load_kv(uint32_t sb, int buf, int k0,
                                              size_t brow, size_t head, int tid)
{
    const uint32_t kb = sb + (buf ? KOFF1 : KOFF0);
    const uint32_t vb = sb + (buf ? VOFF1 : VOFF0);
#pragma unroll
    for (int i = 0; i < 4; i++) {
        int id = tid + i * 256;
        int r = id >> 4, c = id & 15;
        cp_async16(kb + r * KVSTR + c * 16, g_Kh + (brow + k0 + r) * (size_t)DD + head + c * 8);
        cp_async16(vb + r * KVSTR + c * 16, g_Vh + (brow + k0 + r) * (size_t)DD + head + c * 8);
    }
}

__global__ void __launch_bounds__(256, 1) flash_f16_kernel()
{
    extern __shared__ __align__(16) char smem[];
    const uint32_t sb = smem_u32(smem);
    const int tid = threadIdx.x;
    const int wid = tid >> 5, lane = tid & 31;
    const int g = lane >> 2, q = lane & 3;
    const int l15 = lane & 15, lhi = (lane >> 4) * 16;
    const int q0 = (gridDim.x - 1 - blockIdx.x) * FBQ;
    const int h = blockIdx.y, b = blockIdx.z;
    const size_t brow = (size_t)b * SS;
    const size_t head = (size_t)h * FHD;

#pragma unroll
    for (int i = 0; i < 8; i++) {
        int id = tid + i * 256;
        int r = id >> 4, c = id & 15;
        cp_async16(sb + r * KVSTR + c * 16, g_Qh + (brow + q0 + r) * (size_t)DD + head + c * 8);
    }
    cp_commit(); cp_wait<0>(); __syncthreads();

    uint32_t qf[8][4];
#pragma unroll
    for (int ks = 0; ks < 8; ks++)
        ldsm4(qf[ks][0], qf[ks][1], qf[ks][2], qf[ks][3],
              sb + (wid * 16 + l15) * KVSTR + ks * 32 + lhi);
    __syncthreads();

    const int rl0 = wid * 16 + g, rl1 = rl0 + 8;
    const int rg0 = q0 + rl0, rg1 = rg0 + 8;

    float m0 = -1e30f, m1 = -1e30f, l0 = 0.0f, l1 = 0.0f;
    float o[16][4];
#pragma unroll
    for (int nf = 0; nf < 16; nf++)
#pragma unroll
        for (int j = 0; j < 4; j++) o[nf][j] = 0.0f;

    const int ktiles = q0 / FBK + 2;
    flash_load_kv(sb, 0, 0, brow, head, tid);
    cp_commit();

    for (int t = 0; t < ktiles; t++) {
        if (t + 1 < ktiles)
            flash_load_kv(sb, (t + 1) & 1, (t + 1) * FBK, brow, head, tid);
        cp_commit();
        cp_wait<1>();
        __syncthreads();

        const int k0 = t * FBK;
        const uint32_t kb = sb + ((t & 1) ? KOFF1 : KOFF0);
        const uint32_t vb = sb + ((t & 1) ? VOFF1 : VOFF0);

        float s[8][4];
#pragma unroll
        for (int nf = 0; nf < 8; nf++)
#pragma unroll
            for (int j = 0; j < 4; j++) s[nf][j] = 0.0f;

#pragma unroll
        for (int ks = 0; ks < 8; ks++) {
#pragma unroll
            for (int nj = 0; nj < 4; nj++) {
                uint32_t b0, b1, b2, b3;
                ldsm4(b0, b1, b2, b3, kb + (nj * 16 + l15) * KVSTR + ks * 32 + lhi);
                mma_f16(s[2 * nj],     qf[ks], b0, b2);
                mma_f16(s[2 * nj + 1], qf[ks], b1, b3);
            }
        }

#pragma unroll
        for (int nf = 0; nf < 8; nf++)
#pragma unroll
            for (int j = 0; j < 4; j++) s[nf][j] *= FSCALE;

        if (k0 + FBK - 1 > q0 + wid * 16) {
#pragma unroll
            for (int nf = 0; nf < 8; nf++) {
                int c0 = k0 + nf * 8 + 2 * q;
                if (c0 > rg0)     s[nf][0] = -1e30f;
                if (c0 + 1 > rg0) s[nf][1] = -1e30f;
                if (c0 > rg1)     s[nf][2] = -1e30f;
                if (c0 + 1 > rg1) s[nf][3] = -1e30f;
            }
        }

        float mx0 = -1e30f, mx1 = -1e30f;
#pragma unroll
        for (int nf = 0; nf < 8; nf++) {
            mx0 = fmaxf(mx0, fmaxf(s[nf][0], s[nf][1]));
            mx1 = fmaxf(mx1, fmaxf(s[nf][2], s[nf][3]));
        }
        mx0 = fmaxf(mx0, __shfl_xor_sync(0xffffffffu, mx0, 1));
        mx0 = fmaxf(mx0, __shfl_xor_sync(0xffffffffu, mx0, 2));
        mx1 = fmaxf(mx1, __shfl_xor_sync(0xffffffffu, mx1, 1));
        mx1 = fmaxf(mx1, __shfl_xor_sync(0xffffffffu, mx1, 2));

        float mn0 = fmaxf(m0, mx0), mn1 = fmaxf(m1, mx1);
        float cr0 = __expf(m0 - mn0), cr1 = __expf(m1 - mn1);
        m0 = mn0; m1 = mn1;

        float rs0 = 0.0f, rs1 = 0.0f;
#pragma unroll
        for (int nf = 0; nf < 8; nf++) {
            s[nf][0] = __expf(s[nf][0] - mn0);
            s[nf][1] = __expf(s[nf][1] - mn0);
            s[nf][2] = __expf(s[nf][2] - mn1);
            s[nf][3] = __expf(s[nf][3] - mn1);
            rs0 += s[nf][0] + s[nf][1];
            rs1 += s[nf][2] + s[nf][3];
        }
        rs0 += __shfl_xor_sync(0xffffffffu, rs0, 1);
        rs0 += __shfl_xor_sync(0xffffffffu, rs0, 2);
        rs1 += __shfl_xor_sync(0xffffffffu, rs1, 1);
        rs1 += __shfl_xor_sync(0xffffffffu, rs1, 2);
        l0 = l0 * cr0 + rs0;
        l1 = l1 * cr1 + rs1;

#pragma unroll
        for (int nf = 0; nf < 16; nf++) {
            o[nf][0] *= cr0; o[nf][1] *= cr0;
            o[nf][2] *= cr1; o[nf][3] *= cr1;
        }

#pragma unroll
        for (int nf = 0; nf < 8; nf++) {
            *(__half2*)(smem + PSOFF + rl0 * PSTR + (nf * 8 + 2 * q) * 2) =
                __floats2half2_rn(s[nf][0], s[nf][1]);
            *(__half2*)(smem + PSOFF + rl1 * PSTR + (nf * 8 + 2 * q) * 2) =
                __floats2half2_rn(s[nf][2], s[nf][3]);
        }
        __syncwarp();

#pragma unroll
        for (int ks2 = 0; ks2 < 4; ks2++) {
            uint32_t pa[4];
            ldsm4(pa[0], pa[1], pa[2], pa[3],
                  sb + PSOFF + (wid * 16 + l15) * PSTR + ks2 * 32 + lhi);
#pragma unroll
            for (int nj = 0; nj < 8; nj++) {
                uint32_t v0, v1, v2, v3;
                ldsm4t(v0, v1, v2, v3,
                       vb + (ks2 * 16 + l15) * KVSTR + nj * 32 + lhi);
                mma_f16(o[2 * nj],     pa, v0, v1);
                mma_f16(o[2 * nj + 1], pa, v2, v3);
            }
        }
        __syncthreads();
    }

    float i0 = 1.0f / l0, i1 = 1.0f / l1;
#pragma unroll
    for (int nf = 0; nf < 16; nf++) {
        *(__half2*)(g_AOh + (brow + rg0) * (size_t)DD + head + nf * 8 + 2 * q) =
            __floats2half2_rn(o[nf][0] * i0, o[nf][1] * i0);
        *(__half2*)(g_AOh + (brow + rg1) * (size_t)DD + head + nf * 8 + 2 * q) =
            __floats2half2_rn(o[nf][2] * i1, o[nf][3] * i1);
    }
}

// ---------------------------------------------------------------------------
// Launch
// ---------------------------------------------------------------------------
extern "C" void kernel_launch(void* const* d_in, const int* in_sizes, int n_in,
                              void* d_out, int out_size)
{
    const float* x  = (const float*)d_in[0];
    const float* wq = (const float*)d_in[1];
    const float* wk = (const float*)d_in[2];
    const float* wv = (const float*)d_in[3];
    const float* wo = (const float*)d_in[4];
    const float* fc = (const float*)d_in[5];
    const float* fs = (const float*)d_in[6];
    float* out = (float*)d_out;

    void *p_xh, *p_woh, *p_aoh;
    cudaGetSymbolAddress(&p_xh,  g_xh);
    cudaGetSymbolAddress(&p_woh, g_woh);
    cudaGetSymbolAddress(&p_aoh, g_AOh);

    cudaFuncSetAttribute(gemm_f16_kernel,
                         cudaFuncAttributeMaxDynamicSharedMemorySize, GEMM_SMEM);
    cudaFuncSetAttribute(qkv_f16_kernel,
                         cudaFuncAttributeMaxDynamicSharedMemorySize, GEMM_SMEM);
    cudaFuncSetAttribute(flash_f16_kernel,
                         cudaFuncAttributeMaxDynamicSharedMemorySize, FLASH_SMEM);

    // 0) one conversion pass: x + 4 weights -> half
    cvt_all_kernel<<<(N4X + 4 * N4W) / 256, 256>>>(x, wq, wk, wv, wo);

    // 1) QKV projections with fused RoPE epilogue -> g_Qh/g_Kh/g_Vh (half)
    dim3 gq(NDIM / GTN, MDIM / GTM, 3);   // (16, 32, 3)
    qkv_f16_kernel<<<gq, NTHR, GEMM_SMEM>>>((const __half*)p_xh, fc, fs);

    // 2) Causal flash attention -> g_AOh
    flash_f16_kernel<<<dim3(SS / FBQ, NH, BB), 256, FLASH_SMEM>>>();

    // 3) Output projection -> fp32 out
    gemm_f16_kernel<<<dim3(NDIM / GTN, MDIM / GTM), NTHR, GEMM_SMEM>>>(
        (const __half*)p_aoh, (const __half*)p_woh, out);
}